// round 6
// baseline (speedup 1.0000x reference)
#include <cuda_runtime.h>
#include <cuda_fp16.h>
#include <math.h>
#include <stdint.h>

#define Bn 8
#define Ln 2048
#define Cn 512
#define Hn 8
#define Dn 64
#define FFn 2048
#define BLn (Bn*Ln)          /* 16384 */
#define BHn (Bn*Hn)          /* 64    */
#define BHLn (BHn*Ln)        /* 131072*/
#define KVCHUNKS 8

// ---------------- scratch (static device globals; no allocation) ----------------
static __device__ __align__(16) float  g_xbuf[BLn*Cn];
static __device__ __align__(16) __half g_lnh[BLn*Cn];
static __device__ __align__(16) __half g_qkh[BLn*2*Cn];
static __device__ __align__(16) __half g_vh[BLn*Cn];
static __device__ __align__(16) __half g_q2h[BHLn*Dn];
static __device__ __align__(16) __half g_k2h[BHLn*Dn];
static __device__ __align__(16) float  g_kmean[BHn*Dn];
static __device__ __align__(16) float  g_kv[BHn*Dn*Dn];
static __device__ __align__(16) float  g_kvpart[KVCHUNKS*BHn*Dn*Dn];
static __device__ __align__(16) float  g_z[BHLn];
static __device__ __align__(16) float  g_spin[BLn*Cn];
static __device__ __align__(16) __half g_hb[BLn*Cn];
static __device__ __align__(16) __half g_ffnh[(long)BLn*FFn];
// transposed (N-major) half weights: B^T [N,K] row-major
static __device__ __align__(16) __half g_qkTh[1024*512];
static __device__ __align__(16) __half g_vTh[512*512];
static __device__ __align__(16) __half g_w1Th[2048*512];
static __device__ __align__(16) __half g_w2Th[512*2048];
static __device__ __align__(16) __half g_wtT2h[1024*1536];   // interleaved (vv,gg) pairs
static __device__ __align__(16) float  g_bias2[1024];

// ---------------- PTX helpers ----------------
__device__ __forceinline__ uint32_t smem_u32(const void* p) {
    uint32_t a;
    asm("{ .reg .u64 t; cvta.to.shared.u64 t, %1; cvt.u32.u64 %0, t; }" : "=r"(a) : "l"(p));
    return a;
}
__device__ __forceinline__ void cpasync16(uint32_t saddr, const void* g) {
    asm volatile("cp.async.cg.shared.global [%0], [%1], 16;" :: "r"(saddr), "l"(g) : "memory");
}
// zero-fill variant: src-size 0 -> fills 16B of zeros, no global read
__device__ __forceinline__ void cpasync16z(uint32_t saddr, const void* g, uint32_t sz) {
    asm volatile("cp.async.cg.shared.global [%0], [%1], 16, %2;"
                 :: "r"(saddr), "l"(g), "r"(sz) : "memory");
}
#define CP_COMMIT() asm volatile("cp.async.commit_group;" ::: "memory")
#define CP_WAIT1()  asm volatile("cp.async.wait_group 1;" ::: "memory")

__device__ __forceinline__ void ldsm4(uint32_t* r, uint32_t addr) {
    asm volatile("ldmatrix.sync.aligned.m8n8.x4.shared.b16 {%0,%1,%2,%3}, [%4];"
        : "=r"(r[0]), "=r"(r[1]), "=r"(r[2]), "=r"(r[3]) : "r"(addr));
}
__device__ __forceinline__ void mma_f16(float* c, const uint32_t* a, const uint32_t* b) {
    asm volatile(
        "mma.sync.aligned.m16n8k16.row.col.f32.f16.f16.f32 "
        "{%0,%1,%2,%3}, {%4,%5,%6,%7}, {%8,%9}, {%0,%1,%2,%3};"
        : "+f"(c[0]), "+f"(c[1]), "+f"(c[2]), "+f"(c[3])
        : "r"(a[0]), "r"(a[1]), "r"(a[2]), "r"(a[3]), "r"(b[0]), "r"(b[1]));
}

// ---------------- small helpers ----------------
__device__ __forceinline__ float elu1(float x) { return x > 0.0f ? x + 1.0f : expf(x); }
__device__ __forceinline__ uint32_t swz(uint32_t r) { return (r ^ (r >> 2)) & 3u; }

// ---------------- LayerNorm (half out) ----------------
__global__ void ln_h_kernel(const float* __restrict__ in, const float* __restrict__ gam,
                            const float* __restrict__ bet, __half* __restrict__ out) {
    int row = blockIdx.x;
    int t = threadIdx.x;
    const float4 v = ((const float4*)(in + (long)row * Cn))[t];
    float s  = v.x + v.y + v.z + v.w;
    float sq = v.x*v.x + v.y*v.y + v.z*v.z + v.w*v.w;
    #pragma unroll
    for (int o = 16; o; o >>= 1) {
        s  += __shfl_xor_sync(0xFFFFFFFFu, s,  o);
        sq += __shfl_xor_sync(0xFFFFFFFFu, sq, o);
    }
    __shared__ float ss[4], ssq[4];
    if ((t & 31) == 0) { ss[t >> 5] = s; ssq[t >> 5] = sq; }
    __syncthreads();
    s  = ss[0] + ss[1] + ss[2] + ss[3];
    sq = ssq[0] + ssq[1] + ssq[2] + ssq[3];
    float mu   = s * (1.0f / Cn);
    float var  = sq * (1.0f / Cn) - mu * mu;
    float rstd = rsqrtf(var + 1e-5f);
    float4 g4 = ((const float4*)gam)[t];
    float4 b4 = ((const float4*)bet)[t];
    __half2* o = (__half2*)(out + (long)row * Cn);
    o[t * 2]     = __floats2half2_rn((v.x - mu) * rstd * g4.x + b4.x,
                                     (v.y - mu) * rstd * g4.y + b4.y);
    o[t * 2 + 1] = __floats2half2_rn((v.z - mu) * rstd * g4.z + b4.z,
                                     (v.w - mu) * rstd * g4.w + b4.w);
}

// ---------------- fused LN2 + LN3: xbuf -> spin (f32), hb = LN3(spin) (half) ----------------
__global__ void ln2ln3_kernel(const float* __restrict__ in,
                              const float* __restrict__ g2, const float* __restrict__ b2,
                              const float* __restrict__ g3, const float* __restrict__ b3,
                              float* __restrict__ spin, __half* __restrict__ hb) {
    int row = blockIdx.x;
    int t = threadIdx.x;
    __shared__ float ss[4], ssq[4];
    const float4 v = ((const float4*)(in + (long)row * Cn))[t];
    float s  = v.x + v.y + v.z + v.w;
    float sq = v.x*v.x + v.y*v.y + v.z*v.z + v.w*v.w;
    #pragma unroll
    for (int o = 16; o; o >>= 1) {
        s  += __shfl_xor_sync(0xFFFFFFFFu, s,  o);
        sq += __shfl_xor_sync(0xFFFFFFFFu, sq, o);
    }
    if ((t & 31) == 0) { ss[t >> 5] = s; ssq[t >> 5] = sq; }
    __syncthreads();
    s  = ss[0] + ss[1] + ss[2] + ss[3];
    sq = ssq[0] + ssq[1] + ssq[2] + ssq[3];
    float mu   = s * (1.0f / Cn);
    float var  = sq * (1.0f / Cn) - mu * mu;
    float rstd = rsqrtf(var + 1e-5f);
    float4 gg = ((const float4*)g2)[t];
    float4 bb = ((const float4*)b2)[t];
    float4 o1;
    o1.x = (v.x - mu) * rstd * gg.x + bb.x;
    o1.y = (v.y - mu) * rstd * gg.y + bb.y;
    o1.z = (v.z - mu) * rstd * gg.z + bb.z;
    o1.w = (v.w - mu) * rstd * gg.w + bb.w;
    ((float4*)(spin + (long)row * Cn))[t] = o1;
    // second LN over o1
    float s2  = o1.x + o1.y + o1.z + o1.w;
    float sq2 = o1.x*o1.x + o1.y*o1.y + o1.z*o1.z + o1.w*o1.w;
    #pragma unroll
    for (int o = 16; o; o >>= 1) {
        s2  += __shfl_xor_sync(0xFFFFFFFFu, s2,  o);
        sq2 += __shfl_xor_sync(0xFFFFFFFFu, sq2, o);
    }
    __syncthreads();
    if ((t & 31) == 0) { ss[t >> 5] = s2; ssq[t >> 5] = sq2; }
    __syncthreads();
    s2  = ss[0] + ss[1] + ss[2] + ss[3];
    sq2 = ssq[0] + ssq[1] + ssq[2] + ssq[3];
    float mu2   = s2 * (1.0f / Cn);
    float var2  = sq2 * (1.0f / Cn) - mu2 * mu2;
    float rstd2 = rsqrtf(var2 + 1e-5f);
    float4 g4 = ((const float4*)g3)[t];
    float4 b4 = ((const float4*)b3)[t];
    __half2* o = (__half2*)(hb + (long)row * Cn);
    o[t * 2]     = __floats2half2_rn((o1.x - mu2) * rstd2 * g4.x + b4.x,
                                     (o1.y - mu2) * rstd2 * g4.y + b4.y);
    o[t * 2 + 1] = __floats2half2_rn((o1.z - mu2) * rstd2 * g4.z + b4.z,
                                     (o1.w - mu2) * rstd2 * g4.w + b4.w);
}

// ---------------- qk post: elu+1 then LePE (half in, half out) ----------------
__global__ void qk_post_kernel(const __half* __restrict__ qk,
                               const float* __restrict__ lw, const float* __restrict__ lb,
                               __half* __restrict__ q2, __half* __restrict__ k2) {
    int idx = blockIdx.x * blockDim.x + threadIdx.x;          // over BHLn*Dn
    int d  = idx & 63;
    int l  = (idx >> 6) & (Ln - 1);
    int bh = idx >> 17;
    int b = bh >> 3, h = bh & 7;
    long base = (long)b * Ln * 1024 + h * 64;
    float w0 = lw[d*3+0], w1 = lw[d*3+1], w2 = lw[d*3+2], bias = lb[d];
    int flat = d * Ln + l;
    #pragma unroll
    for (int sel = 0; sel < 2; sel++) {
        const __half* src = qk + base + sel * 512;
        float acc = elu1(__half2float(src[(long)l * 1024 + d])) + bias;
        if (l - 1 >= 0) {
            int fi = flat - 1; acc += w0 * elu1(__half2float(src[(long)(fi >> 6) * 1024 + (fi & 63)]));
        }
        {
            int fi = flat;     acc += w1 * elu1(__half2float(src[(long)(fi >> 6) * 1024 + (fi & 63)]));
        }
        if (l + 1 < Ln) {
            int fi = flat + 1; acc += w2 * elu1(__half2float(src[(long)(fi >> 6) * 1024 + (fi & 63)]));
        }
        (sel ? k2 : q2)[idx] = __float2half_rn(acc);
    }
}

// ---------------- k mean ----------------
__global__ void kmean_kernel(const __half* __restrict__ k2, float* __restrict__ km) {
    int bh = blockIdx.x;
    int t = threadIdx.x;
    int d = t & 63, part = t >> 6;
    float s = 0.0f;
    const __half* base = k2 + (long)bh * Ln * Dn;
    for (int l = part; l < Ln; l += 4) s += __half2float(base[l * 64 + d]);
    __shared__ float sm[4][64];
    sm[part][d] = s;
    __syncthreads();
    if (part == 0)
        km[bh * 64 + d] = (sm[0][d] + sm[1][d] + sm[2][d] + sm[3][d]) * (1.0f / Ln);
}

// ---------------- z ----------------
__global__ void z_kernel(const __half* __restrict__ q2, const float* __restrict__ km,
                         float* __restrict__ z) {
    int row  = blockIdx.x * 8 + (threadIdx.x >> 5);
    int lane = threadIdx.x & 31;
    int bh = row >> 11;
    float a = __half2float(q2[(long)row * 64 + lane])      * km[bh * 64 + lane]
            + __half2float(q2[(long)row * 64 + 32 + lane]) * km[bh * 64 + 32 + lane];
    #pragma unroll
    for (int o = 16; o; o >>= 1) a += __shfl_xor_sync(0xFFFFFFFFu, a, o);
    if (lane == 0) z[row] = 1.0f / (a + 1e-6f);
}

// ---------------- kv partials (half inputs, fp32 accumulate) ----------------
__global__ void kv_kernel(const __half* __restrict__ k2, const __half* __restrict__ v,
                          float* __restrict__ part) {
    int bh = blockIdx.x, chunk = blockIdx.y;
    int b = bh >> 3, h = bh & 7;
    __shared__ float ks[32][64];
    __shared__ float vs[32][64];
    int t = threadIdx.x;
    int e0 = (t & 15) * 4, d0 = (t >> 4) * 4;
    float acc[4][4] = {};
    int lc = Ln / KVCHUNKS;
    for (int l0 = chunk * lc; l0 < chunk * lc + lc; l0 += 32) {
        #pragma unroll
        for (int i = 0; i < 2; i++) {
            int idx = t + i * 256;
            int r = idx >> 4, c4 = (idx & 15) * 4;
            int l = l0 + r;
            uint2 kr = *(const uint2*)&k2[((long)bh * Ln + l) * 64 + c4];
            uint2 vr = *(const uint2*)&v[((long)(b * Ln + l)) * Cn + h * 64 + c4];
            float2 k0 = __half22float2(*(__half2*)&kr.x);
            float2 k1 = __half22float2(*(__half2*)&kr.y);
            float2 v0 = __half22float2(*(__half2*)&vr.x);
            float2 v1 = __half22float2(*(__half2*)&vr.y);
            ks[r][c4] = k0.x; ks[r][c4+1] = k0.y; ks[r][c4+2] = k1.x; ks[r][c4+3] = k1.y;
            vs[r][c4] = v0.x; vs[r][c4+1] = v0.y; vs[r][c4+2] = v1.x; vs[r][c4+3] = v1.y;
        }
        __syncthreads();
        #pragma unroll
        for (int l = 0; l < 32; l++) {
            float4 kr = *(const float4*)&ks[l][d0];
            float4 vr = *(const float4*)&vs[l][e0];
            float k_[4] = {kr.x, kr.y, kr.z, kr.w};
            float v_[4] = {vr.x, vr.y, vr.z, vr.w};
            #pragma unroll
            for (int i = 0; i < 4; i++)
                #pragma unroll
                for (int j = 0; j < 4; j++)
                    acc[i][j] += k_[i] * v_[j];
        }
        __syncthreads();
    }
    float* dst = part + ((long)chunk * BHn + bh) * (Dn * Dn);
    #pragma unroll
    for (int i = 0; i < 4; i++)
        #pragma unroll
        for (int j = 0; j < 4; j++)
            dst[(d0 + i) * 64 + e0 + j] = acc[i][j];
}

__global__ void kv_reduce_kernel(const float* __restrict__ part, float* __restrict__ kv) {
    int i = blockIdx.x * blockDim.x + threadIdx.x;
    float s = 0.0f;
    #pragma unroll
    for (int c = 0; c < KVCHUNKS; c++) s += part[(long)c * (BHn * Dn * Dn) + i];
    kv[i] = s * (1.0f / Ln);
}

// ---------------- attention output: xbuf = x + q2@kv * z ----------------
__global__ void attn_out_kernel(const __half* __restrict__ q2, const float* __restrict__ kv,
                                const float* __restrict__ z, const float* __restrict__ x,
                                float* __restrict__ xbuf) {
    int bh = blockIdx.x, b = bh >> 3, h = bh & 7;
    int lbase = blockIdx.y * 32;
    __shared__ float kvs[64][64];
    __shared__ float qs[16][64];
    int t = threadIdx.x;
    #pragma unroll
    for (int i = 0; i < 4; i++) {
        int idx = t + i * 256;
        ((float4*)kvs)[idx] = ((const float4*)(kv + (long)bh * 4096))[idx];
    }
    int g = t >> 4;
    int e0 = (t & 15) * 4;
    for (int it = 0; it < 2; it++) {
        __syncthreads();
        int rbase = lbase + it * 16;
        #pragma unroll
        for (int i = 0; i < 4; i++) {
            int idx = t + i * 256;
            int r = idx >> 6, c = idx & 63;
            qs[r][c] = __half2float(q2[((long)bh * Ln + rbase + r) * 64 + c]);
        }
        __syncthreads();
        int l = rbase + g;
        float4 acc = {0.f, 0.f, 0.f, 0.f};
        #pragma unroll
        for (int d = 0; d < 64; d++) {
            float qd = qs[g][d];
            float4 kvv = *(const float4*)&kvs[d][e0];
            acc.x += qd * kvv.x; acc.y += qd * kvv.y;
            acc.z += qd * kvv.z; acc.w += qd * kvv.w;
        }
        float zz = z[(long)bh * Ln + l];
        long off = ((long)(b * Ln + l)) * Cn + h * 64 + e0;
        float4 cur = *(const float4*)&x[off];
        cur.x += acc.x * zz; cur.y += acc.y * zz;
        cur.z += acc.z * zz; cur.w += acc.w * zz;
        *(float4*)&xbuf[off] = cur;
    }
}

// ---------------- weight transposes -> half ----------------
__global__ void transpose_h_kernel(const float* __restrict__ src, __half* __restrict__ dst,
                                   int K, int N) {
    long idx = (long)blockIdx.x * blockDim.x + threadIdx.x;
    if (idx >= (long)K * N) return;
    int k = (int)(idx % K);
    int n = (int)(idx / K);
    dst[idx] = __float2half_rn(src[(long)k * N + n]);
}

// interleaved conv weight: wtT2[n2][kk=k*512+ci], n2 = 2*(co&511) + (co>>9)
__global__ void wtT2_kernel(const float* __restrict__ w, const float* __restrict__ cb,
                            __half* __restrict__ wtT2, float* __restrict__ bias2) {
    long idx = (long)blockIdx.x * blockDim.x + threadIdx.x;   // 1024*1536
    if (idx >= 1024L * 1536) return;
    int kk = (int)(idx % 1536);
    int n2 = (int)(idx / 1536);
    int co = (n2 & 1) * 512 + (n2 >> 1);
    int k  = kk >> 9;
    int ci = kk & 511;
    wtT2[idx] = __float2half_rn(w[co * 1536 + ci * 3 + k]);
    if (kk == 0) bias2[n2] = cb[co];
}

// ================= fp16 mma.sync GEMM =================
// C[M,N] = A[M,K] @ Bt[N,K]^T.  CTA 128x128, K-chunk 32, 3-stage cp.async, 8 warps.
// CONVA=1: A is hb [BL,512] viewed as im2col [BL,1536] with zero-padded taps.
// EPI: 1 = bias + exact GELU (half out); 2 = bias + residual (float out);
//      3 = gated conv: out(xbuf) += spin + vv*sigmoid(gg), N logical 1024, out stride 512;
//      4 = bias (half out).
#define GSM (3 * 16384)

template<int EPI, int CONVA>
__global__ void __launch_bounds__(256, 2)
gemm_h(const __half* __restrict__ A, const __half* __restrict__ Bt,
       const float* __restrict__ bias, const float* __restrict__ res,
       void* __restrict__ Cv, int M, int N, int K) {
    extern __shared__ char smraw[];
    uint32_t sb = smem_u32(smraw);
    int t = threadIdx.x, wid = t >> 5, lane = t & 31;
    int g = lane >> 2, tig = lane & 3;
    int bm = blockIdx.y * 128, bn = blockIdx.x * 128;
    int wm = (wid >> 2) * 64, wn = (wid & 3) * 32;

    // ---- cp.async slots ----
    const __half* aG[2]; const __half* bG[2]; uint32_t offA[2], offB[2];
    int rs[2], cs[2];
    #pragma unroll
    for (int i = 0; i < 2; i++) {
        int idx = t + i * 256;
        int r = idx >> 2;
        int c = idx & 3;
        rs[i] = r; cs[i] = c;
        uint32_t off = (uint32_t)r * 64 + ((c ^ swz(r)) << 4);
        offA[i] = off;
        offB[i] = off + 8192;
        if (!CONVA) aG[i] = A + (long)(bm + r) * K + c * 8;
        bG[i] = Bt + (long)(bn + r) * K + c * 8;
    }

    // ---- ldmatrix address components ----
    uint32_t aRow[4], aSw[4];
    #pragma unroll
    for (int mt = 0; mt < 4; mt++) {
        uint32_t m = wm + mt * 16 + (lane & 15);
        aRow[mt] = m * 64;
        aSw[mt] = swz(m);
    }
    uint32_t cHiA = lane >> 4;
    uint32_t bRow[2], bSw[2];
    #pragma unroll
    for (int np = 0; np < 2; np++) {
        uint32_t n = wn + np * 16 + ((lane >> 4) << 3) + (lane & 7);
        bRow[np] = n * 64 + 8192;
        bSw[np] = swz(n);
    }
    uint32_t cHiB = (lane >> 3) & 1;

    int nk = K >> 5;

    // conv A-loader: chunk kt entirely within tap kt/16
    auto loadA_conv = [&](uint32_t stb, int kt) {
        int tap = kt >> 4;
        int kin = (kt & 15) * 32;
        #pragma unroll
        for (int i = 0; i < 2; i++) {
            long row = bm + rs[i];
            int l = (int)(row & (Ln - 1));
            bool valid = (unsigned)(l + tap - 1) < (unsigned)Ln;
            const __half* src = valid ? (A + (row + tap - 1) * Cn + kin + cs[i] * 8) : A;
            cpasync16z(stb + offA[i], src, valid ? 16u : 0u);
        }
    };

    // prologue
    #pragma unroll
    for (int s = 0; s < 2; s++) {
        uint32_t stb = sb + s * 16384;
        if (CONVA) loadA_conv(stb, s);
        else {
            #pragma unroll
            for (int i = 0; i < 2; i++) cpasync16(stb + offA[i], aG[i] + s * 32);
        }
        #pragma unroll
        for (int i = 0; i < 2; i++) cpasync16(stb + offB[i], bG[i] + s * 32);
        CP_COMMIT();
    }
    CP_WAIT1();
    __syncthreads();

    float acc[4][4][4] = {};

    for (int kt = 0; kt < nk; kt++) {
        if (kt + 2 < nk) {
            uint32_t stb = sb + ((kt + 2) % 3) * 16384;
            if (CONVA) loadA_conv(stb, kt + 2);
            else {
                #pragma unroll
                for (int i = 0; i < 2; i++) cpasync16(stb + offA[i], aG[i] + (long)(kt + 2) * 32);
            }
            #pragma unroll
            for (int i = 0; i < 2; i++) cpasync16(stb + offB[i], bG[i] + (long)(kt + 2) * 32);
        }
        CP_COMMIT();

        uint32_t stb = sb + (kt % 3) * 16384;
        #pragma unroll
        for (int kb = 0; kb < 2; kb++) {
            uint32_t a[4][4], b[4][2];
            #pragma unroll
            for (int mt = 0; mt < 4; mt++) {
                uint32_t addr = stb + aRow[mt] + ((((uint32_t)(2 * kb) | cHiA) ^ aSw[mt]) << 4);
                ldsm4(a[mt], addr);
            }
            #pragma unroll
            for (int np = 0; np < 2; np++) {
                uint32_t bb[4];
                uint32_t addr = stb + bRow[np] + ((((uint32_t)(2 * kb) | cHiB) ^ bSw[np]) << 4);
                ldsm4(bb, addr);
                b[2*np][0] = bb[0]; b[2*np][1] = bb[1];
                b[2*np+1][0] = bb[2]; b[2*np+1][1] = bb[3];
            }
            #pragma unroll
            for (int mt = 0; mt < 4; mt++)
                #pragma unroll
                for (int nt = 0; nt < 4; nt++)
                    mma_f16(acc[mt][nt], a[mt], b[nt]);
        }

        CP_WAIT1();
        __syncthreads();
    }

    // ---- epilogue ----
    #pragma unroll
    for (int mt = 0; mt < 4; mt++) {
        int row = bm + wm + mt * 16 + g;
        #pragma unroll
        for (int nt = 0; nt < 4; nt++) {
            int col = bn + wn + nt * 8 + tig * 2;
            float b0 = bias[col], b1 = bias[col + 1];
            float v00 = acc[mt][nt][0] + b0;
            float v01 = acc[mt][nt][1] + b1;
            float v10 = acc[mt][nt][2] + b0;
            float v11 = acc[mt][nt][3] + b1;
            if (EPI == 1) {
                v00 = 0.5f * v00 * (1.0f + erff(v00 * 0.70710678118654752f));
                v01 = 0.5f * v01 * (1.0f + erff(v01 * 0.70710678118654752f));
                v10 = 0.5f * v10 * (1.0f + erff(v10 * 0.70710678118654752f));
                v11 = 0.5f * v11 * (1.0f + erff(v11 * 0.70710678118654752f));
                __half2* C = (__half2*)Cv;
                C[((long)row * N + col) >> 1]       = __floats2half2_rn(v00, v01);
                C[((long)(row + 8) * N + col) >> 1] = __floats2half2_rn(v10, v11);
            } else if (EPI == 4) {
                __half2* C = (__half2*)Cv;
                C[((long)row * N + col) >> 1]       = __floats2half2_rn(v00, v01);
                C[((long)(row + 8) * N + col) >> 1] = __floats2half2_rn(v10, v11);
            } else if (EPI == 3) {
                // col even: v00/v10 = vv, v01/v11 = gg; output col = col>>1, stride 512
                int cp = col >> 1;
                float* X = (float*)Cv;
                long o0 = (long)row * Cn + cp;
                long o1 = (long)(row + 8) * Cn + cp;
                float r0 = X[o0] + res[o0] + v00 / (1.0f + expf(-v01));
                float r1 = X[o1] + res[o1] + v10 / (1.0f + expf(-v11));
                X[o0] = r0;
                X[o1] = r1;
            } else {  // EPI == 2
                const float* r0 = res + (long)row * N + col;
                const float* r1 = res + (long)(row + 8) * N + col;
                v00 += r0[0]; v01 += r0[1];
                v10 += r1[0]; v11 += r1[1];
                float* C = (float*)Cv;
                float2 p0 = {v00, v01}, p1 = {v10, v11};
                *(float2*)(C + (long)row * N + col)       = p0;
                *(float2*)(C + (long)(row + 8) * N + col) = p1;
            }
        }
    }
}

// ---------------- host launcher ----------------
extern "C" void kernel_launch(void* const* d_in, const int* in_sizes, int n_in,
                              void* d_out, int out_size) {
    const float* x      = (const float*)d_in[0];
    const float* g1     = (const float*)d_in[1];
    const float* b1     = (const float*)d_in[2];
    const float* qk_w   = (const float*)d_in[3];
    const float* qk_b   = (const float*)d_in[4];
    const float* v_w    = (const float*)d_in[5];
    const float* v_b    = (const float*)d_in[6];
    const float* lepe_w = (const float*)d_in[7];
    const float* lepe_b = (const float*)d_in[8];
    const float* g2     = (const float*)d_in[9];
    const float* b2     = (const float*)d_in[10];
    const float* spn_g  = (const float*)d_in[11];
    const float* spn_b  = (const float*)d_in[12];
    const float* sp_cw  = (const float*)d_in[13];
    const float* sp_cb  = (const float*)d_in[14];
    const float* g3     = (const float*)d_in[15];
    const float* b3     = (const float*)d_in[16];
    const float* w1     = (const float*)d_in[17];
    const float* bb1    = (const float*)d_in[18];
    const float* w2     = (const float*)d_in[19];
    const float* bb2    = (const float*)d_in[20];
    float* out = (float*)d_out;

    float *xbuf, *km, *kv, *kvpart, *z, *spin, *bias2;
    __half *lnh, *qkh, *vh, *q2h, *k2h, *hb, *ffnh, *qkTh, *vTh, *w1Th, *w2Th, *wtT2h;
    cudaGetSymbolAddress((void**)&xbuf,   g_xbuf);
    cudaGetSymbolAddress((void**)&lnh,    g_lnh);
    cudaGetSymbolAddress((void**)&qkh,    g_qkh);
    cudaGetSymbolAddress((void**)&vh,     g_vh);
    cudaGetSymbolAddress((void**)&q2h,    g_q2h);
    cudaGetSymbolAddress((void**)&k2h,    g_k2h);
    cudaGetSymbolAddress((void**)&km,     g_kmean);
    cudaGetSymbolAddress((void**)&kv,     g_kv);
    cudaGetSymbolAddress((void**)&kvpart, g_kvpart);
    cudaGetSymbolAddress((void**)&z,      g_z);
    cudaGetSymbolAddress((void**)&spin,   g_spin);
    cudaGetSymbolAddress((void**)&hb,     g_hb);
    cudaGetSymbolAddress((void**)&ffnh,   g_ffnh);
    cudaGetSymbolAddress((void**)&qkTh,   g_qkTh);
    cudaGetSymbolAddress((void**)&vTh,    g_vTh);
    cudaGetSymbolAddress((void**)&w1Th,   g_w1Th);
    cudaGetSymbolAddress((void**)&w2Th,   g_w2Th);
    cudaGetSymbolAddress((void**)&wtT2h,  g_wtT2h);
    cudaGetSymbolAddress((void**)&bias2,  g_bias2);

    cudaFuncSetAttribute((const void*)gemm_h<4,0>, cudaFuncAttributeMaxDynamicSharedMemorySize, GSM);
    cudaFuncSetAttribute((const void*)gemm_h<3,1>, cudaFuncAttributeMaxDynamicSharedMemorySize, GSM);
    cudaFuncSetAttribute((const void*)gemm_h<1,0>, cudaFuncAttributeMaxDynamicSharedMemorySize, GSM);
    cudaFuncSetAttribute((const void*)gemm_h<2,0>, cudaFuncAttributeMaxDynamicSharedMemorySize, GSM);

    // weight transposes (half)
    transpose_h_kernel<<<(512 * 1024 + 255) / 256, 256>>>(qk_w, qkTh, 512, 1024);
    transpose_h_kernel<<<(512 * 512 + 255) / 256, 256>>>(v_w, vTh, 512, 512);
    transpose_h_kernel<<<(512 * 2048 + 255) / 256, 256>>>(w1, w1Th, 512, 2048);
    transpose_h_kernel<<<(2048 * 512 + 255) / 256, 256>>>(w2, w2Th, 2048, 512);
    wtT2_kernel<<<(1024 * 1536 + 255) / 256, 256>>>(sp_cw, sp_cb, wtT2h, bias2);

    // Block 1: xbuf = x + attn(LN1(x))
    ln_h_kernel<<<BLn, 128>>>(x, g1, b1, lnh);
    gemm_h<4,0><<<dim3(1024 / 128, BLn / 128), 256, GSM>>>(lnh, qkTh, qk_b, nullptr, qkh, BLn, 1024, Cn);
    gemm_h<4,0><<<dim3(512 / 128, BLn / 128), 256, GSM>>>(lnh, vTh, v_b, nullptr, vh, BLn, 512, Cn);
    qk_post_kernel<<<(BHLn * Dn) / 256, 256>>>(qkh, lepe_w, lepe_b, q2h, k2h);
    kmean_kernel<<<BHn, 256>>>(k2h, km);
    z_kernel<<<BHLn / 8, 256>>>(q2h, km, z);
    kv_kernel<<<dim3(BHn, KVCHUNKS), 256>>>(k2h, vh, kvpart);
    kv_reduce_kernel<<<(BHn * Dn * Dn) / 256, 256>>>(kvpart, kv);
    attn_out_kernel<<<dim3(BHn, Ln / 32), 256>>>(q2h, kv, z, x, xbuf);

    // Block 2: gated conv state path (fused LN2+LN3, direct-conv GEMM + fused gate)
    ln2ln3_kernel<<<BLn, 128>>>(xbuf, g2, b2, spn_g, spn_b, spin, hb);
    gemm_h<3,1><<<dim3(1024 / 128, BLn / 128), 256, GSM>>>(hb, wtT2h, bias2, spin, xbuf, BLn, 1024, 3 * Cn);

    // Block 3: FFN
    ln_h_kernel<<<BLn, 128>>>(xbuf, g3, b3, lnh);
    gemm_h<1,0><<<dim3(FFn / 128, BLn / 128), 256, GSM>>>(lnh, w1Th, bb1, nullptr, ffnh, BLn, FFn, Cn);
    gemm_h<2,0><<<dim3(512 / 128, BLn / 128), 256, GSM>>>(ffnh, w2Th, bb2, xbuf, out, BLn, 512, FFn);
}

// round 7
// speedup vs baseline: 1.1349x; 1.1349x over previous
#include <cuda_runtime.h>
#include <cuda_fp16.h>
#include <math.h>
#include <stdint.h>

#define Bn 8
#define Ln 2048
#define Cn 512
#define Hn 8
#define Dn 64
#define FFn 2048
#define BLn (Bn*Ln)          /* 16384 */
#define BHn (Bn*Hn)          /* 64    */
#define BHLn (BHn*Ln)        /* 131072*/
#define KVCHUNKS 8

// ---------------- scratch (static device globals; no allocation) ----------------
static __device__ __align__(16) float  g_xbuf[BLn*Cn];
static __device__ __align__(16) __half g_lnh[BLn*Cn];
static __device__ __align__(16) __half g_qkh[BLn*2*Cn];
static __device__ __align__(16) __half g_vh[BLn*Cn];
static __device__ __align__(16) __half g_q2h[BHLn*Dn];
static __device__ __align__(16) __half g_k2h[BHLn*Dn];
static __device__ __align__(16) float  g_kmean[BHn*Dn];
static __device__ __align__(16) float  g_kv[BHn*Dn*Dn];
static __device__ __align__(16) float  g_kvpart[KVCHUNKS*BHn*Dn*Dn];
static __device__ __align__(16) float  g_z[BHLn];
static __device__ __align__(16) float  g_spin[BLn*Cn];
static __device__ __align__(16) __half g_hb[BLn*Cn];
static __device__ __align__(16) __half g_ffnh[(long)BLn*FFn];
// transposed (N-major) half weights: B^T [N,K] row-major
static __device__ __align__(16) __half g_qkTh[1024*512];
static __device__ __align__(16) __half g_vTh[512*512];
static __device__ __align__(16) __half g_w1Th[2048*512];
static __device__ __align__(16) __half g_w2Th[512*2048];
static __device__ __align__(16) __half g_wtT2h[1024*1536];   // interleaved (vv,gg) pairs
static __device__ __align__(16) float  g_bias2[1024];

// ---------------- PTX helpers ----------------
__device__ __forceinline__ uint32_t smem_u32(const void* p) {
    uint32_t a;
    asm("{ .reg .u64 t; cvta.to.shared.u64 t, %1; cvt.u32.u64 %0, t; }" : "=r"(a) : "l"(p));
    return a;
}
__device__ __forceinline__ void cpasync16(uint32_t saddr, const void* g) {
    asm volatile("cp.async.cg.shared.global [%0], [%1], 16;" :: "r"(saddr), "l"(g) : "memory");
}
// zero-fill variant: src-size 0 -> fills 16B of zeros, no global read
__device__ __forceinline__ void cpasync16z(uint32_t saddr, const void* g, uint32_t sz) {
    asm volatile("cp.async.cg.shared.global [%0], [%1], 16, %2;"
                 :: "r"(saddr), "l"(g), "r"(sz) : "memory");
}
#define CP_COMMIT() asm volatile("cp.async.commit_group;" ::: "memory")
#define CP_WAIT1()  asm volatile("cp.async.wait_group 1;" ::: "memory")

__device__ __forceinline__ void ldsm4(uint32_t* r, uint32_t addr) {
    asm volatile("ldmatrix.sync.aligned.m8n8.x4.shared.b16 {%0,%1,%2,%3}, [%4];"
        : "=r"(r[0]), "=r"(r[1]), "=r"(r[2]), "=r"(r[3]) : "r"(addr));
}
__device__ __forceinline__ void mma_f16(float* c, const uint32_t* a, const uint32_t* b) {
    asm volatile(
        "mma.sync.aligned.m16n8k16.row.col.f32.f16.f16.f32 "
        "{%0,%1,%2,%3}, {%4,%5,%6,%7}, {%8,%9}, {%0,%1,%2,%3};"
        : "+f"(c[0]), "+f"(c[1]), "+f"(c[2]), "+f"(c[3])
        : "r"(a[0]), "r"(a[1]), "r"(a[2]), "r"(a[3]), "r"(b[0]), "r"(b[1]));
}

// ---------------- small helpers ----------------
__device__ __forceinline__ float elu1(float x) { return x > 0.0f ? x + 1.0f : expf(x); }
__device__ __forceinline__ uint32_t swz(uint32_t r) { return (r ^ (r >> 2)) & 3u; }

// ---------------- LayerNorm (half out) ----------------
__global__ void ln_h_kernel(const float* __restrict__ in, const float* __restrict__ gam,
                            const float* __restrict__ bet, __half* __restrict__ out) {
    int row = blockIdx.x;
    int t = threadIdx.x;
    const float4 v = ((const float4*)(in + (long)row * Cn))[t];
    float s  = v.x + v.y + v.z + v.w;
    float sq = v.x*v.x + v.y*v.y + v.z*v.z + v.w*v.w;
    #pragma unroll
    for (int o = 16; o; o >>= 1) {
        s  += __shfl_xor_sync(0xFFFFFFFFu, s,  o);
        sq += __shfl_xor_sync(0xFFFFFFFFu, sq, o);
    }
    __shared__ float ss[4], ssq[4];
    if ((t & 31) == 0) { ss[t >> 5] = s; ssq[t >> 5] = sq; }
    __syncthreads();
    s  = ss[0] + ss[1] + ss[2] + ss[3];
    sq = ssq[0] + ssq[1] + ssq[2] + ssq[3];
    float mu   = s * (1.0f / Cn);
    float var  = sq * (1.0f / Cn) - mu * mu;
    float rstd = rsqrtf(var + 1e-5f);
    float4 g4 = ((const float4*)gam)[t];
    float4 b4 = ((const float4*)bet)[t];
    __half2* o = (__half2*)(out + (long)row * Cn);
    o[t * 2]     = __floats2half2_rn((v.x - mu) * rstd * g4.x + b4.x,
                                     (v.y - mu) * rstd * g4.y + b4.y);
    o[t * 2 + 1] = __floats2half2_rn((v.z - mu) * rstd * g4.z + b4.z,
                                     (v.w - mu) * rstd * g4.w + b4.w);
}

// ---------------- fused LN2 + LN3: xbuf -> spin (f32), hb = LN3(spin) (half) ----------------
__global__ void ln2ln3_kernel(const float* __restrict__ in,
                              const float* __restrict__ g2, const float* __restrict__ b2,
                              const float* __restrict__ g3, const float* __restrict__ b3,
                              float* __restrict__ spin, __half* __restrict__ hb) {
    int row = blockIdx.x;
    int t = threadIdx.x;
    __shared__ float ss[4], ssq[4];
    const float4 v = ((const float4*)(in + (long)row * Cn))[t];
    float s  = v.x + v.y + v.z + v.w;
    float sq = v.x*v.x + v.y*v.y + v.z*v.z + v.w*v.w;
    #pragma unroll
    for (int o = 16; o; o >>= 1) {
        s  += __shfl_xor_sync(0xFFFFFFFFu, s,  o);
        sq += __shfl_xor_sync(0xFFFFFFFFu, sq, o);
    }
    if ((t & 31) == 0) { ss[t >> 5] = s; ssq[t >> 5] = sq; }
    __syncthreads();
    s  = ss[0] + ss[1] + ss[2] + ss[3];
    sq = ssq[0] + ssq[1] + ssq[2] + ssq[3];
    float mu   = s * (1.0f / Cn);
    float var  = sq * (1.0f / Cn) - mu * mu;
    float rstd = rsqrtf(var + 1e-5f);
    float4 gg = ((const float4*)g2)[t];
    float4 bb = ((const float4*)b2)[t];
    float4 o1;
    o1.x = (v.x - mu) * rstd * gg.x + bb.x;
    o1.y = (v.y - mu) * rstd * gg.y + bb.y;
    o1.z = (v.z - mu) * rstd * gg.z + bb.z;
    o1.w = (v.w - mu) * rstd * gg.w + bb.w;
    ((float4*)(spin + (long)row * Cn))[t] = o1;
    // second LN over o1
    float s2  = o1.x + o1.y + o1.z + o1.w;
    float sq2 = o1.x*o1.x + o1.y*o1.y + o1.z*o1.z + o1.w*o1.w;
    #pragma unroll
    for (int o = 16; o; o >>= 1) {
        s2  += __shfl_xor_sync(0xFFFFFFFFu, s2,  o);
        sq2 += __shfl_xor_sync(0xFFFFFFFFu, sq2, o);
    }
    __syncthreads();
    if ((t & 31) == 0) { ss[t >> 5] = s2; ssq[t >> 5] = sq2; }
    __syncthreads();
    s2  = ss[0] + ss[1] + ss[2] + ss[3];
    sq2 = ssq[0] + ssq[1] + ssq[2] + ssq[3];
    float mu2   = s2 * (1.0f / Cn);
    float var2  = sq2 * (1.0f / Cn) - mu2 * mu2;
    float rstd2 = rsqrtf(var2 + 1e-5f);
    float4 g4 = ((const float4*)g3)[t];
    float4 b4 = ((const float4*)b3)[t];
    __half2* o = (__half2*)(hb + (long)row * Cn);
    o[t * 2]     = __floats2half2_rn((o1.x - mu2) * rstd2 * g4.x + b4.x,
                                     (o1.y - mu2) * rstd2 * g4.y + b4.y);
    o[t * 2 + 1] = __floats2half2_rn((o1.z - mu2) * rstd2 * g4.z + b4.z,
                                     (o1.w - mu2) * rstd2 * g4.w + b4.w);
}

// ---------------- qk post: elu+1 then LePE (half in, half out) ----------------
__global__ void qk_post_kernel(const __half* __restrict__ qk,
                               const float* __restrict__ lw, const float* __restrict__ lb,
                               __half* __restrict__ q2, __half* __restrict__ k2) {
    int idx = blockIdx.x * blockDim.x + threadIdx.x;          // over BHLn*Dn
    int d  = idx & 63;
    int l  = (idx >> 6) & (Ln - 1);
    int bh = idx >> 17;
    int b = bh >> 3, h = bh & 7;
    long base = (long)b * Ln * 1024 + h * 64;
    float w0 = lw[d*3+0], w1 = lw[d*3+1], w2 = lw[d*3+2], bias = lb[d];
    int flat = d * Ln + l;
    #pragma unroll
    for (int sel = 0; sel < 2; sel++) {
        const __half* src = qk + base + sel * 512;
        float acc = elu1(__half2float(src[(long)l * 1024 + d])) + bias;
        if (l - 1 >= 0) {
            int fi = flat - 1; acc += w0 * elu1(__half2float(src[(long)(fi >> 6) * 1024 + (fi & 63)]));
        }
        {
            int fi = flat;     acc += w1 * elu1(__half2float(src[(long)(fi >> 6) * 1024 + (fi & 63)]));
        }
        if (l + 1 < Ln) {
            int fi = flat + 1; acc += w2 * elu1(__half2float(src[(long)(fi >> 6) * 1024 + (fi & 63)]));
        }
        (sel ? k2 : q2)[idx] = __float2half_rn(acc);
    }
}

// ---------------- k mean ----------------
__global__ void kmean_kernel(const __half* __restrict__ k2, float* __restrict__ km) {
    int bh = blockIdx.x;
    int t = threadIdx.x;
    int d = t & 63, part = t >> 6;
    float s = 0.0f;
    const __half* base = k2 + (long)bh * Ln * Dn;
    for (int l = part; l < Ln; l += 4) s += __half2float(base[l * 64 + d]);
    __shared__ float sm[4][64];
    sm[part][d] = s;
    __syncthreads();
    if (part == 0)
        km[bh * 64 + d] = (sm[0][d] + sm[1][d] + sm[2][d] + sm[3][d]) * (1.0f / Ln);
}

// ---------------- z ----------------
__global__ void z_kernel(const __half* __restrict__ q2, const float* __restrict__ km,
                         float* __restrict__ z) {
    int row  = blockIdx.x * 8 + (threadIdx.x >> 5);
    int lane = threadIdx.x & 31;
    int bh = row >> 11;
    float a = __half2float(q2[(long)row * 64 + lane])      * km[bh * 64 + lane]
            + __half2float(q2[(long)row * 64 + 32 + lane]) * km[bh * 64 + 32 + lane];
    #pragma unroll
    for (int o = 16; o; o >>= 1) a += __shfl_xor_sync(0xFFFFFFFFu, a, o);
    if (lane == 0) z[row] = 1.0f / (a + 1e-6f);
}

// ---------------- kv partials (half inputs, fp32 accumulate) ----------------
__global__ void kv_kernel(const __half* __restrict__ k2, const __half* __restrict__ v,
                          float* __restrict__ part) {
    int bh = blockIdx.x, chunk = blockIdx.y;
    int b = bh >> 3, h = bh & 7;
    __shared__ float ks[32][64];
    __shared__ float vs[32][64];
    int t = threadIdx.x;
    int e0 = (t & 15) * 4, d0 = (t >> 4) * 4;
    float acc[4][4] = {};
    int lc = Ln / KVCHUNKS;
    for (int l0 = chunk * lc; l0 < chunk * lc + lc; l0 += 32) {
        #pragma unroll
        for (int i = 0; i < 2; i++) {
            int idx = t + i * 256;
            int r = idx >> 4, c4 = (idx & 15) * 4;
            int l = l0 + r;
            uint2 kr = *(const uint2*)&k2[((long)bh * Ln + l) * 64 + c4];
            uint2 vr = *(const uint2*)&v[((long)(b * Ln + l)) * Cn + h * 64 + c4];
            float2 k0 = __half22float2(*(__half2*)&kr.x);
            float2 k1 = __half22float2(*(__half2*)&kr.y);
            float2 v0 = __half22float2(*(__half2*)&vr.x);
            float2 v1 = __half22float2(*(__half2*)&vr.y);
            ks[r][c4] = k0.x; ks[r][c4+1] = k0.y; ks[r][c4+2] = k1.x; ks[r][c4+3] = k1.y;
            vs[r][c4] = v0.x; vs[r][c4+1] = v0.y; vs[r][c4+2] = v1.x; vs[r][c4+3] = v1.y;
        }
        __syncthreads();
        #pragma unroll
        for (int l = 0; l < 32; l++) {
            float4 kr = *(const float4*)&ks[l][d0];
            float4 vr = *(const float4*)&vs[l][e0];
            float k_[4] = {kr.x, kr.y, kr.z, kr.w};
            float v_[4] = {vr.x, vr.y, vr.z, vr.w};
            #pragma unroll
            for (int i = 0; i < 4; i++)
                #pragma unroll
                for (int j = 0; j < 4; j++)
                    acc[i][j] += k_[i] * v_[j];
        }
        __syncthreads();
    }
    float* dst = part + ((long)chunk * BHn + bh) * (Dn * Dn);
    #pragma unroll
    for (int i = 0; i < 4; i++)
        #pragma unroll
        for (int j = 0; j < 4; j++)
            dst[(d0 + i) * 64 + e0 + j] = acc[i][j];
}

__global__ void kv_reduce_kernel(const float* __restrict__ part, float* __restrict__ kv) {
    int i = blockIdx.x * blockDim.x + threadIdx.x;
    float s = 0.0f;
    #pragma unroll
    for (int c = 0; c < KVCHUNKS; c++) s += part[(long)c * (BHn * Dn * Dn) + i];
    kv[i] = s * (1.0f / Ln);
}

// ---------------- attention output: xbuf = x + q2@kv * z ----------------
__global__ void attn_out_kernel(const __half* __restrict__ q2, const float* __restrict__ kv,
                                const float* __restrict__ z, const float* __restrict__ x,
                                float* __restrict__ xbuf) {
    int bh = blockIdx.x, b = bh >> 3, h = bh & 7;
    int lbase = blockIdx.y * 32;
    __shared__ float kvs[64][64];
    __shared__ float qs[16][64];
    int t = threadIdx.x;
    #pragma unroll
    for (int i = 0; i < 4; i++) {
        int idx = t + i * 256;
        ((float4*)kvs)[idx] = ((const float4*)(kv + (long)bh * 4096))[idx];
    }
    int g = t >> 4;
    int e0 = (t & 15) * 4;
    for (int it = 0; it < 2; it++) {
        __syncthreads();
        int rbase = lbase + it * 16;
        #pragma unroll
        for (int i = 0; i < 4; i++) {
            int idx = t + i * 256;
            int r = idx >> 6, c = idx & 63;
            qs[r][c] = __half2float(q2[((long)bh * Ln + rbase + r) * 64 + c]);
        }
        __syncthreads();
        int l = rbase + g;
        float4 acc = {0.f, 0.f, 0.f, 0.f};
        #pragma unroll
        for (int d = 0; d < 64; d++) {
            float qd = qs[g][d];
            float4 kvv = *(const float4*)&kvs[d][e0];
            acc.x += qd * kvv.x; acc.y += qd * kvv.y;
            acc.z += qd * kvv.z; acc.w += qd * kvv.w;
        }
        float zz = z[(long)bh * Ln + l];
        long off = ((long)(b * Ln + l)) * Cn + h * 64 + e0;
        float4 cur = *(const float4*)&x[off];
        cur.x += acc.x * zz; cur.y += acc.y * zz;
        cur.z += acc.z * zz; cur.w += acc.w * zz;
        *(float4*)&xbuf[off] = cur;
    }
}

// ---------------- weight transposes -> half ----------------
__global__ void transpose_h_kernel(const float* __restrict__ src, __half* __restrict__ dst,
                                   int K, int N) {
    long idx = (long)blockIdx.x * blockDim.x + threadIdx.x;
    if (idx >= (long)K * N) return;
    int k = (int)(idx % K);
    int n = (int)(idx / K);
    dst[idx] = __float2half_rn(src[(long)k * N + n]);
}

// interleaved conv weight: wtT2[n2][kk=k*512+ci], n2 = 2*(co&511) + (co>>9)
__global__ void wtT2_kernel(const float* __restrict__ w, const float* __restrict__ cb,
                            __half* __restrict__ wtT2, float* __restrict__ bias2) {
    long idx = (long)blockIdx.x * blockDim.x + threadIdx.x;   // 1024*1536
    if (idx >= 1024L * 1536) return;
    int kk = (int)(idx % 1536);
    int n2 = (int)(idx / 1536);
    int co = (n2 & 1) * 512 + (n2 >> 1);
    int k  = kk >> 9;
    int ci = kk & 511;
    wtT2[idx] = __float2half_rn(w[co * 1536 + ci * 3 + k]);
    if (kk == 0) bias2[n2] = cb[co];
}

// ================= fp16 mma.sync GEMM =================
// C[M,N] = A[M,K] @ Bt[N,K]^T.  CTA 128x128, K-chunk 32, 3-stage cp.async, 8 warps.
// CONVA=1: A is hb [BL,512] viewed as im2col [BL,1536] with zero-padded taps.
// EPI: 1 = bias + exact GELU (half out); 2 = bias + residual (float out);
//      3 = gated conv (smem-staged coalesced): xbuf += spin + vv*sigmoid(gg);
//      4 = bias (half out).
#define GSM (3 * 16384)

template<int EPI, int CONVA>
__global__ void __launch_bounds__(256, 2)
gemm_h(const __half* __restrict__ A, const __half* __restrict__ Bt,
       const float* __restrict__ bias, const float* __restrict__ res,
       void* __restrict__ Cv, int M, int N, int K) {
    extern __shared__ char smraw[];
    uint32_t sb = smem_u32(smraw);
    int t = threadIdx.x, wid = t >> 5, lane = t & 31;
    int g = lane >> 2, tig = lane & 3;
    int bm = blockIdx.y * 128, bn = blockIdx.x * 128;
    int wm = (wid >> 2) * 64, wn = (wid & 3) * 32;

    // ---- cp.async slots ----
    const __half* aG[2]; const __half* bG[2]; uint32_t offA[2], offB[2];
    int rs[2], cs[2];
    #pragma unroll
    for (int i = 0; i < 2; i++) {
        int idx = t + i * 256;
        int r = idx >> 2;
        int c = idx & 3;
        rs[i] = r; cs[i] = c;
        uint32_t off = (uint32_t)r * 64 + ((c ^ swz(r)) << 4);
        offA[i] = off;
        offB[i] = off + 8192;
        if (!CONVA) aG[i] = A + (long)(bm + r) * K + c * 8;
        bG[i] = Bt + (long)(bn + r) * K + c * 8;
    }

    // ---- ldmatrix address components ----
    uint32_t aRow[4], aSw[4];
    #pragma unroll
    for (int mt = 0; mt < 4; mt++) {
        uint32_t m = wm + mt * 16 + (lane & 15);
        aRow[mt] = m * 64;
        aSw[mt] = swz(m);
    }
    uint32_t cHiA = lane >> 4;
    uint32_t bRow[2], bSw[2];
    #pragma unroll
    for (int np = 0; np < 2; np++) {
        uint32_t n = wn + np * 16 + ((lane >> 4) << 3) + (lane & 7);
        bRow[np] = n * 64 + 8192;
        bSw[np] = swz(n);
    }
    uint32_t cHiB = (lane >> 3) & 1;

    int nk = K >> 5;

    // conv A-loader: chunk kt entirely within tap kt/16
    auto loadA_conv = [&](uint32_t stb, int kt) {
        int tap = kt >> 4;
        int kin = (kt & 15) * 32;
        #pragma unroll
        for (int i = 0; i < 2; i++) {
            long row = bm + rs[i];
            int l = (int)(row & (Ln - 1));
            bool valid = (unsigned)(l + tap - 1) < (unsigned)Ln;
            const __half* src = valid ? (A + (row + tap - 1) * Cn + kin + cs[i] * 8) : A;
            cpasync16z(stb + offA[i], src, valid ? 16u : 0u);
        }
    };

    // prologue
    #pragma unroll
    for (int s = 0; s < 2; s++) {
        uint32_t stb = sb + s * 16384;
        if (CONVA) loadA_conv(stb, s);
        else {
            #pragma unroll
            for (int i = 0; i < 2; i++) cpasync16(stb + offA[i], aG[i] + s * 32);
        }
        #pragma unroll
        for (int i = 0; i < 2; i++) cpasync16(stb + offB[i], bG[i] + s * 32);
        CP_COMMIT();
    }
    CP_WAIT1();
    __syncthreads();

    float acc[4][4][4] = {};

    for (int kt = 0; kt < nk; kt++) {
        if (kt + 2 < nk) {
            uint32_t stb = sb + ((kt + 2) % 3) * 16384;
            if (CONVA) loadA_conv(stb, kt + 2);
            else {
                #pragma unroll
                for (int i = 0; i < 2; i++) cpasync16(stb + offA[i], aG[i] + (long)(kt + 2) * 32);
            }
            #pragma unroll
            for (int i = 0; i < 2; i++) cpasync16(stb + offB[i], bG[i] + (long)(kt + 2) * 32);
        }
        CP_COMMIT();

        uint32_t stb = sb + (kt % 3) * 16384;
        #pragma unroll
        for (int kb = 0; kb < 2; kb++) {
            uint32_t a[4][4], b[4][2];
            #pragma unroll
            for (int mt = 0; mt < 4; mt++) {
                uint32_t addr = stb + aRow[mt] + ((((uint32_t)(2 * kb) | cHiA) ^ aSw[mt]) << 4);
                ldsm4(a[mt], addr);
            }
            #pragma unroll
            for (int np = 0; np < 2; np++) {
                uint32_t bb[4];
                uint32_t addr = stb + bRow[np] + ((((uint32_t)(2 * kb) | cHiB) ^ bSw[np]) << 4);
                ldsm4(bb, addr);
                b[2*np][0] = bb[0]; b[2*np][1] = bb[1];
                b[2*np+1][0] = bb[2]; b[2*np+1][1] = bb[3];
            }
            #pragma unroll
            for (int mt = 0; mt < 4; mt++)
                #pragma unroll
                for (int nt = 0; nt < 4; nt++)
                    mma_f16(acc[mt][nt], a[mt], b[nt]);
        }

        CP_WAIT1();
        __syncthreads();
    }

    // ---- epilogue ----
    if (EPI == 3) {
        // stage gated values in smem (row stride 68 floats to dodge bank conflicts),
        // then coalesced float4 update: xbuf += spin + gated
        float* sg = (float*)smraw;             // 128 * 68 * 4B = 34816 B < GSM
        #pragma unroll
        for (int mt = 0; mt < 4; mt++) {
            int r0 = wm + mt * 16 + g;
            #pragma unroll
            for (int nt = 0; nt < 4; nt++) {
                int col = wn + nt * 8 + tig * 2;           // block-local, even
                float b0 = bias[bn + col], b1 = bias[bn + col + 1];
                float vv0 = acc[mt][nt][0] + b0, gg0 = acc[mt][nt][1] + b1;
                float vv1 = acc[mt][nt][2] + b0, gg1 = acc[mt][nt][3] + b1;
                int cp = col >> 1;                          // 0..63
                sg[r0 * 68 + cp]       = vv0 / (1.0f + expf(-gg0));
                sg[(r0 + 8) * 68 + cp] = vv1 / (1.0f + expf(-gg1));
            }
        }
        __syncthreads();
        int cpb = bn >> 1;                                  // global output col base
        float* X = (float*)Cv;
        #pragma unroll
        for (int i = 0; i < 8; i++) {
            int j = t + i * 256;                            // 0..2047
            int r = j >> 4, c4 = j & 15;
            long off = (long)(bm + r) * Cn + cpb + c4 * 4;
            float4 xv = *(float4*)(X + off);
            float4 sp = *(const float4*)(res + off);
            float4 gv = *(float4*)&sg[r * 68 + c4 * 4];
            xv.x += sp.x + gv.x; xv.y += sp.y + gv.y;
            xv.z += sp.z + gv.z; xv.w += sp.w + gv.w;
            *(float4*)(X + off) = xv;
        }
        return;
    }

    #pragma unroll
    for (int mt = 0; mt < 4; mt++) {
        int row = bm + wm + mt * 16 + g;
        #pragma unroll
        for (int nt = 0; nt < 4; nt++) {
            int col = bn + wn + nt * 8 + tig * 2;
            float b0 = bias[col], b1 = bias[col + 1];
            float v00 = acc[mt][nt][0] + b0;
            float v01 = acc[mt][nt][1] + b1;
            float v10 = acc[mt][nt][2] + b0;
            float v11 = acc[mt][nt][3] + b1;
            if (EPI == 1) {
                v00 = 0.5f * v00 * (1.0f + erff(v00 * 0.70710678118654752f));
                v01 = 0.5f * v01 * (1.0f + erff(v01 * 0.70710678118654752f));
                v10 = 0.5f * v10 * (1.0f + erff(v10 * 0.70710678118654752f));
                v11 = 0.5f * v11 * (1.0f + erff(v11 * 0.70710678118654752f));
                __half2* C = (__half2*)Cv;
                C[((long)row * N + col) >> 1]       = __floats2half2_rn(v00, v01);
                C[((long)(row + 8) * N + col) >> 1] = __floats2half2_rn(v10, v11);
            } else if (EPI == 4) {
                __half2* C = (__half2*)Cv;
                C[((long)row * N + col) >> 1]       = __floats2half2_rn(v00, v01);
                C[((long)(row + 8) * N + col) >> 1] = __floats2half2_rn(v10, v11);
            } else {  // EPI == 2
                const float* r0 = res + (long)row * N + col;
                const float* r1 = res + (long)(row + 8) * N + col;
                v00 += r0[0]; v01 += r0[1];
                v10 += r1[0]; v11 += r1[1];
                float* C = (float*)Cv;
                float2 p0 = {v00, v01}, p1 = {v10, v11};
                *(float2*)(C + (long)row * N + col)       = p0;
                *(float2*)(C + (long)(row + 8) * N + col) = p1;
            }
        }
    }
}

// ---------------- host launcher ----------------
extern "C" void kernel_launch(void* const* d_in, const int* in_sizes, int n_in,
                              void* d_out, int out_size) {
    const float* x      = (const float*)d_in[0];
    const float* g1     = (const float*)d_in[1];
    const float* b1     = (const float*)d_in[2];
    const float* qk_w   = (const float*)d_in[3];
    const float* qk_b   = (const float*)d_in[4];
    const float* v_w    = (const float*)d_in[5];
    const float* v_b    = (const float*)d_in[6];
    const float* lepe_w = (const float*)d_in[7];
    const float* lepe_b = (const float*)d_in[8];
    const float* g2     = (const float*)d_in[9];
    const float* b2     = (const float*)d_in[10];
    const float* spn_g  = (const float*)d_in[11];
    const float* spn_b  = (const float*)d_in[12];
    const float* sp_cw  = (const float*)d_in[13];
    const float* sp_cb  = (const float*)d_in[14];
    const float* g3     = (const float*)d_in[15];
    const float* b3     = (const float*)d_in[16];
    const float* w1     = (const float*)d_in[17];
    const float* bb1    = (const float*)d_in[18];
    const float* w2     = (const float*)d_in[19];
    const float* bb2    = (const float*)d_in[20];
    float* out = (float*)d_out;

    float *xbuf, *km, *kv, *kvpart, *z, *spin, *bias2;
    __half *lnh, *qkh, *vh, *q2h, *k2h, *hb, *ffnh, *qkTh, *vTh, *w1Th, *w2Th, *wtT2h;
    cudaGetSymbolAddress((void**)&xbuf,   g_xbuf);
    cudaGetSymbolAddress((void**)&lnh,    g_lnh);
    cudaGetSymbolAddress((void**)&qkh,    g_qkh);
    cudaGetSymbolAddress((void**)&vh,     g_vh);
    cudaGetSymbolAddress((void**)&q2h,    g_q2h);
    cudaGetSymbolAddress((void**)&k2h,    g_k2h);
    cudaGetSymbolAddress((void**)&km,     g_kmean);
    cudaGetSymbolAddress((void**)&kv,     g_kv);
    cudaGetSymbolAddress((void**)&kvpart, g_kvpart);
    cudaGetSymbolAddress((void**)&z,      g_z);
    cudaGetSymbolAddress((void**)&spin,   g_spin);
    cudaGetSymbolAddress((void**)&hb,     g_hb);
    cudaGetSymbolAddress((void**)&ffnh,   g_ffnh);
    cudaGetSymbolAddress((void**)&qkTh,   g_qkTh);
    cudaGetSymbolAddress((void**)&vTh,    g_vTh);
    cudaGetSymbolAddress((void**)&w1Th,   g_w1Th);
    cudaGetSymbolAddress((void**)&w2Th,   g_w2Th);
    cudaGetSymbolAddress((void**)&wtT2h,  g_wtT2h);
    cudaGetSymbolAddress((void**)&bias2,  g_bias2);

    cudaFuncSetAttribute((const void*)gemm_h<4,0>, cudaFuncAttributeMaxDynamicSharedMemorySize, GSM);
    cudaFuncSetAttribute((const void*)gemm_h<3,1>, cudaFuncAttributeMaxDynamicSharedMemorySize, GSM);
    cudaFuncSetAttribute((const void*)gemm_h<1,0>, cudaFuncAttributeMaxDynamicSharedMemorySize, GSM);
    cudaFuncSetAttribute((const void*)gemm_h<2,0>, cudaFuncAttributeMaxDynamicSharedMemorySize, GSM);

    // weight transposes (half)
    transpose_h_kernel<<<(512 * 1024 + 255) / 256, 256>>>(qk_w, qkTh, 512, 1024);
    transpose_h_kernel<<<(512 * 512 + 255) / 256, 256>>>(v_w, vTh, 512, 512);
    transpose_h_kernel<<<(512 * 2048 + 255) / 256, 256>>>(w1, w1Th, 512, 2048);
    transpose_h_kernel<<<(2048 * 512 + 255) / 256, 256>>>(w2, w2Th, 2048, 512);
    wtT2_kernel<<<(1024 * 1536 + 255) / 256, 256>>>(sp_cw, sp_cb, wtT2h, bias2);

    // Block 1: xbuf = x + attn(LN1(x))
    ln_h_kernel<<<BLn, 128>>>(x, g1, b1, lnh);
    gemm_h<4,0><<<dim3(1024 / 128, BLn / 128), 256, GSM>>>(lnh, qkTh, qk_b, nullptr, qkh, BLn, 1024, Cn);
    gemm_h<4,0><<<dim3(512 / 128, BLn / 128), 256, GSM>>>(lnh, vTh, v_b, nullptr, vh, BLn, 512, Cn);
    qk_post_kernel<<<(BHLn * Dn) / 256, 256>>>(qkh, lepe_w, lepe_b, q2h, k2h);
    kmean_kernel<<<BHn, 256>>>(k2h, km);
    z_kernel<<<BHLn / 8, 256>>>(q2h, km, z);
    kv_kernel<<<dim3(BHn, KVCHUNKS), 256>>>(k2h, vh, kvpart);
    kv_reduce_kernel<<<(BHn * Dn * Dn) / 256, 256>>>(kvpart, kv);
    attn_out_kernel<<<dim3(BHn, Ln / 32), 256>>>(q2h, kv, z, x, xbuf);

    // Block 2: gated conv state path (fused LN2+LN3, direct-conv GEMM + staged fused gate)
    ln2ln3_kernel<<<BLn, 128>>>(xbuf, g2, b2, spn_g, spn_b, spin, hb);
    gemm_h<3,1><<<dim3(1024 / 128, BLn / 128), 256, GSM>>>(hb, wtT2h, bias2, spin, xbuf, BLn, 1024, 3 * Cn);

    // Block 3: FFN
    ln_h_kernel<<<BLn, 128>>>(xbuf, g3, b3, lnh);
    gemm_h<1,0><<<dim3(FFn / 128, BLn / 128), 256, GSM>>>(lnh, w1Th, bb1, nullptr, ffnh, BLn, FFn, Cn);
    gemm_h<2,0><<<dim3(512 / 128, BLn / 128), 256, GSM>>>(ffnh, w2Th, bb2, xbuf, out, BLn, 512, FFn);
}

// round 8
// speedup vs baseline: 1.3366x; 1.1777x over previous
#include <cuda_runtime.h>
#include <cuda_fp16.h>
#include <math.h>
#include <stdint.h>

#define Bn 8
#define Ln 2048
#define Cn 512
#define Hn 8
#define Dn 64
#define FFn 2048
#define BLn (Bn*Ln)          /* 16384 */
#define BHn (Bn*Hn)          /* 64    */
#define BHLn (BHn*Ln)        /* 131072*/
#define KVCHUNKS 8

// ---------------- scratch (static device globals; no allocation) ----------------
static __device__ __align__(16) float  g_xbuf[BLn*Cn];
static __device__ __align__(16) __half g_lnh[BLn*Cn];
static __device__ __align__(16) __half g_qkh[BLn*2*Cn];
static __device__ __align__(16) __half g_vh[BLn*Cn];
static __device__ __align__(16) __half g_q2h[BHLn*Dn];
static __device__ __align__(16) __half g_k2h[BHLn*Dn];
static __device__ __align__(16) float  g_kmean[BHn*Dn];
static __device__ __align__(16) float  g_kv[BHn*Dn*Dn];
static __device__ __align__(16) float  g_kvpart[KVCHUNKS*BHn*Dn*Dn];
static __device__ __align__(16) __half g_spinh[BLn*Cn];
static __device__ __align__(16) __half g_hb[BLn*Cn];
static __device__ __align__(16) __half g_ffnh[(long)BLn*FFn];
// transposed (N-major) half weights: B^T [N,K] row-major
static __device__ __align__(16) __half g_qkTh[1024*512];
static __device__ __align__(16) __half g_vTh[512*512];
static __device__ __align__(16) __half g_w1Th[2048*512];
static __device__ __align__(16) __half g_w2Th[512*2048];
static __device__ __align__(16) __half g_wtT2h[1024*1536];   // interleaved (vv,gg) pairs
static __device__ __align__(16) float  g_bias2[1024];

// ---------------- PTX helpers ----------------
__device__ __forceinline__ uint32_t smem_u32(const void* p) {
    uint32_t a;
    asm("{ .reg .u64 t; cvta.to.shared.u64 t, %1; cvt.u32.u64 %0, t; }" : "=r"(a) : "l"(p));
    return a;
}
__device__ __forceinline__ void cpasync16(uint32_t saddr, const void* g) {
    asm volatile("cp.async.cg.shared.global [%0], [%1], 16;" :: "r"(saddr), "l"(g) : "memory");
}
__device__ __forceinline__ void cpasync16z(uint32_t saddr, const void* g, uint32_t sz) {
    asm volatile("cp.async.cg.shared.global [%0], [%1], 16, %2;"
                 :: "r"(saddr), "l"(g), "r"(sz) : "memory");
}
#define CP_COMMIT() asm volatile("cp.async.commit_group;" ::: "memory")
#define CP_WAIT1()  asm volatile("cp.async.wait_group 1;" ::: "memory")

__device__ __forceinline__ void ldsm4(uint32_t* r, uint32_t addr) {
    asm volatile("ldmatrix.sync.aligned.m8n8.x4.shared.b16 {%0,%1,%2,%3}, [%4];"
        : "=r"(r[0]), "=r"(r[1]), "=r"(r[2]), "=r"(r[3]) : "r"(addr));
}
__device__ __forceinline__ void mma_f16(float* c, const uint32_t* a, const uint32_t* b) {
    asm volatile(
        "mma.sync.aligned.m16n8k16.row.col.f32.f16.f16.f32 "
        "{%0,%1,%2,%3}, {%4,%5,%6,%7}, {%8,%9}, {%0,%1,%2,%3};"
        : "+f"(c[0]), "+f"(c[1]), "+f"(c[2]), "+f"(c[3])
        : "r"(a[0]), "r"(a[1]), "r"(a[2]), "r"(a[3]), "r"(b[0]), "r"(b[1]));
}

// ---------------- small helpers ----------------
__device__ __forceinline__ float elu1(float x) { return x > 0.0f ? x + 1.0f : expf(x); }
__device__ __forceinline__ uint32_t swz(uint32_t r) { return (r ^ (r >> 2)) & 3u; }

// ---------------- LayerNorm (half out) ----------------
__global__ void ln_h_kernel(const float* __restrict__ in, const float* __restrict__ gam,
                            const float* __restrict__ bet, __half* __restrict__ out) {
    int row = blockIdx.x;
    int t = threadIdx.x;
    const float4 v = ((const float4*)(in + (long)row * Cn))[t];
    float s  = v.x + v.y + v.z + v.w;
    float sq = v.x*v.x + v.y*v.y + v.z*v.z + v.w*v.w;
    #pragma unroll
    for (int o = 16; o; o >>= 1) {
        s  += __shfl_xor_sync(0xFFFFFFFFu, s,  o);
        sq += __shfl_xor_sync(0xFFFFFFFFu, sq, o);
    }
    __shared__ float ss[4], ssq[4];
    if ((t & 31) == 0) { ss[t >> 5] = s; ssq[t >> 5] = sq; }
    __syncthreads();
    s  = ss[0] + ss[1] + ss[2] + ss[3];
    sq = ssq[0] + ssq[1] + ssq[2] + ssq[3];
    float mu   = s * (1.0f / Cn);
    float var  = sq * (1.0f / Cn) - mu * mu;
    float rstd = rsqrtf(var + 1e-5f);
    float4 g4 = ((const float4*)gam)[t];
    float4 b4 = ((const float4*)bet)[t];
    __half2* o = (__half2*)(out + (long)row * Cn);
    o[t * 2]     = __floats2half2_rn((v.x - mu) * rstd * g4.x + b4.x,
                                     (v.y - mu) * rstd * g4.y + b4.y);
    o[t * 2 + 1] = __floats2half2_rn((v.z - mu) * rstd * g4.z + b4.z,
                                     (v.w - mu) * rstd * g4.w + b4.w);
}

// ---------------- fused LN2 + LN3: xbuf -> spin (half), hb = LN3(spin_f32) (half) ----------------
__global__ void ln2ln3_kernel(const float* __restrict__ in,
                              const float* __restrict__ g2, const float* __restrict__ b2,
                              const float* __restrict__ g3, const float* __restrict__ b3,
                              __half* __restrict__ spin, __half* __restrict__ hb) {
    int row = blockIdx.x;
    int t = threadIdx.x;
    __shared__ float ss[4], ssq[4];
    const float4 v = ((const float4*)(in + (long)row * Cn))[t];
    float s  = v.x + v.y + v.z + v.w;
    float sq = v.x*v.x + v.y*v.y + v.z*v.z + v.w*v.w;
    #pragma unroll
    for (int o = 16; o; o >>= 1) {
        s  += __shfl_xor_sync(0xFFFFFFFFu, s,  o);
        sq += __shfl_xor_sync(0xFFFFFFFFu, sq, o);
    }
    if ((t & 31) == 0) { ss[t >> 5] = s; ssq[t >> 5] = sq; }
    __syncthreads();
    s  = ss[0] + ss[1] + ss[2] + ss[3];
    sq = ssq[0] + ssq[1] + ssq[2] + ssq[3];
    float mu   = s * (1.0f / Cn);
    float var  = sq * (1.0f / Cn) - mu * mu;
    float rstd = rsqrtf(var + 1e-5f);
    float4 gg = ((const float4*)g2)[t];
    float4 bb = ((const float4*)b2)[t];
    float4 o1;
    o1.x = (v.x - mu) * rstd * gg.x + bb.x;
    o1.y = (v.y - mu) * rstd * gg.y + bb.y;
    o1.z = (v.z - mu) * rstd * gg.z + bb.z;
    o1.w = (v.w - mu) * rstd * gg.w + bb.w;
    __half2* sp = (__half2*)(spin + (long)row * Cn);
    sp[t * 2]     = __floats2half2_rn(o1.x, o1.y);
    sp[t * 2 + 1] = __floats2half2_rn(o1.z, o1.w);
    // second LN over o1 (fp32)
    float s2  = o1.x + o1.y + o1.z + o1.w;
    float sq2 = o1.x*o1.x + o1.y*o1.y + o1.z*o1.z + o1.w*o1.w;
    #pragma unroll
    for (int o = 16; o; o >>= 1) {
        s2  += __shfl_xor_sync(0xFFFFFFFFu, s2,  o);
        sq2 += __shfl_xor_sync(0xFFFFFFFFu, sq2, o);
    }
    __syncthreads();
    if ((t & 31) == 0) { ss[t >> 5] = s2; ssq[t >> 5] = sq2; }
    __syncthreads();
    s2  = ss[0] + ss[1] + ss[2] + ss[3];
    sq2 = ssq[0] + ssq[1] + ssq[2] + ssq[3];
    float mu2   = s2 * (1.0f / Cn);
    float var2  = sq2 * (1.0f / Cn) - mu2 * mu2;
    float rstd2 = rsqrtf(var2 + 1e-5f);
    float4 g4 = ((const float4*)g3)[t];
    float4 b4 = ((const float4*)b3)[t];
    __half2* o = (__half2*)(hb + (long)row * Cn);
    o[t * 2]     = __floats2half2_rn((o1.x - mu2) * rstd2 * g4.x + b4.x,
                                     (o1.y - mu2) * rstd2 * g4.y + b4.y);
    o[t * 2 + 1] = __floats2half2_rn((o1.z - mu2) * rstd2 * g4.z + b4.z,
                                     (o1.w - mu2) * rstd2 * g4.w + b4.w);
}

// ---------------- qk post: elu+1 then LePE, smem-tiled coalesced ----------------
// grid (BHn, Ln/64), 256 threads. Tile: 64 l x 64 d, both sel.
// identity tile: src rows l0..l0+63 (cols d).  tap tile: src rows d*32+lt (cols c),
// where flat fi = d*2048 + l0 + c; plus halo elems (row d*32+lt-1 col 63 / +1 col 0).
__global__ void qk_post_kernel(const __half* __restrict__ qk,
                               const float* __restrict__ lw, const float* __restrict__ lb,
                               __half* __restrict__ q2, __half* __restrict__ k2) {
    int bh = blockIdx.x;
    int lt = blockIdx.y;
    int l0 = lt * 64;
    int b = bh >> 3, h = bh & 7;
    const __half* base = qk + (long)b * Ln * 1024 + h * 64;
    __shared__ __half sId[2][64][64];
    __shared__ __half sTapT[2][64][66];   // [sel][c][d] transposed, 66 pad: conflict-free compute reads
    __shared__ __half sLo[2][64], sHi[2][64];
    int t = threadIdx.x;
    #pragma unroll
    for (int sel = 0; sel < 2; sel++) {
        #pragma unroll
        for (int i = 0; i < 2; i++) {
            int idx = t + i * 256;               // 0..511
            int r  = idx >> 3;                   // row / d 0..63
            int c8 = (idx & 7) * 8;
            *(uint4*)&sId[sel][r][c8] =
                *(const uint4*)&base[(long)(l0 + r) * 1024 + sel * 512 + c8];
            __half tmp[8];
            *(uint4*)tmp = *(const uint4*)&base[(long)(r * 32 + lt) * 1024 + sel * 512 + c8];
            #pragma unroll
            for (int k = 0; k < 8; k++) sTapT[sel][c8 + k][r] = tmp[k];
        }
    }
    if (t < 128) {
        int sel = t >> 6, d = t & 63;
        __half lo = __ushort_as_half((unsigned short)0), hi = lo;
        if (l0 > 0)       lo = base[(long)(d * 32 + lt - 1) * 1024 + sel * 512 + 63];
        if (l0 + 64 < Ln) hi = base[(long)(d * 32 + lt + 1) * 1024 + sel * 512];
        sLo[sel][d] = lo;
        sHi[sel][d] = hi;
    }
    __syncthreads();
    int d2 = (t & 31) * 2, rb = t >> 5;           // 2 d per thread, 8 r per thread
    bool hasLo = (l0 > 0), hasHi = (l0 + 64 < Ln);
    #pragma unroll
    for (int sel = 0; sel < 2; sel++) {
        __half* dst = sel ? k2 : q2;
        float w0[2], w1[2], w2[2], bi[2];
        #pragma unroll
        for (int dd = 0; dd < 2; dd++) {
            int d = d2 + dd;
            w0[dd] = lw[d*3]; w1[dd] = lw[d*3+1]; w2[dd] = lw[d*3+2]; bi[dd] = lb[d];
        }
        #pragma unroll
        for (int i = 0; i < 8; i++) {
            int r = rb + i * 8;
            float o[2];
            #pragma unroll
            for (int dd = 0; dd < 2; dd++) {
                int d = d2 + dd;
                float acc = elu1(__half2float(sId[sel][r][d])) + bi[dd];
                float c1 = elu1(__half2float(sTapT[sel][r][d]));
                float c0 = (r > 0) ? elu1(__half2float(sTapT[sel][r-1][d]))
                                   : (hasLo ? elu1(__half2float(sLo[sel][d])) : 0.0f);
                float c2 = (r < 63) ? elu1(__half2float(sTapT[sel][r+1][d]))
                                    : (hasHi ? elu1(__half2float(sHi[sel][d])) : 0.0f);
                o[dd] = acc + w0[dd] * c0 + w1[dd] * c1 + w2[dd] * c2;
            }
            *(__half2*)&dst[(long)bh * (Ln * Dn) + (long)(l0 + r) * 64 + d2] =
                __floats2half2_rn(o[0], o[1]);
        }
    }
}

// ---------------- k mean ----------------
__global__ void kmean_kernel(const __half* __restrict__ k2, float* __restrict__ km) {
    int bh = blockIdx.x;
    int t = threadIdx.x;
    int d = t & 63, part = t >> 6;
    float s = 0.0f;
    const __half* base = k2 + (long)bh * Ln * Dn;
    for (int l = part; l < Ln; l += 4) s += __half2float(base[l * 64 + d]);
    __shared__ float sm[4][64];
    sm[part][d] = s;
    __syncthreads();
    if (part == 0)
        km[bh * 64 + d] = (sm[0][d] + sm[1][d] + sm[2][d] + sm[3][d]) * (1.0f / Ln);
}

// ---------------- kv partials (half inputs, fp32 accumulate) ----------------
__global__ void kv_kernel(const __half* __restrict__ k2, const __half* __restrict__ v,
                          float* __restrict__ part) {
    int bh = blockIdx.x, chunk = blockIdx.y;
    int b = bh >> 3, h = bh & 7;
    __shared__ float ks[32][64];
    __shared__ float vs[32][64];
    int t = threadIdx.x;
    int e0 = (t & 15) * 4, d0 = (t >> 4) * 4;
    float acc[4][4] = {};
    int lc = Ln / KVCHUNKS;
    for (int l0 = chunk * lc; l0 < chunk * lc + lc; l0 += 32) {
        #pragma unroll
        for (int i = 0; i < 2; i++) {
            int idx = t + i * 256;
            int r = idx >> 4, c4 = (idx & 15) * 4;
            int l = l0 + r;
            uint2 kr = *(const uint2*)&k2[((long)bh * Ln + l) * 64 + c4];
            uint2 vr = *(const uint2*)&v[((long)(b * Ln + l)) * Cn + h * 64 + c4];
            float2 k0 = __half22float2(*(__half2*)&kr.x);
            float2 k1 = __half22float2(*(__half2*)&kr.y);
            float2 v0 = __half22float2(*(__half2*)&vr.x);
            float2 v1 = __half22float2(*(__half2*)&vr.y);
            ks[r][c4] = k0.x; ks[r][c4+1] = k0.y; ks[r][c4+2] = k1.x; ks[r][c4+3] = k1.y;
            vs[r][c4] = v0.x; vs[r][c4+1] = v0.y; vs[r][c4+2] = v1.x; vs[r][c4+3] = v1.y;
        }
        __syncthreads();
        #pragma unroll
        for (int l = 0; l < 32; l++) {
            float4 kr = *(const float4*)&ks[l][d0];
            float4 vr = *(const float4*)&vs[l][e0];
            float k_[4] = {kr.x, kr.y, kr.z, kr.w};
            float v_[4] = {vr.x, vr.y, vr.z, vr.w};
            #pragma unroll
            for (int i = 0; i < 4; i++)
                #pragma unroll
                for (int j = 0; j < 4; j++)
                    acc[i][j] += k_[i] * v_[j];
        }
        __syncthreads();
    }
    float* dst = part + ((long)chunk * BHn + bh) * (Dn * Dn);
    #pragma unroll
    for (int i = 0; i < 4; i++)
        #pragma unroll
        for (int j = 0; j < 4; j++)
            dst[(d0 + i) * 64 + e0 + j] = acc[i][j];
}

__global__ void kv_reduce_kernel(const float* __restrict__ part, float* __restrict__ kv) {
    int i = blockIdx.x * blockDim.x + threadIdx.x;
    float s = 0.0f;
    #pragma unroll
    for (int c = 0; c < KVCHUNKS; c++) s += part[(long)c * (BHn * Dn * Dn) + i];
    kv[i] = s * (1.0f / Ln);
}

// ---------------- attention output: xbuf = x + (q2@kv) * z, z fused ----------------
__global__ void attn_out_kernel(const __half* __restrict__ q2, const float* __restrict__ kv,
                                const float* __restrict__ km, const float* __restrict__ x,
                                float* __restrict__ xbuf) {
    int bh = blockIdx.x, b = bh >> 3, h = bh & 7;
    int lbase = blockIdx.y * 32;
    __shared__ float kvs[64][64];
    __shared__ float qs[16][64];
    __shared__ float skm[64];
    int t = threadIdx.x;
    #pragma unroll
    for (int i = 0; i < 4; i++) {
        int idx = t + i * 256;
        ((float4*)kvs)[idx] = ((const float4*)(kv + (long)bh * 4096))[idx];
    }
    if (t < 64) skm[t] = km[bh * 64 + t];
    int g = t >> 4;
    int e0 = (t & 15) * 4;
    for (int it = 0; it < 2; it++) {
        __syncthreads();
        int rbase = lbase + it * 16;
        #pragma unroll
        for (int i = 0; i < 4; i++) {
            int idx = t + i * 256;
            int r = idx >> 6, c = idx & 63;
            qs[r][c] = __half2float(q2[((long)bh * Ln + rbase + r) * 64 + c]);
        }
        __syncthreads();
        int l = rbase + g;
        // fused z: dot(q_row, km) over 16 lanes
        float part = qs[g][e0] * skm[e0] + qs[g][e0+1] * skm[e0+1]
                   + qs[g][e0+2] * skm[e0+2] + qs[g][e0+3] * skm[e0+3];
        #pragma unroll
        for (int o = 8; o; o >>= 1) part += __shfl_xor_sync(0xFFFFFFFFu, part, o);
        float zz = 1.0f / (part + 1e-6f);
        float4 acc = {0.f, 0.f, 0.f, 0.f};
        #pragma unroll
        for (int d = 0; d < 64; d++) {
            float qd = qs[g][d];
            float4 kvv = *(const float4*)&kvs[d][e0];
            acc.x += qd * kvv.x; acc.y += qd * kvv.y;
            acc.z += qd * kvv.z; acc.w += qd * kvv.w;
        }
        long off = ((long)(b * Ln + l)) * Cn + h * 64 + e0;
        float4 cur = *(const float4*)&x[off];
        cur.x += acc.x * zz; cur.y += acc.y * zz;
        cur.z += acc.z * zz; cur.w += acc.w * zz;
        *(float4*)&xbuf[off] = cur;
    }
}

// ---------------- weight transposes -> half ----------------
__global__ void transpose_h_kernel(const float* __restrict__ src, __half* __restrict__ dst,
                                   int K, int N) {
    long idx = (long)blockIdx.x * blockDim.x + threadIdx.x;
    if (idx >= (long)K * N) return;
    int k = (int)(idx % K);
    int n = (int)(idx / K);
    dst[idx] = __float2half_rn(src[(long)k * N + n]);
}

// interleaved conv weight: wtT2[n2][kk=k*512+ci], n2 = 2*(co&511) + (co>>9)
__global__ void wtT2_kernel(const float* __restrict__ w, const float* __restrict__ cb,
                            __half* __restrict__ wtT2, float* __restrict__ bias2) {
    long idx = (long)blockIdx.x * blockDim.x + threadIdx.x;   // 1024*1536
    if (idx >= 1024L * 1536) return;
    int kk = (int)(idx % 1536);
    int n2 = (int)(idx / 1536);
    int co = (n2 & 1) * 512 + (n2 >> 1);
    int k  = kk >> 9;
    int ci = kk & 511;
    wtT2[idx] = __float2half_rn(w[co * 1536 + ci * 3 + k]);
    if (kk == 0) bias2[n2] = cb[co];
}

// ================= fp16 mma.sync GEMM =================
// C[M,N] = A[M,K] @ Bt[N,K]^T.  CTA 128x128, K-chunk 32, 3-stage cp.async, 8 warps.
// CONVA=1: A is hb [BL,512] viewed as im2col [BL,1536] with zero-padded taps.
// EPI: 1 = bias + exact GELU (half out); 2 = bias + residual f32 (float out);
//      3 = gated conv (smem-staged coalesced): xbuf += spin(half) + vv*sigmoid(gg);
//      4 = bias (half out).
#define GSM (3 * 16384)

template<int EPI, int CONVA>
__global__ void __launch_bounds__(256, 2)
gemm_h(const __half* __restrict__ A, const __half* __restrict__ Bt,
       const float* __restrict__ bias, const void* __restrict__ resv,
       void* __restrict__ Cv, int M, int N, int K) {
    extern __shared__ char smraw[];
    uint32_t sb = smem_u32(smraw);
    int t = threadIdx.x, wid = t >> 5, lane = t & 31;
    int g = lane >> 2, tig = lane & 3;
    int bm = blockIdx.y * 128, bn = blockIdx.x * 128;
    int wm = (wid >> 2) * 64, wn = (wid & 3) * 32;

    // ---- cp.async slots ----
    const __half* aG[2]; const __half* bG[2]; uint32_t offA[2], offB[2];
    int rs[2], cs[2];
    #pragma unroll
    for (int i = 0; i < 2; i++) {
        int idx = t + i * 256;
        int r = idx >> 2;
        int c = idx & 3;
        rs[i] = r; cs[i] = c;
        uint32_t off = (uint32_t)r * 64 + ((c ^ swz(r)) << 4);
        offA[i] = off;
        offB[i] = off + 8192;
        if (!CONVA) aG[i] = A + (long)(bm + r) * K + c * 8;
        bG[i] = Bt + (long)(bn + r) * K + c * 8;
    }

    // ---- ldmatrix address components ----
    uint32_t aRow[4], aSw[4];
    #pragma unroll
    for (int mt = 0; mt < 4; mt++) {
        uint32_t m = wm + mt * 16 + (lane & 15);
        aRow[mt] = m * 64;
        aSw[mt] = swz(m);
    }
    uint32_t cHiA = lane >> 4;
    uint32_t bRow[2], bSw[2];
    #pragma unroll
    for (int np = 0; np < 2; np++) {
        uint32_t n = wn + np * 16 + ((lane >> 4) << 3) + (lane & 7);
        bRow[np] = n * 64 + 8192;
        bSw[np] = swz(n);
    }
    uint32_t cHiB = (lane >> 3) & 1;

    int nk = K >> 5;

    auto loadA_conv = [&](uint32_t stb, int kt) {
        int tap = kt >> 4;
        int kin = (kt & 15) * 32;
        #pragma unroll
        for (int i = 0; i < 2; i++) {
            long row = bm + rs[i];
            int l = (int)(row & (Ln - 1));
            bool valid = (unsigned)(l + tap - 1) < (unsigned)Ln;
            const __half* src = valid ? (A + (row + tap - 1) * Cn + kin + cs[i] * 8) : A;
            cpasync16z(stb + offA[i], src, valid ? 16u : 0u);
        }
    };

    // prologue
    #pragma unroll
    for (int s = 0; s < 2; s++) {
        uint32_t stb = sb + s * 16384;
        if (CONVA) loadA_conv(stb, s);
        else {
            #pragma unroll
            for (int i = 0; i < 2; i++) cpasync16(stb + offA[i], aG[i] + s * 32);
        }
        #pragma unroll
        for (int i = 0; i < 2; i++) cpasync16(stb + offB[i], bG[i] + s * 32);
        CP_COMMIT();
    }
    CP_WAIT1();
    __syncthreads();

    float acc[4][4][4] = {};

    for (int kt = 0; kt < nk; kt++) {
        if (kt + 2 < nk) {
            uint32_t stb = sb + ((kt + 2) % 3) * 16384;
            if (CONVA) loadA_conv(stb, kt + 2);
            else {
                #pragma unroll
                for (int i = 0; i < 2; i++) cpasync16(stb + offA[i], aG[i] + (long)(kt + 2) * 32);
            }
            #pragma unroll
            for (int i = 0; i < 2; i++) cpasync16(stb + offB[i], bG[i] + (long)(kt + 2) * 32);
        }
        CP_COMMIT();

        uint32_t stb = sb + (kt % 3) * 16384;
        #pragma unroll
        for (int kb = 0; kb < 2; kb++) {
            uint32_t a[4][4], b[4][2];
            #pragma unroll
            for (int mt = 0; mt < 4; mt++) {
                uint32_t addr = stb + aRow[mt] + ((((uint32_t)(2 * kb) | cHiA) ^ aSw[mt]) << 4);
                ldsm4(a[mt], addr);
            }
            #pragma unroll
            for (int np = 0; np < 2; np++) {
                uint32_t bb[4];
                uint32_t addr = stb + bRow[np] + ((((uint32_t)(2 * kb) | cHiB) ^ bSw[np]) << 4);
                ldsm4(bb, addr);
                b[2*np][0] = bb[0]; b[2*np][1] = bb[1];
                b[2*np+1][0] = bb[2]; b[2*np+1][1] = bb[3];
            }
            #pragma unroll
            for (int mt = 0; mt < 4; mt++)
                #pragma unroll
                for (int nt = 0; nt < 4; nt++)
                    mma_f16(acc[mt][nt], a[mt], b[nt]);
        }

        CP_WAIT1();
        __syncthreads();
    }

    // ---- epilogue ----
    if (EPI == 3) {
        // stage gated values in smem, then coalesced update: xbuf += spin(half) + gated
        float* sg = (float*)smraw;             // 128*68*4 = 34816 B < GSM
        #pragma unroll
        for (int mt = 0; mt < 4; mt++) {
            int r0 = wm + mt * 16 + g;
            #pragma unroll
            for (int nt = 0; nt < 4; nt++) {
                int col = wn + nt * 8 + tig * 2;
                float b0 = bias[bn + col], b1 = bias[bn + col + 1];
                float vv0 = acc[mt][nt][0] + b0, gg0 = acc[mt][nt][1] + b1;
                float vv1 = acc[mt][nt][2] + b0, gg1 = acc[mt][nt][3] + b1;
                int cp = col >> 1;
                sg[r0 * 68 + cp]       = vv0 / (1.0f + expf(-gg0));
                sg[(r0 + 8) * 68 + cp] = vv1 / (1.0f + expf(-gg1));
            }
        }
        __syncthreads();
        int cpb = bn >> 1;
        float* X = (float*)Cv;
        const __half* R = (const __half*)resv;
        #pragma unroll
        for (int i = 0; i < 8; i++) {
            int j = t + i * 256;
            int r = j >> 4, c4 = j & 15;
            long off = (long)(bm + r) * Cn + cpb + c4 * 4;
            float4 xv = *(float4*)(X + off);
            uint2 spraw = *(const uint2*)(R + off);
            float2 s0 = __half22float2(*(__half2*)&spraw.x);
            float2 s1 = __half22float2(*(__half2*)&spraw.y);
            float4 gv = *(float4*)&sg[r * 68 + c4 * 4];
            xv.x += s0.x + gv.x; xv.y += s0.y + gv.y;
            xv.z += s1.x + gv.z; xv.w += s1.y + gv.w;
            *(float4*)(X + off) = xv;
        }
        return;
    }

    #pragma unroll
    for (int mt = 0; mt < 4; mt++) {
        int row = bm + wm + mt * 16 + g;
        #pragma unroll
        for (int nt = 0; nt < 4; nt++) {
            int col = bn + wn + nt * 8 + tig * 2;
            float b0 = bias[col], b1 = bias[col + 1];
            float v00 = acc[mt][nt][0] + b0;
            float v01 = acc[mt][nt][1] + b1;
            float v10 = acc[mt][nt][2] + b0;
            float v11 = acc[mt][nt][3] + b1;
            if (EPI == 1) {
                v00 = 0.5f * v00 * (1.0f + erff(v00 * 0.70710678118654752f));
                v01 = 0.5f * v01 * (1.0f + erff(v01 * 0.70710678118654752f));
                v10 = 0.5f * v10 * (1.0f + erff(v10 * 0.70710678118654752f));
                v11 = 0.5f * v11 * (1.0f + erff(v11 * 0.70710678118654752f));
                __half2* C = (__half2*)Cv;
                C[((long)row * N + col) >> 1]       = __floats2half2_rn(v00, v01);
                C[((long)(row + 8) * N + col) >> 1] = __floats2half2_rn(v10, v11);
            } else if (EPI == 4) {
                __half2* C = (__half2*)Cv;
                C[((long)row * N + col) >> 1]       = __floats2half2_rn(v00, v01);
                C[((long)(row + 8) * N + col) >> 1] = __floats2half2_rn(v10, v11);
            } else {  // EPI == 2
                const float* R = (const float*)resv;
                const float* r0 = R + (long)row * N + col;
                const float* r1 = R + (long)(row + 8) * N + col;
                v00 += r0[0]; v01 += r0[1];
                v10 += r1[0]; v11 += r1[1];
                float* C = (float*)Cv;
                float2 p0 = {v00, v01}, p1 = {v10, v11};
                *(float2*)(C + (long)row * N + col)       = p0;
                *(float2*)(C + (long)(row + 8) * N + col) = p1;
            }
        }
    }
}

// ---------------- host launcher ----------------
extern "C" void kernel_launch(void* const* d_in, const int* in_sizes, int n_in,
                              void* d_out, int out_size) {
    const float* x      = (const float*)d_in[0];
    const float* g1     = (const float*)d_in[1];
    const float* b1     = (const float*)d_in[2];
    const float* qk_w   = (const float*)d_in[3];
    const float* qk_b   = (const float*)d_in[4];
    const float* v_w    = (const float*)d_in[5];
    const float* v_b    = (const float*)d_in[6];
    const float* lepe_w = (const float*)d_in[7];
    const float* lepe_b = (const float*)d_in[8];
    const float* g2     = (const float*)d_in[9];
    const float* b2     = (const float*)d_in[10];
    const float* spn_g  = (const float*)d_in[11];
    const float* spn_b  = (const float*)d_in[12];
    const float* sp_cw  = (const float*)d_in[13];
    const float* sp_cb  = (const float*)d_in[14];
    const float* g3     = (const float*)d_in[15];
    const float* b3     = (const float*)d_in[16];
    const float* w1     = (const float*)d_in[17];
    const float* bb1    = (const float*)d_in[18];
    const float* w2     = (const float*)d_in[19];
    const float* bb2    = (const float*)d_in[20];
    float* out = (float*)d_out;

    float *xbuf, *km, *kv, *kvpart, *bias2;
    __half *lnh, *qkh, *vh, *q2h, *k2h, *spinh, *hb, *ffnh, *qkTh, *vTh, *w1Th, *w2Th, *wtT2h;
    cudaGetSymbolAddress((void**)&xbuf,   g_xbuf);
    cudaGetSymbolAddress((void**)&lnh,    g_lnh);
    cudaGetSymbolAddress((void**)&qkh,    g_qkh);
    cudaGetSymbolAddress((void**)&vh,     g_vh);
    cudaGetSymbolAddress((void**)&q2h,    g_q2h);
    cudaGetSymbolAddress((void**)&k2h,    g_k2h);
    cudaGetSymbolAddress((void**)&km,     g_kmean);
    cudaGetSymbolAddress((void**)&kv,     g_kv);
    cudaGetSymbolAddress((void**)&kvpart, g_kvpart);
    cudaGetSymbolAddress((void**)&spinh,  g_spinh);
    cudaGetSymbolAddress((void**)&hb,     g_hb);
    cudaGetSymbolAddress((void**)&ffnh,   g_ffnh);
    cudaGetSymbolAddress((void**)&qkTh,   g_qkTh);
    cudaGetSymbolAddress((void**)&vTh,    g_vTh);
    cudaGetSymbolAddress((void**)&w1Th,   g_w1Th);
    cudaGetSymbolAddress((void**)&w2Th,   g_w2Th);
    cudaGetSymbolAddress((void**)&wtT2h,  g_wtT2h);
    cudaGetSymbolAddress((void**)&bias2,  g_bias2);

    cudaFuncSetAttribute((const void*)gemm_h<4,0>, cudaFuncAttributeMaxDynamicSharedMemorySize, GSM);
    cudaFuncSetAttribute((const void*)gemm_h<3,1>, cudaFuncAttributeMaxDynamicSharedMemorySize, GSM);
    cudaFuncSetAttribute((const void*)gemm_h<1,0>, cudaFuncAttributeMaxDynamicSharedMemorySize, GSM);
    cudaFuncSetAttribute((const void*)gemm_h<2,0>, cudaFuncAttributeMaxDynamicSharedMemorySize, GSM);

    // launch order arranged so launch #6 (ncu -s 5 -c 1) is the qk GEMM
    ln_h_kernel<<<BLn, 128>>>(x, g1, b1, lnh);                                       // 1
    transpose_h_kernel<<<(512 * 1024 + 255) / 256, 256>>>(qk_w, qkTh, 512, 1024);    // 2
    transpose_h_kernel<<<(512 * 512 + 255) / 256, 256>>>(v_w, vTh, 512, 512);        // 3
    transpose_h_kernel<<<(512 * 2048 + 255) / 256, 256>>>(w1, w1Th, 512, 2048);      // 4
    transpose_h_kernel<<<(2048 * 512 + 255) / 256, 256>>>(w2, w2Th, 2048, 512);      // 5
    gemm_h<4,0><<<dim3(1024 / 128, BLn / 128), 256, GSM>>>(lnh, qkTh, qk_b, nullptr, qkh, BLn, 1024, Cn);  // 6 <- profiled
    wtT2_kernel<<<(1024 * 1536 + 255) / 256, 256>>>(sp_cw, sp_cb, wtT2h, bias2);
    gemm_h<4,0><<<dim3(512 / 128, BLn / 128), 256, GSM>>>(lnh, vTh, v_b, nullptr, vh, BLn, 512, Cn);
    qk_post_kernel<<<dim3(BHn, Ln / 64), 256>>>(qkh, lepe_w, lepe_b, q2h, k2h);
    kmean_kernel<<<BHn, 256>>>(k2h, km);
    kv_kernel<<<dim3(BHn, KVCHUNKS), 256>>>(k2h, vh, kvpart);
    kv_reduce_kernel<<<(BHn * Dn * Dn) / 256, 256>>>(kvpart, kv);
    attn_out_kernel<<<dim3(BHn, Ln / 32), 256>>>(q2h, kv, km, x, xbuf);

    // Block 2: gated conv state path
    ln2ln3_kernel<<<BLn, 128>>>(xbuf, g2, b2, spn_g, spn_b, spinh, hb);
    gemm_h<3,1><<<dim3(1024 / 128, BLn / 128), 256, GSM>>>(hb, wtT2h, bias2, spinh, xbuf, BLn, 1024, 3 * Cn);

    // Block 3: FFN
    ln_h_kernel<<<BLn, 128>>>(xbuf, g3, b3, lnh);
    gemm_h<1,0><<<dim3(FFn / 128, BLn / 128), 256, GSM>>>(lnh, w1Th, bb1, nullptr, ffnh, BLn, FFn, Cn);
    gemm_h<2,0><<<dim3(512 / 128, BLn / 128), 256, GSM>>>(ffnh, w2Th, bb2, xbuf, out, BLn, 512, FFn);
}

// round 9
// speedup vs baseline: 1.3677x; 1.0233x over previous
#include <cuda_runtime.h>
#include <cuda_fp16.h>
#include <math.h>
#include <stdint.h>

#define Bn 8
#define Ln 2048
#define Cn 512
#define Hn 8
#define Dn 64
#define FFn 2048
#define BLn (Bn*Ln)          /* 16384 */
#define BHn (Bn*Hn)          /* 64    */
#define BHLn (BHn*Ln)        /* 131072*/
#define KVCHUNKS 8

// ---------------- scratch (static device globals; no allocation) ----------------
static __device__ __align__(16) float  g_xbuf[BLn*Cn];
static __device__ __align__(16) __half g_lnh[BLn*Cn];
static __device__ __align__(16) __half g_qkvh[(long)BLn*1536];
static __device__ __align__(16) __half g_q2h[BHLn*Dn];
static __device__ __align__(16) __half g_k2h[BHLn*Dn];
static __device__ __align__(16) float  g_kmean[BHn*Dn];
static __device__ __align__(16) float  g_kv[BHn*Dn*Dn];
static __device__ __align__(16) float  g_kvpart[KVCHUNKS*BHn*Dn*Dn];
static __device__ __align__(16) __half g_spinh[BLn*Cn];
static __device__ __align__(16) __half g_hb[BLn*Cn];
static __device__ __align__(16) __half g_ffnh[(long)BLn*FFn];
// weights (half), prepared once per call
static __device__ __align__(16) __half g_qkvTh[1536*512];
static __device__ __align__(16) __half g_w1Th[2048*512];
static __device__ __align__(16) __half g_w2Th[512*2048];
static __device__ __align__(16) __half g_wtT2h[1024*1536];   // interleaved (vv,gg) pairs
static __device__ __align__(16) float  g_bias2[1024];
static __device__ __align__(16) float  g_bias3[1536];

// ---------------- PTX helpers ----------------
__device__ __forceinline__ uint32_t smem_u32(const void* p) {
    uint32_t a;
    asm("{ .reg .u64 t; cvta.to.shared.u64 t, %1; cvt.u32.u64 %0, t; }" : "=r"(a) : "l"(p));
    return a;
}
__device__ __forceinline__ void cpasync16(uint32_t saddr, const void* g) {
    asm volatile("cp.async.cg.shared.global [%0], [%1], 16;" :: "r"(saddr), "l"(g) : "memory");
}
__device__ __forceinline__ void cpasync16z(uint32_t saddr, const void* g, uint32_t sz) {
    asm volatile("cp.async.cg.shared.global [%0], [%1], 16, %2;"
                 :: "r"(saddr), "l"(g), "r"(sz) : "memory");
}
#define CP_COMMIT() asm volatile("cp.async.commit_group;" ::: "memory")
#define CP_WAIT1()  asm volatile("cp.async.wait_group 1;" ::: "memory")

__device__ __forceinline__ void ldsm4(uint32_t* r, uint32_t addr) {
    asm volatile("ldmatrix.sync.aligned.m8n8.x4.shared.b16 {%0,%1,%2,%3}, [%4];"
        : "=r"(r[0]), "=r"(r[1]), "=r"(r[2]), "=r"(r[3]) : "r"(addr));
}
__device__ __forceinline__ void mma_f16(float* c, const uint32_t* a, const uint32_t* b) {
    asm volatile(
        "mma.sync.aligned.m16n8k16.row.col.f32.f16.f16.f32 "
        "{%0,%1,%2,%3}, {%4,%5,%6,%7}, {%8,%9}, {%0,%1,%2,%3};"
        : "+f"(c[0]), "+f"(c[1]), "+f"(c[2]), "+f"(c[3])
        : "r"(a[0]), "r"(a[1]), "r"(a[2]), "r"(a[3]), "r"(b[0]), "r"(b[1]));
}

// ---------------- small helpers ----------------
__device__ __forceinline__ float elu1(float x) { return x > 0.0f ? x + 1.0f : expf(x); }
__device__ __forceinline__ uint32_t swz(uint32_t r) { return (r ^ (r >> 2)) & 3u; }

// ---------------- one-shot weight prep: all transposes + biases ----------------
#define PW_S0 524288L                    /* qk part of qkvT */
#define PW_S1 (PW_S0 + 262144L)          /* v part */
#define PW_S2 (PW_S1 + 1048576L)         /* w1T */
#define PW_S3 (PW_S2 + 1048576L)         /* w2T */
#define PW_S4 (PW_S3 + 1572864L)         /* wtT2 */
#define PW_TOT (PW_S4 + 1536L)           /* bias3 */
__global__ void prep_weights_kernel(const float* __restrict__ qk_w, const float* __restrict__ v_w,
                                    const float* __restrict__ w1, const float* __restrict__ w2,
                                    const float* __restrict__ sp_cw,
                                    const float* __restrict__ qk_b, const float* __restrict__ v_b,
                                    const float* __restrict__ sp_cb,
                                    __half* __restrict__ qkvT, __half* __restrict__ w1T,
                                    __half* __restrict__ w2T, __half* __restrict__ wtT2,
                                    float* __restrict__ bias2, float* __restrict__ bias3) {
    long idx = (long)blockIdx.x * blockDim.x + threadIdx.x;
    if (idx < PW_S0) {
        int k = (int)(idx & 511), n = (int)(idx >> 9);
        qkvT[idx] = __float2half_rn(qk_w[(long)k * 1024 + n]);
    } else if (idx < PW_S1) {
        long i = idx - PW_S0;
        int k = (int)(i & 511), n = (int)(i >> 9);
        qkvT[idx] = __float2half_rn(v_w[(long)k * 512 + n]);   // dst row 1024+n
    } else if (idx < PW_S2) {
        long i = idx - PW_S1;
        int k = (int)(i & 511), n = (int)(i >> 9);
        w1T[i] = __float2half_rn(w1[(long)k * 2048 + n]);
    } else if (idx < PW_S3) {
        long i = idx - PW_S2;
        int k = (int)(i & 2047), n = (int)(i >> 11);
        w2T[i] = __float2half_rn(w2[(long)k * 512 + n]);
    } else if (idx < PW_S4) {
        long i = idx - PW_S3;
        int kk = (int)(i % 1536), n2 = (int)(i / 1536);
        int co = (n2 & 1) * 512 + (n2 >> 1);
        int k  = kk >> 9, ci = kk & 511;
        wtT2[i] = __float2half_rn(sp_cw[co * 1536 + ci * 3 + k]);
        if (kk == 0) bias2[n2] = sp_cb[co];
    } else if (idx < PW_TOT) {
        int j = (int)(idx - PW_S4);
        bias3[j] = (j < 1024) ? qk_b[j] : v_b[j - 1024];
    }
}

// ---------------- LayerNorm (half out) ----------------
__global__ void ln_h_kernel(const float* __restrict__ in, const float* __restrict__ gam,
                            const float* __restrict__ bet, __half* __restrict__ out) {
    int row = blockIdx.x;
    int t = threadIdx.x;
    const float4 v = ((const float4*)(in + (long)row * Cn))[t];
    float s  = v.x + v.y + v.z + v.w;
    float sq = v.x*v.x + v.y*v.y + v.z*v.z + v.w*v.w;
    #pragma unroll
    for (int o = 16; o; o >>= 1) {
        s  += __shfl_xor_sync(0xFFFFFFFFu, s,  o);
        sq += __shfl_xor_sync(0xFFFFFFFFu, sq, o);
    }
    __shared__ float ss[4], ssq[4];
    if ((t & 31) == 0) { ss[t >> 5] = s; ssq[t >> 5] = sq; }
    __syncthreads();
    s  = ss[0] + ss[1] + ss[2] + ss[3];
    sq = ssq[0] + ssq[1] + ssq[2] + ssq[3];
    float mu   = s * (1.0f / Cn);
    float var  = sq * (1.0f / Cn) - mu * mu;
    float rstd = rsqrtf(var + 1e-5f);
    float4 g4 = ((const float4*)gam)[t];
    float4 b4 = ((const float4*)bet)[t];
    __half2* o = (__half2*)(out + (long)row * Cn);
    o[t * 2]     = __floats2half2_rn((v.x - mu) * rstd * g4.x + b4.x,
                                     (v.y - mu) * rstd * g4.y + b4.y);
    o[t * 2 + 1] = __floats2half2_rn((v.z - mu) * rstd * g4.z + b4.z,
                                     (v.w - mu) * rstd * g4.w + b4.w);
}

// ---------------- fused LN2 + LN3 ----------------
__global__ void ln2ln3_kernel(const float* __restrict__ in,
                              const float* __restrict__ g2, const float* __restrict__ b2,
                              const float* __restrict__ g3, const float* __restrict__ b3,
                              __half* __restrict__ spin, __half* __restrict__ hb) {
    int row = blockIdx.x;
    int t = threadIdx.x;
    __shared__ float ss[4], ssq[4];
    const float4 v = ((const float4*)(in + (long)row * Cn))[t];
    float s  = v.x + v.y + v.z + v.w;
    float sq = v.x*v.x + v.y*v.y + v.z*v.z + v.w*v.w;
    #pragma unroll
    for (int o = 16; o; o >>= 1) {
        s  += __shfl_xor_sync(0xFFFFFFFFu, s,  o);
        sq += __shfl_xor_sync(0xFFFFFFFFu, sq, o);
    }
    if ((t & 31) == 0) { ss[t >> 5] = s; ssq[t >> 5] = sq; }
    __syncthreads();
    s  = ss[0] + ss[1] + ss[2] + ss[3];
    sq = ssq[0] + ssq[1] + ssq[2] + ssq[3];
    float mu   = s * (1.0f / Cn);
    float var  = sq * (1.0f / Cn) - mu * mu;
    float rstd = rsqrtf(var + 1e-5f);
    float4 gg = ((const float4*)g2)[t];
    float4 bb = ((const float4*)b2)[t];
    float4 o1;
    o1.x = (v.x - mu) * rstd * gg.x + bb.x;
    o1.y = (v.y - mu) * rstd * gg.y + bb.y;
    o1.z = (v.z - mu) * rstd * gg.z + bb.z;
    o1.w = (v.w - mu) * rstd * gg.w + bb.w;
    __half2* sp = (__half2*)(spin + (long)row * Cn);
    sp[t * 2]     = __floats2half2_rn(o1.x, o1.y);
    sp[t * 2 + 1] = __floats2half2_rn(o1.z, o1.w);
    float s2  = o1.x + o1.y + o1.z + o1.w;
    float sq2 = o1.x*o1.x + o1.y*o1.y + o1.z*o1.z + o1.w*o1.w;
    #pragma unroll
    for (int o = 16; o; o >>= 1) {
        s2  += __shfl_xor_sync(0xFFFFFFFFu, s2,  o);
        sq2 += __shfl_xor_sync(0xFFFFFFFFu, sq2, o);
    }
    __syncthreads();
    if ((t & 31) == 0) { ss[t >> 5] = s2; ssq[t >> 5] = sq2; }
    __syncthreads();
    s2  = ss[0] + ss[1] + ss[2] + ss[3];
    sq2 = ssq[0] + ssq[1] + ssq[2] + ssq[3];
    float mu2   = s2 * (1.0f / Cn);
    float var2  = sq2 * (1.0f / Cn) - mu2 * mu2;
    float rstd2 = rsqrtf(var2 + 1e-5f);
    float4 g4 = ((const float4*)g3)[t];
    float4 b4 = ((const float4*)b3)[t];
    __half2* o = (__half2*)(hb + (long)row * Cn);
    o[t * 2]     = __floats2half2_rn((o1.x - mu2) * rstd2 * g4.x + b4.x,
                                     (o1.y - mu2) * rstd2 * g4.y + b4.y);
    o[t * 2 + 1] = __floats2half2_rn((o1.z - mu2) * rstd2 * g4.z + b4.z,
                                     (o1.w - mu2) * rstd2 * g4.w + b4.w);
}

// ---------------- qk post: elu+1 then LePE, smem-tiled (qkv row stride 1536) ----------------
__global__ void qk_post_kernel(const __half* __restrict__ qkv,
                               const float* __restrict__ lw, const float* __restrict__ lb,
                               __half* __restrict__ q2, __half* __restrict__ k2) {
    int bh = blockIdx.x;
    int lt = blockIdx.y;
    int l0 = lt * 64;
    int b = bh >> 3, h = bh & 7;
    const __half* base = qkv + (long)b * Ln * 1536 + h * 64;
    __shared__ __half sId[2][64][64];
    __shared__ __half sTapT[2][64][66];
    __shared__ __half sLo[2][64], sHi[2][64];
    int t = threadIdx.x;
    #pragma unroll
    for (int sel = 0; sel < 2; sel++) {
        #pragma unroll
        for (int i = 0; i < 2; i++) {
            int idx = t + i * 256;
            int r  = idx >> 3;
            int c8 = (idx & 7) * 8;
            *(uint4*)&sId[sel][r][c8] =
                *(const uint4*)&base[(long)(l0 + r) * 1536 + sel * 512 + c8];
            __half tmp[8];
            *(uint4*)tmp = *(const uint4*)&base[(long)(r * 32 + lt) * 1536 + sel * 512 + c8];
            #pragma unroll
            for (int k = 0; k < 8; k++) sTapT[sel][c8 + k][r] = tmp[k];
        }
    }
    if (t < 128) {
        int sel = t >> 6, d = t & 63;
        __half lo = __ushort_as_half((unsigned short)0), hi = lo;
        if (l0 > 0)       lo = base[(long)(d * 32 + lt - 1) * 1536 + sel * 512 + 63];
        if (l0 + 64 < Ln) hi = base[(long)(d * 32 + lt + 1) * 1536 + sel * 512];
        sLo[sel][d] = lo;
        sHi[sel][d] = hi;
    }
    __syncthreads();
    int d2 = (t & 31) * 2, rb = t >> 5;
    bool hasLo = (l0 > 0), hasHi = (l0 + 64 < Ln);
    #pragma unroll
    for (int sel = 0; sel < 2; sel++) {
        __half* dst = sel ? k2 : q2;
        float w0[2], w1[2], w2[2], bi[2];
        #pragma unroll
        for (int dd = 0; dd < 2; dd++) {
            int d = d2 + dd;
            w0[dd] = lw[d*3]; w1[dd] = lw[d*3+1]; w2[dd] = lw[d*3+2]; bi[dd] = lb[d];
        }
        #pragma unroll
        for (int i = 0; i < 8; i++) {
            int r = rb + i * 8;
            float o[2];
            #pragma unroll
            for (int dd = 0; dd < 2; dd++) {
                int d = d2 + dd;
                float acc = elu1(__half2float(sId[sel][r][d])) + bi[dd];
                float c1 = elu1(__half2float(sTapT[sel][r][d]));
                float c0 = (r > 0) ? elu1(__half2float(sTapT[sel][r-1][d]))
                                   : (hasLo ? elu1(__half2float(sLo[sel][d])) : 0.0f);
                float c2 = (r < 63) ? elu1(__half2float(sTapT[sel][r+1][d]))
                                    : (hasHi ? elu1(__half2float(sHi[sel][d])) : 0.0f);
                o[dd] = acc + w0[dd] * c0 + w1[dd] * c1 + w2[dd] * c2;
            }
            *(__half2*)&dst[(long)bh * (Ln * Dn) + (long)(l0 + r) * 64 + d2] =
                __floats2half2_rn(o[0], o[1]);
        }
    }
}

// ---------------- k mean ----------------
__global__ void kmean_kernel(const __half* __restrict__ k2, float* __restrict__ km) {
    int bh = blockIdx.x;
    int t = threadIdx.x;
    int d = t & 63, part = t >> 6;
    float s = 0.0f;
    const __half* base = k2 + (long)bh * Ln * Dn;
    for (int l = part; l < Ln; l += 4) s += __half2float(base[l * 64 + d]);
    __shared__ float sm[4][64];
    sm[part][d] = s;
    __syncthreads();
    if (part == 0)
        km[bh * 64 + d] = (sm[0][d] + sm[1][d] + sm[2][d] + sm[3][d]) * (1.0f / Ln);
}

// ---------------- kv partials (k2 + v-in-qkv, fp32 accumulate) ----------------
__global__ void kv_kernel(const __half* __restrict__ k2, const __half* __restrict__ qkv,
                          float* __restrict__ part) {
    int bh = blockIdx.x, chunk = blockIdx.y;
    int b = bh >> 3, h = bh & 7;
    __shared__ float ks[32][64];
    __shared__ float vs[32][64];
    int t = threadIdx.x;
    int e0 = (t & 15) * 4, d0 = (t >> 4) * 4;
    float acc[4][4] = {};
    int lc = Ln / KVCHUNKS;
    for (int l0 = chunk * lc; l0 < chunk * lc + lc; l0 += 32) {
        #pragma unroll
        for (int i = 0; i < 2; i++) {
            int idx = t + i * 256;
            int r = idx >> 4, c4 = (idx & 15) * 4;
            int l = l0 + r;
            uint2 kr = *(const uint2*)&k2[((long)bh * Ln + l) * 64 + c4];
            uint2 vr = *(const uint2*)&qkv[((long)(b * Ln + l)) * 1536 + 1024 + h * 64 + c4];
            float2 k0 = __half22float2(*(__half2*)&kr.x);
            float2 k1 = __half22float2(*(__half2*)&kr.y);
            float2 v0 = __half22float2(*(__half2*)&vr.x);
            float2 v1 = __half22float2(*(__half2*)&vr.y);
            ks[r][c4] = k0.x; ks[r][c4+1] = k0.y; ks[r][c4+2] = k1.x; ks[r][c4+3] = k1.y;
            vs[r][c4] = v0.x; vs[r][c4+1] = v0.y; vs[r][c4+2] = v1.x; vs[r][c4+3] = v1.y;
        }
        __syncthreads();
        #pragma unroll
        for (int l = 0; l < 32; l++) {
            float4 kr = *(const float4*)&ks[l][d0];
            float4 vr = *(const float4*)&vs[l][e0];
            float k_[4] = {kr.x, kr.y, kr.z, kr.w};
            float v_[4] = {vr.x, vr.y, vr.z, vr.w};
            #pragma unroll
            for (int i = 0; i < 4; i++)
                #pragma unroll
                for (int j = 0; j < 4; j++)
                    acc[i][j] += k_[i] * v_[j];
        }
        __syncthreads();
    }
    float* dst = part + ((long)chunk * BHn + bh) * (Dn * Dn);
    #pragma unroll
    for (int i = 0; i < 4; i++)
        #pragma unroll
        for (int j = 0; j < 4; j++)
            dst[(d0 + i) * 64 + e0 + j] = acc[i][j];
}

__global__ void kv_reduce_kernel(const float* __restrict__ part, float* __restrict__ kv) {
    int i = blockIdx.x * blockDim.x + threadIdx.x;
    float s = 0.0f;
    #pragma unroll
    for (int c = 0; c < KVCHUNKS; c++) s += part[(long)c * (BHn * Dn * Dn) + i];
    kv[i] = s * (1.0f / Ln);
}

// ---------------- attention output: xbuf = x + (q2@kv) * z, z fused; 128 rows/block ----------------
__global__ void attn_out_kernel(const __half* __restrict__ q2, const float* __restrict__ kv,
                                const float* __restrict__ km, const float* __restrict__ x,
                                float* __restrict__ xbuf) {
    int bh = blockIdx.x, b = bh >> 3, h = bh & 7;
    int lbase = blockIdx.y * 128;
    __shared__ float kvs[64][64];
    __shared__ float qs[16][64];
    __shared__ float skm[64];
    int t = threadIdx.x;
    #pragma unroll
    for (int i = 0; i < 4; i++) {
        int idx = t + i * 256;
        ((float4*)kvs)[idx] = ((const float4*)(kv + (long)bh * 4096))[idx];
    }
    if (t < 64) skm[t] = km[bh * 64 + t];
    int g = t >> 4;
    int e0 = (t & 15) * 4;
    for (int it = 0; it < 8; it++) {
        __syncthreads();
        int rbase = lbase + it * 16;
        #pragma unroll
        for (int i = 0; i < 4; i++) {
            int idx = t + i * 256;
            int r = idx >> 6, c = idx & 63;
            qs[r][c] = __half2float(q2[((long)bh * Ln + rbase + r) * 64 + c]);
        }
        __syncthreads();
        int l = rbase + g;
        float part = qs[g][e0] * skm[e0] + qs[g][e0+1] * skm[e0+1]
                   + qs[g][e0+2] * skm[e0+2] + qs[g][e0+3] * skm[e0+3];
        #pragma unroll
        for (int o = 8; o; o >>= 1) part += __shfl_xor_sync(0xFFFFFFFFu, part, o);
        float zz = 1.0f / (part + 1e-6f);
        float4 acc = {0.f, 0.f, 0.f, 0.f};
        #pragma unroll
        for (int d = 0; d < 64; d++) {
            float qd = qs[g][d];
            float4 kvv = *(const float4*)&kvs[d][e0];
            acc.x += qd * kvv.x; acc.y += qd * kvv.y;
            acc.z += qd * kvv.z; acc.w += qd * kvv.w;
        }
        long off = ((long)(b * Ln + l)) * Cn + h * 64 + e0;
        float4 cur = *(const float4*)&x[off];
        cur.x += acc.x * zz; cur.y += acc.y * zz;
        cur.z += acc.z * zz; cur.w += acc.w * zz;
        *(float4*)&xbuf[off] = cur;
    }
}

// ================= fp16 mma.sync GEMM =================
// C[M,N] = A[M,K] @ Bt[N,K]^T.  CTA 128x128, K-chunk 32, 3-stage cp.async, 8 warps.
// CONVA=1: A is hb [BL,512] viewed as im2col [BL,1536] with zero-padded taps.
// EPI: 1 = bias + exact GELU (half out); 2 = bias + residual f32 (float out);
//      3 = gated conv (smem-staged coalesced): xbuf += spin(half) + vv*sigmoid(gg);
//      4 = bias (half out).
#define GSM (3 * 16384)

template<int EPI, int CONVA>
__global__ void __launch_bounds__(256, 2)
gemm_h(const __half* __restrict__ A, const __half* __restrict__ Bt,
       const float* __restrict__ bias, const void* __restrict__ resv,
       void* __restrict__ Cv, int M, int N, int K) {
    extern __shared__ char smraw[];
    uint32_t sb = smem_u32(smraw);
    int t = threadIdx.x, wid = t >> 5, lane = t & 31;
    int g = lane >> 2, tig = lane & 3;
    int bm = blockIdx.y * 128, bn = blockIdx.x * 128;
    int wm = (wid >> 2) * 64, wn = (wid & 3) * 32;

    const __half* aG[2]; const __half* bG[2]; uint32_t offA[2], offB[2];
    int rs[2], cs[2];
    #pragma unroll
    for (int i = 0; i < 2; i++) {
        int idx = t + i * 256;
        int r = idx >> 2;
        int c = idx & 3;
        rs[i] = r; cs[i] = c;
        uint32_t off = (uint32_t)r * 64 + ((c ^ swz(r)) << 4);
        offA[i] = off;
        offB[i] = off + 8192;
        if (!CONVA) aG[i] = A + (long)(bm + r) * K + c * 8;
        bG[i] = Bt + (long)(bn + r) * K + c * 8;
    }

    uint32_t aRow[4], aSw[4];
    #pragma unroll
    for (int mt = 0; mt < 4; mt++) {
        uint32_t m = wm + mt * 16 + (lane & 15);
        aRow[mt] = m * 64;
        aSw[mt] = swz(m);
    }
    uint32_t cHiA = lane >> 4;
    uint32_t bRow[2], bSw[2];
    #pragma unroll
    for (int np = 0; np < 2; np++) {
        uint32_t n = wn + np * 16 + ((lane >> 4) << 3) + (lane & 7);
        bRow[np] = n * 64 + 8192;
        bSw[np] = swz(n);
    }
    uint32_t cHiB = (lane >> 3) & 1;

    int nk = K >> 5;

    auto loadA_conv = [&](uint32_t stb, int kt) {
        int tap = kt >> 4;
        int kin = (kt & 15) * 32;
        #pragma unroll
        for (int i = 0; i < 2; i++) {
            long row = bm + rs[i];
            int l = (int)(row & (Ln - 1));
            bool valid = (unsigned)(l + tap - 1) < (unsigned)Ln;
            const __half* src = valid ? (A + (row + tap - 1) * Cn + kin + cs[i] * 8) : A;
            cpasync16z(stb + offA[i], src, valid ? 16u : 0u);
        }
    };

    #pragma unroll
    for (int s = 0; s < 2; s++) {
        uint32_t stb = sb + s * 16384;
        if (CONVA) loadA_conv(stb, s);
        else {
            #pragma unroll
            for (int i = 0; i < 2; i++) cpasync16(stb + offA[i], aG[i] + s * 32);
        }
        #pragma unroll
        for (int i = 0; i < 2; i++) cpasync16(stb + offB[i], bG[i] + s * 32);
        CP_COMMIT();
    }
    CP_WAIT1();
    __syncthreads();

    float acc[4][4][4] = {};

    for (int kt = 0; kt < nk; kt++) {
        if (kt + 2 < nk) {
            uint32_t stb = sb + ((kt + 2) % 3) * 16384;
            if (CONVA) loadA_conv(stb, kt + 2);
            else {
                #pragma unroll
                for (int i = 0; i < 2; i++) cpasync16(stb + offA[i], aG[i] + (long)(kt + 2) * 32);
            }
            #pragma unroll
            for (int i = 0; i < 2; i++) cpasync16(stb + offB[i], bG[i] + (long)(kt + 2) * 32);
        }
        CP_COMMIT();

        uint32_t stb = sb + (kt % 3) * 16384;
        #pragma unroll
        for (int kb = 0; kb < 2; kb++) {
            uint32_t a[4][4], b[4][2];
            #pragma unroll
            for (int mt = 0; mt < 4; mt++) {
                uint32_t addr = stb + aRow[mt] + ((((uint32_t)(2 * kb) | cHiA) ^ aSw[mt]) << 4);
                ldsm4(a[mt], addr);
            }
            #pragma unroll
            for (int np = 0; np < 2; np++) {
                uint32_t bb[4];
                uint32_t addr = stb + bRow[np] + ((((uint32_t)(2 * kb) | cHiB) ^ bSw[np]) << 4);
                ldsm4(bb, addr);
                b[2*np][0] = bb[0]; b[2*np][1] = bb[1];
                b[2*np+1][0] = bb[2]; b[2*np+1][1] = bb[3];
            }
            #pragma unroll
            for (int mt = 0; mt < 4; mt++)
                #pragma unroll
                for (int nt = 0; nt < 4; nt++)
                    mma_f16(acc[mt][nt], a[mt], b[nt]);
        }

        CP_WAIT1();
        __syncthreads();
    }

    // ---- epilogue ----
    if (EPI == 3) {
        float* sg = (float*)smraw;
        #pragma unroll
        for (int mt = 0; mt < 4; mt++) {
            int r0 = wm + mt * 16 + g;
            #pragma unroll
            for (int nt = 0; nt < 4; nt++) {
                int col = wn + nt * 8 + tig * 2;
                float b0 = bias[bn + col], b1 = bias[bn + col + 1];
                float vv0 = acc[mt][nt][0] + b0, gg0 = acc[mt][nt][1] + b1;
                float vv1 = acc[mt][nt][2] + b0, gg1 = acc[mt][nt][3] + b1;
                int cp = col >> 1;
                sg[r0 * 68 + cp]       = vv0 / (1.0f + expf(-gg0));
                sg[(r0 + 8) * 68 + cp] = vv1 / (1.0f + expf(-gg1));
            }
        }
        __syncthreads();
        int cpb = bn >> 1;
        float* X = (float*)Cv;
        const __half* R = (const __half*)resv;
        #pragma unroll
        for (int i = 0; i < 8; i++) {
            int j = t + i * 256;
            int r = j >> 4, c4 = j & 15;
            long off = (long)(bm + r) * Cn + cpb + c4 * 4;
            float4 xv = *(float4*)(X + off);
            uint2 spraw = *(const uint2*)(R + off);
            float2 s0 = __half22float2(*(__half2*)&spraw.x);
            float2 s1 = __half22float2(*(__half2*)&spraw.y);
            float4 gv = *(float4*)&sg[r * 68 + c4 * 4];
            xv.x += s0.x + gv.x; xv.y += s0.y + gv.y;
            xv.z += s1.x + gv.z; xv.w += s1.y + gv.w;
            *(float4*)(X + off) = xv;
        }
        return;
    }

    #pragma unroll
    for (int mt = 0; mt < 4; mt++) {
        int row = bm + wm + mt * 16 + g;
        #pragma unroll
        for (int nt = 0; nt < 4; nt++) {
            int col = bn + wn + nt * 8 + tig * 2;
            float b0 = bias[col], b1 = bias[col + 1];
            float v00 = acc[mt][nt][0] + b0;
            float v01 = acc[mt][nt][1] + b1;
            float v10 = acc[mt][nt][2] + b0;
            float v11 = acc[mt][nt][3] + b1;
            if (EPI == 1) {
                v00 = 0.5f * v00 * (1.0f + erff(v00 * 0.70710678118654752f));
                v01 = 0.5f * v01 * (1.0f + erff(v01 * 0.70710678118654752f));
                v10 = 0.5f * v10 * (1.0f + erff(v10 * 0.70710678118654752f));
                v11 = 0.5f * v11 * (1.0f + erff(v11 * 0.70710678118654752f));
                __half2* C = (__half2*)Cv;
                C[((long)row * N + col) >> 1]       = __floats2half2_rn(v00, v01);
                C[((long)(row + 8) * N + col) >> 1] = __floats2half2_rn(v10, v11);
            } else if (EPI == 4) {
                __half2* C = (__half2*)Cv;
                C[((long)row * N + col) >> 1]       = __floats2half2_rn(v00, v01);
                C[((long)(row + 8) * N + col) >> 1] = __floats2half2_rn(v10, v11);
            } else {  // EPI == 2
                const float* R = (const float*)resv;
                const float* r0 = R + (long)row * N + col;
                const float* r1 = R + (long)(row + 8) * N + col;
                v00 += r0[0]; v01 += r0[1];
                v10 += r1[0]; v11 += r1[1];
                float* C = (float*)Cv;
                float2 p0 = {v00, v01}, p1 = {v10, v11};
                *(float2*)(C + (long)row * N + col)       = p0;
                *(float2*)(C + (long)(row + 8) * N + col) = p1;
            }
        }
    }
}

// ---------------- host launcher ----------------
extern "C" void kernel_launch(void* const* d_in, const int* in_sizes, int n_in,
                              void* d_out, int out_size) {
    const float* x      = (const float*)d_in[0];
    const float* g1     = (const float*)d_in[1];
    const float* b1     = (const float*)d_in[2];
    const float* qk_w   = (const float*)d_in[3];
    const float* qk_b   = (const float*)d_in[4];
    const float* v_w    = (const float*)d_in[5];
    const float* v_b    = (const float*)d_in[6];
    const float* lepe_w = (const float*)d_in[7];
    const float* lepe_b = (const float*)d_in[8];
    const float* g2     = (const float*)d_in[9];
    const float* b2     = (const float*)d_in[10];
    const float* spn_g  = (const float*)d_in[11];
    const float* spn_b  = (const float*)d_in[12];
    const float* sp_cw  = (const float*)d_in[13];
    const float* sp_cb  = (const float*)d_in[14];
    const float* g3     = (const float*)d_in[15];
    const float* b3     = (const float*)d_in[16];
    const float* w1     = (const float*)d_in[17];
    const float* bb1    = (const float*)d_in[18];
    const float* w2     = (const float*)d_in[19];
    const float* bb2    = (const float*)d_in[20];
    float* out = (float*)d_out;

    float *xbuf, *km, *kv, *kvpart, *bias2, *bias3;
    __half *lnh, *qkvh, *q2h, *k2h, *spinh, *hb, *ffnh, *qkvTh, *w1Th, *w2Th, *wtT2h;
    cudaGetSymbolAddress((void**)&xbuf,   g_xbuf);
    cudaGetSymbolAddress((void**)&lnh,    g_lnh);
    cudaGetSymbolAddress((void**)&qkvh,   g_qkvh);
    cudaGetSymbolAddress((void**)&q2h,    g_q2h);
    cudaGetSymbolAddress((void**)&k2h,    g_k2h);
    cudaGetSymbolAddress((void**)&km,     g_kmean);
    cudaGetSymbolAddress((void**)&kv,     g_kv);
    cudaGetSymbolAddress((void**)&kvpart, g_kvpart);
    cudaGetSymbolAddress((void**)&spinh,  g_spinh);
    cudaGetSymbolAddress((void**)&hb,     g_hb);
    cudaGetSymbolAddress((void**)&ffnh,   g_ffnh);
    cudaGetSymbolAddress((void**)&qkvTh,  g_qkvTh);
    cudaGetSymbolAddress((void**)&w1Th,   g_w1Th);
    cudaGetSymbolAddress((void**)&w2Th,   g_w2Th);
    cudaGetSymbolAddress((void**)&wtT2h,  g_wtT2h);
    cudaGetSymbolAddress((void**)&bias2,  g_bias2);
    cudaGetSymbolAddress((void**)&bias3,  g_bias3);

    cudaFuncSetAttribute((const void*)gemm_h<4,0>, cudaFuncAttributeMaxDynamicSharedMemorySize, GSM);
    cudaFuncSetAttribute((const void*)gemm_h<3,1>, cudaFuncAttributeMaxDynamicSharedMemorySize, GSM);
    cudaFuncSetAttribute((const void*)gemm_h<1,0>, cudaFuncAttributeMaxDynamicSharedMemorySize, GSM);
    cudaFuncSetAttribute((const void*)gemm_h<2,0>, cudaFuncAttributeMaxDynamicSharedMemorySize, GSM);

    // one-shot weight prep (single launch)
    prep_weights_kernel<<<(int)((PW_TOT + 255) / 256), 256>>>(
        qk_w, v_w, w1, w2, sp_cw, qk_b, v_b, sp_cb,
        qkvTh, w1Th, w2Th, wtT2h, bias2, bias3);

    // Block 1: xbuf = x + attn(LN1(x))
    ln_h_kernel<<<BLn, 128>>>(x, g1, b1, lnh);
    gemm_h<4,0><<<dim3(1536 / 128, BLn / 128), 256, GSM>>>(lnh, qkvTh, bias3, nullptr, qkvh, BLn, 1536, Cn);
    qk_post_kernel<<<dim3(BHn, Ln / 64), 256>>>(qkvh, lepe_w, lepe_b, q2h, k2h);
    kmean_kernel<<<BHn, 256>>>(k2h, km);
    kv_kernel<<<dim3(BHn, KVCHUNKS), 256>>>(k2h, qkvh, kvpart);
    kv_reduce_kernel<<<(BHn * Dn * Dn) / 256, 256>>>(kvpart, kv);
    attn_out_kernel<<<dim3(BHn, Ln / 128), 256>>>(q2h, kv, km, x, xbuf);

    // Block 2: gated conv state path
    ln2ln3_kernel<<<BLn, 128>>>(xbuf, g2, b2, spn_g, spn_b, spinh, hb);
    gemm_h<3,1><<<dim3(1024 / 128, BLn / 128), 256, GSM>>>(hb, wtT2h, bias2, spinh, xbuf, BLn, 1024, 3 * Cn);

    // Block 3: FFN
    ln_h_kernel<<<BLn, 128>>>(xbuf, g3, b3, lnh);
    gemm_h<1,0><<<dim3(FFn / 128, BLn / 128), 256, GSM>>>(lnh, w1Th, bb1, nullptr, ffnh, BLn, FFn, Cn);
    gemm_h<2,0><<<dim3(512 / 128, BLn / 128), 256, GSM>>>(ffnh, w2Th, bb2, xbuf, out, BLn, 512, FFn);
}

// round 10
// speedup vs baseline: 1.4525x; 1.0620x over previous
#include <cuda_runtime.h>
#include <cuda_fp16.h>
#include <math.h>
#include <stdint.h>

#define Bn 8
#define Ln 2048
#define Cn 512
#define Hn 8
#define Dn 64
#define FFn 2048
#define BLn (Bn*Ln)          /* 16384 */
#define BHn (Bn*Hn)          /* 64    */
#define BHLn (BHn*Ln)        /* 131072*/
#define KVCHUNKS 8

// ---------------- scratch (static device globals; no allocation) ----------------
static __device__ __align__(16) float  g_xbuf[BLn*Cn];
static __device__ __align__(16) __half g_lnh[BLn*Cn];
static __device__ __align__(16) __half g_qkvh[(long)BLn*1536];
static __device__ __align__(16) __half g_q2h[BHLn*Dn];
static __device__ __align__(16) __half g_k2h[BHLn*Dn];
static __device__ __align__(16) float  g_kmean[BHn*Dn];
static __device__ __align__(16) float  g_kv[BHn*Dn*Dn];
static __device__ __align__(16) float  g_kvpart[KVCHUNKS*BHn*Dn*Dn];
static __device__ __align__(16) float  g_kmpart[KVCHUNKS*BHn*Dn];
static __device__ __align__(16) __half g_spinh[BLn*Cn];
static __device__ __align__(16) __half g_hb[BLn*Cn];
static __device__ __align__(16) __half g_ffnh[(long)BLn*FFn];
// weights (half), prepared once per call
static __device__ __align__(16) __half g_qkvTh[1536*512];
static __device__ __align__(16) __half g_w1Th[2048*512];
static __device__ __align__(16) __half g_w2Th[512*2048];
static __device__ __align__(16) __half g_wtT2h[1024*1536];   // interleaved (vv,gg) pairs
static __device__ __align__(16) float  g_bias2[1024];
static __device__ __align__(16) float  g_bias3[1536];

// ---------------- PTX helpers ----------------
__device__ __forceinline__ uint32_t smem_u32(const void* p) {
    uint32_t a;
    asm("{ .reg .u64 t; cvta.to.shared.u64 t, %1; cvt.u32.u64 %0, t; }" : "=r"(a) : "l"(p));
    return a;
}
__device__ __forceinline__ void cpasync16(uint32_t saddr, const void* g) {
    asm volatile("cp.async.cg.shared.global [%0], [%1], 16;" :: "r"(saddr), "l"(g) : "memory");
}
__device__ __forceinline__ void cpasync16z(uint32_t saddr, const void* g, uint32_t sz) {
    asm volatile("cp.async.cg.shared.global [%0], [%1], 16, %2;"
                 :: "r"(saddr), "l"(g), "r"(sz) : "memory");
}
#define CP_COMMIT() asm volatile("cp.async.commit_group;" ::: "memory")
#define CP_WAIT1()  asm volatile("cp.async.wait_group 1;" ::: "memory")

__device__ __forceinline__ void ldsm4(uint32_t* r, uint32_t addr) {
    asm volatile("ldmatrix.sync.aligned.m8n8.x4.shared.b16 {%0,%1,%2,%3}, [%4];"
        : "=r"(r[0]), "=r"(r[1]), "=r"(r[2]), "=r"(r[3]) : "r"(addr));
}
__device__ __forceinline__ void mma_f16(float* c, const uint32_t* a, const uint32_t* b) {
    asm volatile(
        "mma.sync.aligned.m16n8k16.row.col.f32.f16.f16.f32 "
        "{%0,%1,%2,%3}, {%4,%5,%6,%7}, {%8,%9}, {%0,%1,%2,%3};"
        : "+f"(c[0]), "+f"(c[1]), "+f"(c[2]), "+f"(c[3])
        : "r"(a[0]), "r"(a[1]), "r"(a[2]), "r"(a[3]), "r"(b[0]), "r"(b[1]));
}

// ---------------- small helpers ----------------
__device__ __forceinline__ float elu1f(float x) { return x > 0.0f ? x + 1.0f : __expf(x); }
__device__ __forceinline__ uint32_t swz(uint32_t r) { return (r ^ (r >> 2)) & 3u; }

// ---------------- one-shot weight prep ----------------
#define PW_S0 524288L
#define PW_S1 (PW_S0 + 262144L)
#define PW_S2 (PW_S1 + 1048576L)
#define PW_S3 (PW_S2 + 1048576L)
#define PW_S4 (PW_S3 + 1572864L)
#define PW_TOT (PW_S4 + 1536L)
__global__ void prep_weights_kernel(const float* __restrict__ qk_w, const float* __restrict__ v_w,
                                    const float* __restrict__ w1, const float* __restrict__ w2,
                                    const float* __restrict__ sp_cw,
                                    const float* __restrict__ qk_b, const float* __restrict__ v_b,
                                    const float* __restrict__ sp_cb,
                                    __half* __restrict__ qkvT, __half* __restrict__ w1T,
                                    __half* __restrict__ w2T, __half* __restrict__ wtT2,
                                    float* __restrict__ bias2, float* __restrict__ bias3) {
    long idx = (long)blockIdx.x * blockDim.x + threadIdx.x;
    if (idx < PW_S0) {
        int k = (int)(idx & 511), n = (int)(idx >> 9);
        qkvT[idx] = __float2half_rn(qk_w[(long)k * 1024 + n]);
    } else if (idx < PW_S1) {
        long i = idx - PW_S0;
        int k = (int)(i & 511), n = (int)(i >> 9);
        qkvT[idx] = __float2half_rn(v_w[(long)k * 512 + n]);
    } else if (idx < PW_S2) {
        long i = idx - PW_S1;
        int k = (int)(i & 511), n = (int)(i >> 9);
        w1T[i] = __float2half_rn(w1[(long)k * 2048 + n]);
    } else if (idx < PW_S3) {
        long i = idx - PW_S2;
        int k = (int)(i & 2047), n = (int)(i >> 11);
        w2T[i] = __float2half_rn(w2[(long)k * 512 + n]);
    } else if (idx < PW_S4) {
        long i = idx - PW_S3;
        int kk = (int)(i % 1536), n2 = (int)(i / 1536);
        int co = (n2 & 1) * 512 + (n2 >> 1);
        int k  = kk >> 9, ci = kk & 511;
        wtT2[i] = __float2half_rn(sp_cw[co * 1536 + ci * 3 + k]);
        if (kk == 0) bias2[n2] = sp_cb[co];
    } else if (idx < PW_TOT) {
        int j = (int)(idx - PW_S4);
        bias3[j] = (j < 1024) ? qk_b[j] : v_b[j - 1024];
    }
}

// ---------------- LayerNorm (half out) ----------------
__global__ void ln_h_kernel(const float* __restrict__ in, const float* __restrict__ gam,
                            const float* __restrict__ bet, __half* __restrict__ out) {
    int row = blockIdx.x;
    int t = threadIdx.x;
    const float4 v = ((const float4*)(in + (long)row * Cn))[t];
    float s  = v.x + v.y + v.z + v.w;
    float sq = v.x*v.x + v.y*v.y + v.z*v.z + v.w*v.w;
    #pragma unroll
    for (int o = 16; o; o >>= 1) {
        s  += __shfl_xor_sync(0xFFFFFFFFu, s,  o);
        sq += __shfl_xor_sync(0xFFFFFFFFu, sq, o);
    }
    __shared__ float ss[4], ssq[4];
    if ((t & 31) == 0) { ss[t >> 5] = s; ssq[t >> 5] = sq; }
    __syncthreads();
    s  = ss[0] + ss[1] + ss[2] + ss[3];
    sq = ssq[0] + ssq[1] + ssq[2] + ssq[3];
    float mu   = s * (1.0f / Cn);
    float var  = sq * (1.0f / Cn) - mu * mu;
    float rstd = rsqrtf(var + 1e-5f);
    float4 g4 = ((const float4*)gam)[t];
    float4 b4 = ((const float4*)bet)[t];
    __half2* o = (__half2*)(out + (long)row * Cn);
    o[t * 2]     = __floats2half2_rn((v.x - mu) * rstd * g4.x + b4.x,
                                     (v.y - mu) * rstd * g4.y + b4.y);
    o[t * 2 + 1] = __floats2half2_rn((v.z - mu) * rstd * g4.z + b4.z,
                                     (v.w - mu) * rstd * g4.w + b4.w);
}

// ---------------- fused LN2 + LN3 ----------------
__global__ void ln2ln3_kernel(const float* __restrict__ in,
                              const float* __restrict__ g2, const float* __restrict__ b2,
                              const float* __restrict__ g3, const float* __restrict__ b3,
                              __half* __restrict__ spin, __half* __restrict__ hb) {
    int row = blockIdx.x;
    int t = threadIdx.x;
    __shared__ float ss[4], ssq[4];
    const float4 v = ((const float4*)(in + (long)row * Cn))[t];
    float s  = v.x + v.y + v.z + v.w;
    float sq = v.x*v.x + v.y*v.y + v.z*v.z + v.w*v.w;
    #pragma unroll
    for (int o = 16; o; o >>= 1) {
        s  += __shfl_xor_sync(0xFFFFFFFFu, s,  o);
        sq += __shfl_xor_sync(0xFFFFFFFFu, sq, o);
    }
    if ((t & 31) == 0) { ss[t >> 5] = s; ssq[t >> 5] = sq; }
    __syncthreads();
    s  = ss[0] + ss[1] + ss[2] + ss[3];
    sq = ssq[0] + ssq[1] + ssq[2] + ssq[3];
    float mu   = s * (1.0f / Cn);
    float var  = sq * (1.0f / Cn) - mu * mu;
    float rstd = rsqrtf(var + 1e-5f);
    float4 gg = ((const float4*)g2)[t];
    float4 bb = ((const float4*)b2)[t];
    float4 o1;
    o1.x = (v.x - mu) * rstd * gg.x + bb.x;
    o1.y = (v.y - mu) * rstd * gg.y + bb.y;
    o1.z = (v.z - mu) * rstd * gg.z + bb.z;
    o1.w = (v.w - mu) * rstd * gg.w + bb.w;
    __half2* sp = (__half2*)(spin + (long)row * Cn);
    sp[t * 2]     = __floats2half2_rn(o1.x, o1.y);
    sp[t * 2 + 1] = __floats2half2_rn(o1.z, o1.w);
    float s2  = o1.x + o1.y + o1.z + o1.w;
    float sq2 = o1.x*o1.x + o1.y*o1.y + o1.z*o1.z + o1.w*o1.w;
    #pragma unroll
    for (int o = 16; o; o >>= 1) {
        s2  += __shfl_xor_sync(0xFFFFFFFFu, s2,  o);
        sq2 += __shfl_xor_sync(0xFFFFFFFFu, sq2, o);
    }
    __syncthreads();
    if ((t & 31) == 0) { ss[t >> 5] = s2; ssq[t >> 5] = sq2; }
    __syncthreads();
    s2  = ss[0] + ss[1] + ss[2] + ss[3];
    sq2 = ssq[0] + ssq[1] + ssq[2] + ssq[3];
    float mu2   = s2 * (1.0f / Cn);
    float var2  = sq2 * (1.0f / Cn) - mu2 * mu2;
    float rstd2 = rsqrtf(var2 + 1e-5f);
    float4 g4 = ((const float4*)g3)[t];
    float4 b4 = ((const float4*)b3)[t];
    __half2* o = (__half2*)(hb + (long)row * Cn);
    o[t * 2]     = __floats2half2_rn((o1.x - mu2) * rstd2 * g4.x + b4.x,
                                     (o1.y - mu2) * rstd2 * g4.y + b4.y);
    o[t * 2 + 1] = __floats2half2_rn((o1.z - mu2) * rstd2 * g4.z + b4.z,
                                     (o1.w - mu2) * rstd2 * g4.w + b4.w);
}

// ---------------- qk post: elu applied at smem fill, then pure-FMA LePE ----------------
__global__ void qk_post_kernel(const __half* __restrict__ qkv,
                               const float* __restrict__ lw, const float* __restrict__ lb,
                               __half* __restrict__ q2, __half* __restrict__ k2) {
    int bh = blockIdx.x;
    int lt = blockIdx.y;
    int l0 = lt * 64;
    int b = bh >> 3, h = bh & 7;
    const __half* base = qkv + (long)b * Ln * 1536 + h * 64;
    __shared__ __half sId[2][64][64];     // elu'd identity values
    __shared__ __half sTapT[2][64][66];   // elu'd taps, [sel][c][d]
    __shared__ __half sLo[2][64], sHi[2][64];
    int t = threadIdx.x;
    #pragma unroll
    for (int sel = 0; sel < 2; sel++) {
        #pragma unroll
        for (int i = 0; i < 2; i++) {
            int idx = t + i * 256;
            int r  = idx >> 3;
            int c8 = (idx & 7) * 8;
            __half tmp[8];
            *(uint4*)tmp = *(const uint4*)&base[(long)(l0 + r) * 1536 + sel * 512 + c8];
            #pragma unroll
            for (int k = 0; k < 8; k++) tmp[k] = __float2half_rn(elu1f(__half2float(tmp[k])));
            *(uint4*)&sId[sel][r][c8] = *(uint4*)tmp;
            *(uint4*)tmp = *(const uint4*)&base[(long)(r * 32 + lt) * 1536 + sel * 512 + c8];
            #pragma unroll
            for (int k = 0; k < 8; k++)
                sTapT[sel][c8 + k][r] = __float2half_rn(elu1f(__half2float(tmp[k])));
        }
    }
    if (t < 128) {
        int sel = t >> 6, d = t & 63;
        float lo = 0.0f, hi = 0.0f;
        if (l0 > 0)       lo = elu1f(__half2float(base[(long)(d * 32 + lt - 1) * 1536 + sel * 512 + 63]));
        if (l0 + 64 < Ln) hi = elu1f(__half2float(base[(long)(d * 32 + lt + 1) * 1536 + sel * 512]));
        sLo[sel][d] = __float2half_rn(lo);
        sHi[sel][d] = __float2half_rn(hi);
    }
    __syncthreads();
    int d2 = (t & 31) * 2, rb = t >> 5;
    #pragma unroll
    for (int sel = 0; sel < 2; sel++) {
        __half* dst = sel ? k2 : q2;
        float w0[2], w1[2], w2[2], bi[2];
        #pragma unroll
        for (int dd = 0; dd < 2; dd++) {
            int d = d2 + dd;
            w0[dd] = lw[d*3]; w1[dd] = lw[d*3+1]; w2[dd] = lw[d*3+2]; bi[dd] = lb[d];
        }
        #pragma unroll
        for (int i = 0; i < 8; i++) {
            int r = rb + i * 8;
            float o[2];
            #pragma unroll
            for (int dd = 0; dd < 2; dd++) {
                int d = d2 + dd;
                float c1 = __half2float(sTapT[sel][r][d]);
                float c0 = (r > 0) ? __half2float(sTapT[sel][r-1][d]) : __half2float(sLo[sel][d]);
                float c2 = (r < 63) ? __half2float(sTapT[sel][r+1][d]) : __half2float(sHi[sel][d]);
                o[dd] = __half2float(sId[sel][r][d]) + bi[dd]
                      + w0[dd] * c0 + w1[dd] * c1 + w2[dd] * c2;
            }
            *(__half2*)&dst[(long)bh * (Ln * Dn) + (long)(l0 + r) * 64 + d2] =
                __floats2half2_rn(o[0], o[1]);
        }
    }
}

// ---------------- kv partials + kmean partials (fused) ----------------
__global__ void kv_kernel(const __half* __restrict__ k2, const __half* __restrict__ qkv,
                          float* __restrict__ part, float* __restrict__ kmpart) {
    int bh = blockIdx.x, chunk = blockIdx.y;
    int b = bh >> 3, h = bh & 7;
    __shared__ float ks[32][64];
    __shared__ float vs[32][64];
    int t = threadIdx.x;
    int e0 = (t & 15) * 4, d0 = (t >> 4) * 4;
    float acc[4][4] = {};
    float ksum[4] = {};
    bool kmwriter = (t & 15) == 0;
    int lc = Ln / KVCHUNKS;
    for (int l0 = chunk * lc; l0 < chunk * lc + lc; l0 += 32) {
        #pragma unroll
        for (int i = 0; i < 2; i++) {
            int idx = t + i * 256;
            int r = idx >> 4, c4 = (idx & 15) * 4;
            int l = l0 + r;
            uint2 kr = *(const uint2*)&k2[((long)bh * Ln + l) * 64 + c4];
            uint2 vr = *(const uint2*)&qkv[((long)(b * Ln + l)) * 1536 + 1024 + h * 64 + c4];
            float2 k0 = __half22float2(*(__half2*)&kr.x);
            float2 k1 = __half22float2(*(__half2*)&kr.y);
            float2 v0 = __half22float2(*(__half2*)&vr.x);
            float2 v1 = __half22float2(*(__half2*)&vr.y);
            ks[r][c4] = k0.x; ks[r][c4+1] = k0.y; ks[r][c4+2] = k1.x; ks[r][c4+3] = k1.y;
            vs[r][c4] = v0.x; vs[r][c4+1] = v0.y; vs[r][c4+2] = v1.x; vs[r][c4+3] = v1.y;
        }
        __syncthreads();
        #pragma unroll
        for (int l = 0; l < 32; l++) {
            float4 kr = *(const float4*)&ks[l][d0];
            float4 vr = *(const float4*)&vs[l][e0];
            float k_[4] = {kr.x, kr.y, kr.z, kr.w};
            float v_[4] = {vr.x, vr.y, vr.z, vr.w};
            if (kmwriter) {
                ksum[0] += k_[0]; ksum[1] += k_[1]; ksum[2] += k_[2]; ksum[3] += k_[3];
            }
            #pragma unroll
            for (int i = 0; i < 4; i++)
                #pragma unroll
                for (int j = 0; j < 4; j++)
                    acc[i][j] += k_[i] * v_[j];
        }
        __syncthreads();
    }
    float* dst = part + ((long)chunk * BHn + bh) * (Dn * Dn);
    #pragma unroll
    for (int i = 0; i < 4; i++)
        #pragma unroll
        for (int j = 0; j < 4; j++)
            dst[(d0 + i) * 64 + e0 + j] = acc[i][j];
    if (kmwriter) {
        float* kd = kmpart + ((long)chunk * BHn + bh) * Dn + d0;
        kd[0] = ksum[0]; kd[1] = ksum[1]; kd[2] = ksum[2]; kd[3] = ksum[3];
    }
}

// ---------------- reduce kv partials + kmean partials ----------------
__global__ void kv_reduce_kernel(const float* __restrict__ part, const float* __restrict__ kmpart,
                                 float* __restrict__ kv, float* __restrict__ km) {
    int i = blockIdx.x * blockDim.x + threadIdx.x;
    if (i < BHn * Dn * Dn) {
        float s = 0.0f;
        #pragma unroll
        for (int c = 0; c < KVCHUNKS; c++) s += part[(long)c * (BHn * Dn * Dn) + i];
        kv[i] = s * (1.0f / Ln);
    } else if (i < BHn * Dn * Dn + BHn * Dn) {
        int j = i - BHn * Dn * Dn;
        float s = 0.0f;
        #pragma unroll
        for (int c = 0; c < KVCHUNKS; c++) s += kmpart[(long)c * (BHn * Dn) + j];
        km[j] = s * (1.0f / Ln);
    }
}

// ---------------- attention output: xbuf = x + (q2@kv) * z, z fused; 128 rows/block ----------------
__global__ void attn_out_kernel(const __half* __restrict__ q2, const float* __restrict__ kv,
                                const float* __restrict__ km, const float* __restrict__ x,
                                float* __restrict__ xbuf) {
    int bh = blockIdx.x, b = bh >> 3, h = bh & 7;
    int lbase = blockIdx.y * 128;
    __shared__ float kvs[64][64];
    __shared__ float qs[16][64];
    __shared__ float skm[64];
    int t = threadIdx.x;
    #pragma unroll
    for (int i = 0; i < 4; i++) {
        int idx = t + i * 256;
        ((float4*)kvs)[idx] = ((const float4*)(kv + (long)bh * 4096))[idx];
    }
    if (t < 64) skm[t] = km[bh * 64 + t];
    int g = t >> 4;
    int e0 = (t & 15) * 4;
    for (int it = 0; it < 8; it++) {
        __syncthreads();
        int rbase = lbase + it * 16;
        #pragma unroll
        for (int i = 0; i < 4; i++) {
            int idx = t + i * 256;
            int r = idx >> 6, c = idx & 63;
            qs[r][c] = __half2float(q2[((long)bh * Ln + rbase + r) * 64 + c]);
        }
        __syncthreads();
        int l = rbase + g;
        float part = qs[g][e0] * skm[e0] + qs[g][e0+1] * skm[e0+1]
                   + qs[g][e0+2] * skm[e0+2] + qs[g][e0+3] * skm[e0+3];
        #pragma unroll
        for (int o = 8; o; o >>= 1) part += __shfl_xor_sync(0xFFFFFFFFu, part, o);
        float zz = 1.0f / (part + 1e-6f);
        float4 acc = {0.f, 0.f, 0.f, 0.f};
        #pragma unroll
        for (int d = 0; d < 64; d++) {
            float qd = qs[g][d];
            float4 kvv = *(const float4*)&kvs[d][e0];
            acc.x += qd * kvv.x; acc.y += qd * kvv.y;
            acc.z += qd * kvv.z; acc.w += qd * kvv.w;
        }
        long off = ((long)(b * Ln + l)) * Cn + h * 64 + e0;
        float4 cur = *(const float4*)&x[off];
        cur.x += acc.x * zz; cur.y += acc.y * zz;
        cur.z += acc.z * zz; cur.w += acc.w * zz;
        *(float4*)&xbuf[off] = cur;
    }
}

// ================= fp16 mma.sync GEMM =================
#define GSM (3 * 16384)

template<int EPI, int CONVA>
__global__ void __launch_bounds__(256, 2)
gemm_h(const __half* __restrict__ A, const __half* __restrict__ Bt,
       const float* __restrict__ bias, const void* __restrict__ resv,
       void* __restrict__ Cv, int M, int N, int K) {
    extern __shared__ char smraw[];
    uint32_t sb = smem_u32(smraw);
    int t = threadIdx.x, wid = t >> 5, lane = t & 31;
    int g = lane >> 2, tig = lane & 3;
    int bm = blockIdx.y * 128, bn = blockIdx.x * 128;
    int wm = (wid >> 2) * 64, wn = (wid & 3) * 32;

    const __half* aG[2]; const __half* bG[2]; uint32_t offA[2], offB[2];
    int rs[2], cs[2];
    #pragma unroll
    for (int i = 0; i < 2; i++) {
        int idx = t + i * 256;
        int r = idx >> 2;
        int c = idx & 3;
        rs[i] = r; cs[i] = c;
        uint32_t off = (uint32_t)r * 64 + ((c ^ swz(r)) << 4);
        offA[i] = off;
        offB[i] = off + 8192;
        if (!CONVA) aG[i] = A + (long)(bm + r) * K + c * 8;
        bG[i] = Bt + (long)(bn + r) * K + c * 8;
    }

    uint32_t aRow[4], aSw[4];
    #pragma unroll
    for (int mt = 0; mt < 4; mt++) {
        uint32_t m = wm + mt * 16 + (lane & 15);
        aRow[mt] = m * 64;
        aSw[mt] = swz(m);
    }
    uint32_t cHiA = lane >> 4;
    uint32_t bRow[2], bSw[2];
    #pragma unroll
    for (int np = 0; np < 2; np++) {
        uint32_t n = wn + np * 16 + ((lane >> 4) << 3) + (lane & 7);
        bRow[np] = n * 64 + 8192;
        bSw[np] = swz(n);
    }
    uint32_t cHiB = (lane >> 3) & 1;

    int nk = K >> 5;

    auto loadA_conv = [&](uint32_t stb, int kt) {
        int tap = kt >> 4;
        int kin = (kt & 15) * 32;
        #pragma unroll
        for (int i = 0; i < 2; i++) {
            long row = bm + rs[i];
            int l = (int)(row & (Ln - 1));
            bool valid = (unsigned)(l + tap - 1) < (unsigned)Ln;
            const __half* src = valid ? (A + (row + tap - 1) * Cn + kin + cs[i] * 8) : A;
            cpasync16z(stb + offA[i], src, valid ? 16u : 0u);
        }
    };

    #pragma unroll
    for (int s = 0; s < 2; s++) {
        uint32_t stb = sb + s * 16384;
        if (CONVA) loadA_conv(stb, s);
        else {
            #pragma unroll
            for (int i = 0; i < 2; i++) cpasync16(stb + offA[i], aG[i] + s * 32);
        }
        #pragma unroll
        for (int i = 0; i < 2; i++) cpasync16(stb + offB[i], bG[i] + s * 32);
        CP_COMMIT();
    }
    CP_WAIT1();
    __syncthreads();

    float acc[4][4][4] = {};

    for (int kt = 0; kt < nk; kt++) {
        if (kt + 2 < nk) {
            uint32_t stb = sb + ((kt + 2) % 3) * 16384;
            if (CONVA) loadA_conv(stb, kt + 2);
            else {
                #pragma unroll
                for (int i = 0; i < 2; i++) cpasync16(stb + offA[i], aG[i] + (long)(kt + 2) * 32);
            }
            #pragma unroll
            for (int i = 0; i < 2; i++) cpasync16(stb + offB[i], bG[i] + (long)(kt + 2) * 32);
        }
        CP_COMMIT();

        uint32_t stb = sb + (kt % 3) * 16384;
        #pragma unroll
        for (int kb = 0; kb < 2; kb++) {
            uint32_t a[4][4], b[4][2];
            #pragma unroll
            for (int mt = 0; mt < 4; mt++) {
                uint32_t addr = stb + aRow[mt] + ((((uint32_t)(2 * kb) | cHiA) ^ aSw[mt]) << 4);
                ldsm4(a[mt], addr);
            }
            #pragma unroll
            for (int np = 0; np < 2; np++) {
                uint32_t bb[4];
                uint32_t addr = stb + bRow[np] + ((((uint32_t)(2 * kb) | cHiB) ^ bSw[np]) << 4);
                ldsm4(bb, addr);
                b[2*np][0] = bb[0]; b[2*np][1] = bb[1];
                b[2*np+1][0] = bb[2]; b[2*np+1][1] = bb[3];
            }
            #pragma unroll
            for (int mt = 0; mt < 4; mt++)
                #pragma unroll
                for (int nt = 0; nt < 4; nt++)
                    mma_f16(acc[mt][nt], a[mt], b[nt]);
        }

        CP_WAIT1();
        __syncthreads();
    }

    // ---- epilogue ----
    if (EPI == 3) {
        float* sg = (float*)smraw;
        #pragma unroll
        for (int mt = 0; mt < 4; mt++) {
            int r0 = wm + mt * 16 + g;
            #pragma unroll
            for (int nt = 0; nt < 4; nt++) {
                int col = wn + nt * 8 + tig * 2;
                float b0 = bias[bn + col], b1 = bias[bn + col + 1];
                float vv0 = acc[mt][nt][0] + b0, gg0 = acc[mt][nt][1] + b1;
                float vv1 = acc[mt][nt][2] + b0, gg1 = acc[mt][nt][3] + b1;
                int cp = col >> 1;
                sg[r0 * 68 + cp]       = vv0 / (1.0f + __expf(-gg0));
                sg[(r0 + 8) * 68 + cp] = vv1 / (1.0f + __expf(-gg1));
            }
        }
        __syncthreads();
        int cpb = bn >> 1;
        float* X = (float*)Cv;
        const __half* R = (const __half*)resv;
        #pragma unroll
        for (int i = 0; i < 8; i++) {
            int j = t + i * 256;
            int r = j >> 4, c4 = j & 15;
            long off = (long)(bm + r) * Cn + cpb + c4 * 4;
            float4 xv = *(float4*)(X + off);
            uint2 spraw = *(const uint2*)(R + off);
            float2 s0 = __half22float2(*(__half2*)&spraw.x);
            float2 s1 = __half22float2(*(__half2*)&spraw.y);
            float4 gv = *(float4*)&sg[r * 68 + c4 * 4];
            xv.x += s0.x + gv.x; xv.y += s0.y + gv.y;
            xv.z += s1.x + gv.z; xv.w += s1.y + gv.w;
            *(float4*)(X + off) = xv;
        }
        return;
    }

    #pragma unroll
    for (int mt = 0; mt < 4; mt++) {
        int row = bm + wm + mt * 16 + g;
        #pragma unroll
        for (int nt = 0; nt < 4; nt++) {
            int col = bn + wn + nt * 8 + tig * 2;
            float b0 = bias[col], b1 = bias[col + 1];
            float v00 = acc[mt][nt][0] + b0;
            float v01 = acc[mt][nt][1] + b1;
            float v10 = acc[mt][nt][2] + b0;
            float v11 = acc[mt][nt][3] + b1;
            if (EPI == 1) {
                v00 = 0.5f * v00 * (1.0f + erff(v00 * 0.70710678118654752f));
                v01 = 0.5f * v01 * (1.0f + erff(v01 * 0.70710678118654752f));
                v10 = 0.5f * v10 * (1.0f + erff(v10 * 0.70710678118654752f));
                v11 = 0.5f * v11 * (1.0f + erff(v11 * 0.70710678118654752f));
                __half2* C = (__half2*)Cv;
                C[((long)row * N + col) >> 1]       = __floats2half2_rn(v00, v01);
                C[((long)(row + 8) * N + col) >> 1] = __floats2half2_rn(v10, v11);
            } else if (EPI == 4) {
                __half2* C = (__half2*)Cv;
                C[((long)row * N + col) >> 1]       = __floats2half2_rn(v00, v01);
                C[((long)(row + 8) * N + col) >> 1] = __floats2half2_rn(v10, v11);
            } else {  // EPI == 2
                const float* R = (const float*)resv;
                const float* r0 = R + (long)row * N + col;
                const float* r1 = R + (long)(row + 8) * N + col;
                v00 += r0[0]; v01 += r0[1];
                v10 += r1[0]; v11 += r1[1];
                float* C = (float*)Cv;
                float2 p0 = {v00, v01}, p1 = {v10, v11};
                *(float2*)(C + (long)row * N + col)       = p0;
                *(float2*)(C + (long)(row + 8) * N + col) = p1;
            }
        }
    }
}

// ---------------- host launcher ----------------
extern "C" void kernel_launch(void* const* d_in, const int* in_sizes, int n_in,
                              void* d_out, int out_size) {
    const float* x      = (const float*)d_in[0];
    const float* g1     = (const float*)d_in[1];
    const float* b1     = (const float*)d_in[2];
    const float* qk_w   = (const float*)d_in[3];
    const float* qk_b   = (const float*)d_in[4];
    const float* v_w    = (const float*)d_in[5];
    const float* v_b    = (const float*)d_in[6];
    const float* lepe_w = (const float*)d_in[7];
    const float* lepe_b = (const float*)d_in[8];
    const float* g2     = (const float*)d_in[9];
    const float* b2     = (const float*)d_in[10];
    const float* spn_g  = (const float*)d_in[11];
    const float* spn_b  = (const float*)d_in[12];
    const float* sp_cw  = (const float*)d_in[13];
    const float* sp_cb  = (const float*)d_in[14];
    const float* g3     = (const float*)d_in[15];
    const float* b3     = (const float*)d_in[16];
    const float* w1     = (const float*)d_in[17];
    const float* bb1    = (const float*)d_in[18];
    const float* w2     = (const float*)d_in[19];
    const float* bb2    = (const float*)d_in[20];
    float* out = (float*)d_out;

    float *xbuf, *km, *kv, *kvpart, *kmpart, *bias2, *bias3;
    __half *lnh, *qkvh, *q2h, *k2h, *spinh, *hb, *ffnh, *qkvTh, *w1Th, *w2Th, *wtT2h;
    cudaGetSymbolAddress((void**)&xbuf,   g_xbuf);
    cudaGetSymbolAddress((void**)&lnh,    g_lnh);
    cudaGetSymbolAddress((void**)&qkvh,   g_qkvh);
    cudaGetSymbolAddress((void**)&q2h,    g_q2h);
    cudaGetSymbolAddress((void**)&k2h,    g_k2h);
    cudaGetSymbolAddress((void**)&km,     g_kmean);
    cudaGetSymbolAddress((void**)&kv,     g_kv);
    cudaGetSymbolAddress((void**)&kvpart, g_kvpart);
    cudaGetSymbolAddress((void**)&kmpart, g_kmpart);
    cudaGetSymbolAddress((void**)&spinh,  g_spinh);
    cudaGetSymbolAddress((void**)&hb,     g_hb);
    cudaGetSymbolAddress((void**)&ffnh,   g_ffnh);
    cudaGetSymbolAddress((void**)&qkvTh,  g_qkvTh);
    cudaGetSymbolAddress((void**)&w1Th,   g_w1Th);
    cudaGetSymbolAddress((void**)&w2Th,   g_w2Th);
    cudaGetSymbolAddress((void**)&wtT2h,  g_wtT2h);
    cudaGetSymbolAddress((void**)&bias2,  g_bias2);
    cudaGetSymbolAddress((void**)&bias3,  g_bias3);

    cudaFuncSetAttribute((const void*)gemm_h<4,0>, cudaFuncAttributeMaxDynamicSharedMemorySize, GSM);
    cudaFuncSetAttribute((const void*)gemm_h<3,1>, cudaFuncAttributeMaxDynamicSharedMemorySize, GSM);
    cudaFuncSetAttribute((const void*)gemm_h<1,0>, cudaFuncAttributeMaxDynamicSharedMemorySize, GSM);
    cudaFuncSetAttribute((const void*)gemm_h<2,0>, cudaFuncAttributeMaxDynamicSharedMemorySize, GSM);

    prep_weights_kernel<<<(int)((PW_TOT + 255) / 256), 256>>>(
        qk_w, v_w, w1, w2, sp_cw, qk_b, v_b, sp_cb,
        qkvTh, w1Th, w2Th, wtT2h, bias2, bias3);

    // Block 1: xbuf = x + attn(LN1(x))
    ln_h_kernel<<<BLn, 128>>>(x, g1, b1, lnh);
    gemm_h<4,0><<<dim3(1536 / 128, BLn / 128), 256, GSM>>>(lnh, qkvTh, bias3, nullptr, qkvh, BLn, 1536, Cn);
    qk_post_kernel<<<dim3(BHn, Ln / 64), 256>>>(qkvh, lepe_w, lepe_b, q2h, k2h);
    kv_kernel<<<dim3(BHn, KVCHUNKS), 256>>>(k2h, qkvh, kvpart, kmpart);
    kv_reduce_kernel<<<(BHn * Dn * Dn + BHn * Dn + 255) / 256, 256>>>(kvpart, kmpart, kv, km);
    attn_out_kernel<<<dim3(BHn, Ln / 128), 256>>>(q2h, kv, km, x, xbuf);

    // Block 2: gated conv state path
    ln2ln3_kernel<<<BLn, 128>>>(xbuf, g2, b2, spn_g, spn_b, spinh, hb);
    gemm_h<3,1><<<dim3(1024 / 128, BLn / 128), 256, GSM>>>(hb, wtT2h, bias2, spinh, xbuf, BLn, 1024, 3 * Cn);

    // Block 3: FFN
    ln_h_kernel<<<BLn, 128>>>(xbuf, g3, b3, lnh);
    gemm_h<1,0><<<dim3(FFn / 128, BLn / 128), 256, GSM>>>(lnh, w1Th, bb1, nullptr, ffnh, BLn, FFn, Cn);
    gemm_h<2,0><<<dim3(512 / 128, BLn / 128), 256, GSM>>>(ffnh, w2Th, bb2, xbuf, out, BLn, 512, FFn);
}

// round 11
// speedup vs baseline: 1.4672x; 1.0101x over previous
#include <cuda_runtime.h>
#include <cuda_fp16.h>
#include <math.h>
#include <stdint.h>

#define Bn 8
#define Ln 2048
#define Cn 512
#define Hn 8
#define Dn 64
#define FFn 2048
#define BLn (Bn*Ln)          /* 16384 */
#define BHn (Bn*Hn)          /* 64    */
#define BHLn (BHn*Ln)        /* 131072*/
#define KVCHUNKS 8

// ---------------- scratch (static device globals; no allocation) ----------------
static __device__ __align__(16) __half g_xbufh[BLn*Cn];      // residual stream (half)
static __device__ __align__(16) __half g_lnh[BLn*Cn];
static __device__ __align__(16) __half g_qkvh[(long)BLn*1536];
static __device__ __align__(16) __half g_q2h[BHLn*Dn];
static __device__ __align__(16) __half g_k2h[BHLn*Dn];
static __device__ __align__(16) float  g_kmean[BHn*Dn];
static __device__ __align__(16) float  g_kv[BHn*Dn*Dn];
static __device__ __align__(16) float  g_kvpart[KVCHUNKS*BHn*Dn*Dn];
static __device__ __align__(16) float  g_kmpart[KVCHUNKS*BHn*Dn];
static __device__ __align__(16) __half g_spinh[BLn*Cn];
static __device__ __align__(16) __half g_hb[BLn*Cn];
static __device__ __align__(16) __half g_ffnh[(long)BLn*FFn];
// weights (half), prepared once per call
static __device__ __align__(16) __half g_qkvTh[1536*512];
static __device__ __align__(16) __half g_w1Th[2048*512];
static __device__ __align__(16) __half g_w2Th[512*2048];
static __device__ __align__(16) __half g_wtT2h[1024*1536];   // interleaved (vv,gg) pairs
static __device__ __align__(16) float  g_bias2[1024];
static __device__ __align__(16) float  g_bias3[1536];

// ---------------- PTX helpers ----------------
__device__ __forceinline__ uint32_t smem_u32(const void* p) {
    uint32_t a;
    asm("{ .reg .u64 t; cvta.to.shared.u64 t, %1; cvt.u32.u64 %0, t; }" : "=r"(a) : "l"(p));
    return a;
}
__device__ __forceinline__ void cpasync16(uint32_t saddr, const void* g) {
    asm volatile("cp.async.cg.shared.global [%0], [%1], 16;" :: "r"(saddr), "l"(g) : "memory");
}
__device__ __forceinline__ void cpasync16z(uint32_t saddr, const void* g, uint32_t sz) {
    asm volatile("cp.async.cg.shared.global [%0], [%1], 16, %2;"
                 :: "r"(saddr), "l"(g), "r"(sz) : "memory");
}
#define CP_COMMIT() asm volatile("cp.async.commit_group;" ::: "memory")
#define CP_WAIT1()  asm volatile("cp.async.wait_group 1;" ::: "memory")

__device__ __forceinline__ void ldsm4(uint32_t* r, uint32_t addr) {
    asm volatile("ldmatrix.sync.aligned.m8n8.x4.shared.b16 {%0,%1,%2,%3}, [%4];"
        : "=r"(r[0]), "=r"(r[1]), "=r"(r[2]), "=r"(r[3]) : "r"(addr));
}
__device__ __forceinline__ void mma_f16(float* c, const uint32_t* a, const uint32_t* b) {
    asm volatile(
        "mma.sync.aligned.m16n8k16.row.col.f32.f16.f16.f32 "
        "{%0,%1,%2,%3}, {%4,%5,%6,%7}, {%8,%9}, {%0,%1,%2,%3};"
        : "+f"(c[0]), "+f"(c[1]), "+f"(c[2]), "+f"(c[3])
        : "r"(a[0]), "r"(a[1]), "r"(a[2]), "r"(a[3]), "r"(b[0]), "r"(b[1]));
}

// ---------------- small helpers ----------------
__device__ __forceinline__ float elu1f(float x) { return x > 0.0f ? x + 1.0f : __expf(x); }
__device__ __forceinline__ uint32_t swz(uint32_t r) { return (r ^ (r >> 2)) & 3u; }

// ---------------- one-shot weight prep ----------------
#define PW_S0 524288L
#define PW_S1 (PW_S0 + 262144L)
#define PW_S2 (PW_S1 + 1048576L)
#define PW_S3 (PW_S2 + 1048576L)
#define PW_S4 (PW_S3 + 1572864L)
#define PW_TOT (PW_S4 + 1536L)
__global__ void prep_weights_kernel(const float* __restrict__ qk_w, const float* __restrict__ v_w,
                                    const float* __restrict__ w1, const float* __restrict__ w2,
                                    const float* __restrict__ sp_cw,
                                    const float* __restrict__ qk_b, const float* __restrict__ v_b,
                                    const float* __restrict__ sp_cb,
                                    __half* __restrict__ qkvT, __half* __restrict__ w1T,
                                    __half* __restrict__ w2T, __half* __restrict__ wtT2,
                                    float* __restrict__ bias2, float* __restrict__ bias3) {
    long idx = (long)blockIdx.x * blockDim.x + threadIdx.x;
    if (idx < PW_S0) {
        int k = (int)(idx & 511), n = (int)(idx >> 9);
        qkvT[idx] = __float2half_rn(qk_w[(long)k * 1024 + n]);
    } else if (idx < PW_S1) {
        long i = idx - PW_S0;
        int k = (int)(i & 511), n = (int)(i >> 9);
        qkvT[idx] = __float2half_rn(v_w[(long)k * 512 + n]);
    } else if (idx < PW_S2) {
        long i = idx - PW_S1;
        int k = (int)(i & 511), n = (int)(i >> 9);
        w1T[i] = __float2half_rn(w1[(long)k * 2048 + n]);
    } else if (idx < PW_S3) {
        long i = idx - PW_S2;
        int k = (int)(i & 2047), n = (int)(i >> 11);
        w2T[i] = __float2half_rn(w2[(long)k * 512 + n]);
    } else if (idx < PW_S4) {
        long i = idx - PW_S3;
        int kk = (int)(i % 1536), n2 = (int)(i / 1536);
        int co = (n2 & 1) * 512 + (n2 >> 1);
        int k  = kk >> 9, ci = kk & 511;
        wtT2[i] = __float2half_rn(sp_cw[co * 1536 + ci * 3 + k]);
        if (kk == 0) bias2[n2] = sp_cb[co];
    } else if (idx < PW_TOT) {
        int j = (int)(idx - PW_S4);
        bias3[j] = (j < 1024) ? qk_b[j] : v_b[j - 1024];
    }
}

// ---------------- LayerNorm, float input -> half out (LN1 on x) ----------------
__global__ void ln_h_kernel(const float* __restrict__ in, const float* __restrict__ gam,
                            const float* __restrict__ bet, __half* __restrict__ out) {
    int row = blockIdx.x;
    int t = threadIdx.x;
    const float4 v = ((const float4*)(in + (long)row * Cn))[t];
    float s  = v.x + v.y + v.z + v.w;
    float sq = v.x*v.x + v.y*v.y + v.z*v.z + v.w*v.w;
    #pragma unroll
    for (int o = 16; o; o >>= 1) {
        s  += __shfl_xor_sync(0xFFFFFFFFu, s,  o);
        sq += __shfl_xor_sync(0xFFFFFFFFu, sq, o);
    }
    __shared__ float ss[4], ssq[4];
    if ((t & 31) == 0) { ss[t >> 5] = s; ssq[t >> 5] = sq; }
    __syncthreads();
    s  = ss[0] + ss[1] + ss[2] + ss[3];
    sq = ssq[0] + ssq[1] + ssq[2] + ssq[3];
    float mu   = s * (1.0f / Cn);
    float var  = sq * (1.0f / Cn) - mu * mu;
    float rstd = rsqrtf(var + 1e-5f);
    float4 g4 = ((const float4*)gam)[t];
    float4 b4 = ((const float4*)bet)[t];
    __half2* o = (__half2*)(out + (long)row * Cn);
    o[t * 2]     = __floats2half2_rn((v.x - mu) * rstd * g4.x + b4.x,
                                     (v.y - mu) * rstd * g4.y + b4.y);
    o[t * 2 + 1] = __floats2half2_rn((v.z - mu) * rstd * g4.z + b4.z,
                                     (v.w - mu) * rstd * g4.w + b4.w);
}

// ---------------- LayerNorm, half input -> half out (LN3 on xbufh) ----------------
__global__ void ln_hh_kernel(const __half* __restrict__ in, const float* __restrict__ gam,
                             const float* __restrict__ bet, __half* __restrict__ out) {
    int row = blockIdx.x;
    int t = threadIdx.x;
    uint2 raw = ((const uint2*)(in + (long)row * Cn))[t];
    float2 p0 = __half22float2(*(__half2*)&raw.x);
    float2 p1 = __half22float2(*(__half2*)&raw.y);
    float4 v = {p0.x, p0.y, p1.x, p1.y};
    float s  = v.x + v.y + v.z + v.w;
    float sq = v.x*v.x + v.y*v.y + v.z*v.z + v.w*v.w;
    #pragma unroll
    for (int o = 16; o; o >>= 1) {
        s  += __shfl_xor_sync(0xFFFFFFFFu, s,  o);
        sq += __shfl_xor_sync(0xFFFFFFFFu, sq, o);
    }
    __shared__ float ss[4], ssq[4];
    if ((t & 31) == 0) { ss[t >> 5] = s; ssq[t >> 5] = sq; }
    __syncthreads();
    s  = ss[0] + ss[1] + ss[2] + ss[3];
    sq = ssq[0] + ssq[1] + ssq[2] + ssq[3];
    float mu   = s * (1.0f / Cn);
    float var  = sq * (1.0f / Cn) - mu * mu;
    float rstd = rsqrtf(var + 1e-5f);
    float4 g4 = ((const float4*)gam)[t];
    float4 b4 = ((const float4*)bet)[t];
    __half2* o = (__half2*)(out + (long)row * Cn);
    o[t * 2]     = __floats2half2_rn((v.x - mu) * rstd * g4.x + b4.x,
                                     (v.y - mu) * rstd * g4.y + b4.y);
    o[t * 2 + 1] = __floats2half2_rn((v.z - mu) * rstd * g4.z + b4.z,
                                     (v.w - mu) * rstd * g4.w + b4.w);
}

// ---------------- fused LN2 + LN3 (half in) ----------------
__global__ void ln2ln3_kernel(const __half* __restrict__ in,
                              const float* __restrict__ g2, const float* __restrict__ b2,
                              const float* __restrict__ g3, const float* __restrict__ b3,
                              __half* __restrict__ spin, __half* __restrict__ hb) {
    int row = blockIdx.x;
    int t = threadIdx.x;
    __shared__ float ss[4], ssq[4];
    uint2 raw = ((const uint2*)(in + (long)row * Cn))[t];
    float2 p0 = __half22float2(*(__half2*)&raw.x);
    float2 p1 = __half22float2(*(__half2*)&raw.y);
    float4 v = {p0.x, p0.y, p1.x, p1.y};
    float s  = v.x + v.y + v.z + v.w;
    float sq = v.x*v.x + v.y*v.y + v.z*v.z + v.w*v.w;
    #pragma unroll
    for (int o = 16; o; o >>= 1) {
        s  += __shfl_xor_sync(0xFFFFFFFFu, s,  o);
        sq += __shfl_xor_sync(0xFFFFFFFFu, sq, o);
    }
    if ((t & 31) == 0) { ss[t >> 5] = s; ssq[t >> 5] = sq; }
    __syncthreads();
    s  = ss[0] + ss[1] + ss[2] + ss[3];
    sq = ssq[0] + ssq[1] + ssq[2] + ssq[3];
    float mu   = s * (1.0f / Cn);
    float var  = sq * (1.0f / Cn) - mu * mu;
    float rstd = rsqrtf(var + 1e-5f);
    float4 gg = ((const float4*)g2)[t];
    float4 bb = ((const float4*)b2)[t];
    float4 o1;
    o1.x = (v.x - mu) * rstd * gg.x + bb.x;
    o1.y = (v.y - mu) * rstd * gg.y + bb.y;
    o1.z = (v.z - mu) * rstd * gg.z + bb.z;
    o1.w = (v.w - mu) * rstd * gg.w + bb.w;
    __half2* sp = (__half2*)(spin + (long)row * Cn);
    sp[t * 2]     = __floats2half2_rn(o1.x, o1.y);
    sp[t * 2 + 1] = __floats2half2_rn(o1.z, o1.w);
    float s2  = o1.x + o1.y + o1.z + o1.w;
    float sq2 = o1.x*o1.x + o1.y*o1.y + o1.z*o1.z + o1.w*o1.w;
    #pragma unroll
    for (int o = 16; o; o >>= 1) {
        s2  += __shfl_xor_sync(0xFFFFFFFFu, s2,  o);
        sq2 += __shfl_xor_sync(0xFFFFFFFFu, sq2, o);
    }
    __syncthreads();
    if ((t & 31) == 0) { ss[t >> 5] = s2; ssq[t >> 5] = sq2; }
    __syncthreads();
    s2  = ss[0] + ss[1] + ss[2] + ss[3];
    sq2 = ssq[0] + ssq[1] + ssq[2] + ssq[3];
    float mu2   = s2 * (1.0f / Cn);
    float var2  = sq2 * (1.0f / Cn) - mu2 * mu2;
    float rstd2 = rsqrtf(var2 + 1e-5f);
    float4 g4 = ((const float4*)g3)[t];
    float4 b4 = ((const float4*)b3)[t];
    __half2* o = (__half2*)(hb + (long)row * Cn);
    o[t * 2]     = __floats2half2_rn((o1.x - mu2) * rstd2 * g4.x + b4.x,
                                     (o1.y - mu2) * rstd2 * g4.y + b4.y);
    o[t * 2 + 1] = __floats2half2_rn((o1.z - mu2) * rstd2 * g4.z + b4.z,
                                     (o1.w - mu2) * rstd2 * g4.w + b4.w);
}

// ---------------- qk post: elu applied at smem fill, then pure-FMA LePE ----------------
__global__ void qk_post_kernel(const __half* __restrict__ qkv,
                               const float* __restrict__ lw, const float* __restrict__ lb,
                               __half* __restrict__ q2, __half* __restrict__ k2) {
    int bh = blockIdx.x;
    int lt = blockIdx.y;
    int l0 = lt * 64;
    int b = bh >> 3, h = bh & 7;
    const __half* base = qkv + (long)b * Ln * 1536 + h * 64;
    __shared__ __half sId[2][64][64];
    __shared__ __half sTapT[2][64][66];
    __shared__ __half sLo[2][64], sHi[2][64];
    int t = threadIdx.x;
    #pragma unroll
    for (int sel = 0; sel < 2; sel++) {
        #pragma unroll
        for (int i = 0; i < 2; i++) {
            int idx = t + i * 256;
            int r  = idx >> 3;
            int c8 = (idx & 7) * 8;
            __half tmp[8];
            *(uint4*)tmp = *(const uint4*)&base[(long)(l0 + r) * 1536 + sel * 512 + c8];
            #pragma unroll
            for (int k = 0; k < 8; k++) tmp[k] = __float2half_rn(elu1f(__half2float(tmp[k])));
            *(uint4*)&sId[sel][r][c8] = *(uint4*)tmp;
            *(uint4*)tmp = *(const uint4*)&base[(long)(r * 32 + lt) * 1536 + sel * 512 + c8];
            #pragma unroll
            for (int k = 0; k < 8; k++)
                sTapT[sel][c8 + k][r] = __float2half_rn(elu1f(__half2float(tmp[k])));
        }
    }
    if (t < 128) {
        int sel = t >> 6, d = t & 63;
        float lo = 0.0f, hi = 0.0f;
        if (l0 > 0)       lo = elu1f(__half2float(base[(long)(d * 32 + lt - 1) * 1536 + sel * 512 + 63]));
        if (l0 + 64 < Ln) hi = elu1f(__half2float(base[(long)(d * 32 + lt + 1) * 1536 + sel * 512]));
        sLo[sel][d] = __float2half_rn(lo);
        sHi[sel][d] = __float2half_rn(hi);
    }
    __syncthreads();
    int d2 = (t & 31) * 2, rb = t >> 5;
    #pragma unroll
    for (int sel = 0; sel < 2; sel++) {
        __half* dst = sel ? k2 : q2;
        float w0[2], w1[2], w2[2], bi[2];
        #pragma unroll
        for (int dd = 0; dd < 2; dd++) {
            int d = d2 + dd;
            w0[dd] = lw[d*3]; w1[dd] = lw[d*3+1]; w2[dd] = lw[d*3+2]; bi[dd] = lb[d];
        }
        #pragma unroll
        for (int i = 0; i < 8; i++) {
            int r = rb + i * 8;
            float o[2];
            #pragma unroll
            for (int dd = 0; dd < 2; dd++) {
                int d = d2 + dd;
                float c1 = __half2float(sTapT[sel][r][d]);
                float c0 = (r > 0) ? __half2float(sTapT[sel][r-1][d]) : __half2float(sLo[sel][d]);
                float c2 = (r < 63) ? __half2float(sTapT[sel][r+1][d]) : __half2float(sHi[sel][d]);
                o[dd] = __half2float(sId[sel][r][d]) + bi[dd]
                      + w0[dd] * c0 + w1[dd] * c1 + w2[dd] * c2;
            }
            *(__half2*)&dst[(long)bh * (Ln * Dn) + (long)(l0 + r) * 64 + d2] =
                __floats2half2_rn(o[0], o[1]);
        }
    }
}

// ---------------- kv partials + kmean partials (fused) ----------------
__global__ void kv_kernel(const __half* __restrict__ k2, const __half* __restrict__ qkv,
                          float* __restrict__ part, float* __restrict__ kmpart) {
    int bh = blockIdx.x, chunk = blockIdx.y;
    int b = bh >> 3, h = bh & 7;
    __shared__ float ks[32][64];
    __shared__ float vs[32][64];
    int t = threadIdx.x;
    int e0 = (t & 15) * 4, d0 = (t >> 4) * 4;
    float acc[4][4] = {};
    float ksum[4] = {};
    bool kmwriter = (t & 15) == 0;
    int lc = Ln / KVCHUNKS;
    for (int l0 = chunk * lc; l0 < chunk * lc + lc; l0 += 32) {
        #pragma unroll
        for (int i = 0; i < 2; i++) {
            int idx = t + i * 256;
            int r = idx >> 4, c4 = (idx & 15) * 4;
            int l = l0 + r;
            uint2 kr = *(const uint2*)&k2[((long)bh * Ln + l) * 64 + c4];
            uint2 vr = *(const uint2*)&qkv[((long)(b * Ln + l)) * 1536 + 1024 + h * 64 + c4];
            float2 k0 = __half22float2(*(__half2*)&kr.x);
            float2 k1 = __half22float2(*(__half2*)&kr.y);
            float2 v0 = __half22float2(*(__half2*)&vr.x);
            float2 v1 = __half22float2(*(__half2*)&vr.y);
            ks[r][c4] = k0.x; ks[r][c4+1] = k0.y; ks[r][c4+2] = k1.x; ks[r][c4+3] = k1.y;
            vs[r][c4] = v0.x; vs[r][c4+1] = v0.y; vs[r][c4+2] = v1.x; vs[r][c4+3] = v1.y;
        }
        __syncthreads();
        #pragma unroll
        for (int l = 0; l < 32; l++) {
            float4 kr = *(const float4*)&ks[l][d0];
            float4 vr = *(const float4*)&vs[l][e0];
            float k_[4] = {kr.x, kr.y, kr.z, kr.w};
            float v_[4] = {vr.x, vr.y, vr.z, vr.w};
            if (kmwriter) {
                ksum[0] += k_[0]; ksum[1] += k_[1]; ksum[2] += k_[2]; ksum[3] += k_[3];
            }
            #pragma unroll
            for (int i = 0; i < 4; i++)
                #pragma unroll
                for (int j = 0; j < 4; j++)
                    acc[i][j] += k_[i] * v_[j];
        }
        __syncthreads();
    }
    float* dst = part + ((long)chunk * BHn + bh) * (Dn * Dn);
    #pragma unroll
    for (int i = 0; i < 4; i++)
        #pragma unroll
        for (int j = 0; j < 4; j++)
            dst[(d0 + i) * 64 + e0 + j] = acc[i][j];
    if (kmwriter) {
        float* kd = kmpart + ((long)chunk * BHn + bh) * Dn + d0;
        kd[0] = ksum[0]; kd[1] = ksum[1]; kd[2] = ksum[2]; kd[3] = ksum[3];
    }
}

// ---------------- reduce kv partials + kmean partials ----------------
__global__ void kv_reduce_kernel(const float* __restrict__ part, const float* __restrict__ kmpart,
                                 float* __restrict__ kv, float* __restrict__ km) {
    int i = blockIdx.x * blockDim.x + threadIdx.x;
    if (i < BHn * Dn * Dn) {
        float s = 0.0f;
        #pragma unroll
        for (int c = 0; c < KVCHUNKS; c++) s += part[(long)c * (BHn * Dn * Dn) + i];
        kv[i] = s * (1.0f / Ln);
    } else if (i < BHn * Dn * Dn + BHn * Dn) {
        int j = i - BHn * Dn * Dn;
        float s = 0.0f;
        #pragma unroll
        for (int c = 0; c < KVCHUNKS; c++) s += kmpart[(long)c * (BHn * Dn) + j];
        km[j] = s * (1.0f / Ln);
    }
}

// ---------------- attention output: xbufh = x + (q2@kv) * z (half store) ----------------
__global__ void attn_out_kernel(const __half* __restrict__ q2, const float* __restrict__ kv,
                                const float* __restrict__ km, const float* __restrict__ x,
                                __half* __restrict__ xbuf) {
    int bh = blockIdx.x, b = bh >> 3, h = bh & 7;
    int lbase = blockIdx.y * 128;
    __shared__ float kvs[64][64];
    __shared__ float qs[16][64];
    __shared__ float skm[64];
    int t = threadIdx.x;
    #pragma unroll
    for (int i = 0; i < 4; i++) {
        int idx = t + i * 256;
        ((float4*)kvs)[idx] = ((const float4*)(kv + (long)bh * 4096))[idx];
    }
    if (t < 64) skm[t] = km[bh * 64 + t];
    int g = t >> 4;
    int e0 = (t & 15) * 4;
    for (int it = 0; it < 8; it++) {
        __syncthreads();
        int rbase = lbase + it * 16;
        #pragma unroll
        for (int i = 0; i < 4; i++) {
            int idx = t + i * 256;
            int r = idx >> 6, c = idx & 63;
            qs[r][c] = __half2float(q2[((long)bh * Ln + rbase + r) * 64 + c]);
        }
        __syncthreads();
        int l = rbase + g;
        float part = qs[g][e0] * skm[e0] + qs[g][e0+1] * skm[e0+1]
                   + qs[g][e0+2] * skm[e0+2] + qs[g][e0+3] * skm[e0+3];
        #pragma unroll
        for (int o = 8; o; o >>= 1) part += __shfl_xor_sync(0xFFFFFFFFu, part, o);
        float zz = 1.0f / (part + 1e-6f);
        float4 acc = {0.f, 0.f, 0.f, 0.f};
        #pragma unroll
        for (int d = 0; d < 64; d++) {
            float qd = qs[g][d];
            float4 kvv = *(const float4*)&kvs[d][e0];
            acc.x += qd * kvv.x; acc.y += qd * kvv.y;
            acc.z += qd * kvv.z; acc.w += qd * kvv.w;
        }
        long off = ((long)(b * Ln + l)) * Cn + h * 64 + e0;
        float4 cur = *(const float4*)&x[off];
        cur.x += acc.x * zz; cur.y += acc.y * zz;
        cur.z += acc.z * zz; cur.w += acc.w * zz;
        uint2 outp;
        *(__half2*)&outp.x = __floats2half2_rn(cur.x, cur.y);
        *(__half2*)&outp.y = __floats2half2_rn(cur.z, cur.w);
        *(uint2*)&xbuf[off] = outp;
    }
}

// ================= fp16 mma.sync GEMM =================
// EPI: 1 = bias + exact GELU (half out); 2 = bias + residual half (float out);
//      3 = gated conv: xbufh(half RMW) += spin(half) + vv*sigmoid(gg);
//      4 = bias (half out).
#define GSM (3 * 16384)

template<int EPI, int CONVA>
__global__ void __launch_bounds__(256, 2)
gemm_h(const __half* __restrict__ A, const __half* __restrict__ Bt,
       const float* __restrict__ bias, const void* __restrict__ resv,
       void* __restrict__ Cv, int M, int N, int K) {
    extern __shared__ char smraw[];
    uint32_t sb = smem_u32(smraw);
    int t = threadIdx.x, wid = t >> 5, lane = t & 31;
    int g = lane >> 2, tig = lane & 3;
    int bm = blockIdx.y * 128, bn = blockIdx.x * 128;
    int wm = (wid >> 2) * 64, wn = (wid & 3) * 32;

    const __half* aG[2]; const __half* bG[2]; uint32_t offA[2], offB[2];
    int rs[2], cs[2];
    #pragma unroll
    for (int i = 0; i < 2; i++) {
        int idx = t + i * 256;
        int r = idx >> 2;
        int c = idx & 3;
        rs[i] = r; cs[i] = c;
        uint32_t off = (uint32_t)r * 64 + ((c ^ swz(r)) << 4);
        offA[i] = off;
        offB[i] = off + 8192;
        if (!CONVA) aG[i] = A + (long)(bm + r) * K + c * 8;
        bG[i] = Bt + (long)(bn + r) * K + c * 8;
    }

    uint32_t aRow[4], aSw[4];
    #pragma unroll
    for (int mt = 0; mt < 4; mt++) {
        uint32_t m = wm + mt * 16 + (lane & 15);
        aRow[mt] = m * 64;
        aSw[mt] = swz(m);
    }
    uint32_t cHiA = lane >> 4;
    uint32_t bRow[2], bSw[2];
    #pragma unroll
    for (int np = 0; np < 2; np++) {
        uint32_t n = wn + np * 16 + ((lane >> 4) << 3) + (lane & 7);
        bRow[np] = n * 64 + 8192;
        bSw[np] = swz(n);
    }
    uint32_t cHiB = (lane >> 3) & 1;

    int nk = K >> 5;

    auto loadA_conv = [&](uint32_t stb, int kt) {
        int tap = kt >> 4;
        int kin = (kt & 15) * 32;
        #pragma unroll
        for (int i = 0; i < 2; i++) {
            long row = bm + rs[i];
            int l = (int)(row & (Ln - 1));
            bool valid = (unsigned)(l + tap - 1) < (unsigned)Ln;
            const __half* src = valid ? (A + (row + tap - 1) * Cn + kin + cs[i] * 8) : A;
            cpasync16z(stb + offA[i], src, valid ? 16u : 0u);
        }
    };

    #pragma unroll
    for (int s = 0; s < 2; s++) {
        uint32_t stb = sb + s * 16384;
        if (CONVA) loadA_conv(stb, s);
        else {
            #pragma unroll
            for (int i = 0; i < 2; i++) cpasync16(stb + offA[i], aG[i] + s * 32);
        }
        #pragma unroll
        for (int i = 0; i < 2; i++) cpasync16(stb + offB[i], bG[i] + s * 32);
        CP_COMMIT();
    }
    CP_WAIT1();
    __syncthreads();

    float acc[4][4][4] = {};

    for (int kt = 0; kt < nk; kt++) {
        if (kt + 2 < nk) {
            uint32_t stb = sb + ((kt + 2) % 3) * 16384;
            if (CONVA) loadA_conv(stb, kt + 2);
            else {
                #pragma unroll
                for (int i = 0; i < 2; i++) cpasync16(stb + offA[i], aG[i] + (long)(kt + 2) * 32);
            }
            #pragma unroll
            for (int i = 0; i < 2; i++) cpasync16(stb + offB[i], bG[i] + (long)(kt + 2) * 32);
        }
        CP_COMMIT();

        uint32_t stb = sb + (kt % 3) * 16384;
        #pragma unroll
        for (int kb = 0; kb < 2; kb++) {
            uint32_t a[4][4], b[4][2];
            #pragma unroll
            for (int mt = 0; mt < 4; mt++) {
                uint32_t addr = stb + aRow[mt] + ((((uint32_t)(2 * kb) | cHiA) ^ aSw[mt]) << 4);
                ldsm4(a[mt], addr);
            }
            #pragma unroll
            for (int np = 0; np < 2; np++) {
                uint32_t bb[4];
                uint32_t addr = stb + bRow[np] + ((((uint32_t)(2 * kb) | cHiB) ^ bSw[np]) << 4);
                ldsm4(bb, addr);
                b[2*np][0] = bb[0]; b[2*np][1] = bb[1];
                b[2*np+1][0] = bb[2]; b[2*np+1][1] = bb[3];
            }
            #pragma unroll
            for (int mt = 0; mt < 4; mt++)
                #pragma unroll
                for (int nt = 0; nt < 4; nt++)
                    mma_f16(acc[mt][nt], a[mt], b[nt]);
        }

        CP_WAIT1();
        __syncthreads();
    }

    // ---- epilogue ----
    if (EPI == 3) {
        float* sg = (float*)smraw;
        #pragma unroll
        for (int mt = 0; mt < 4; mt++) {
            int r0 = wm + mt * 16 + g;
            #pragma unroll
            for (int nt = 0; nt < 4; nt++) {
                int col = wn + nt * 8 + tig * 2;
                float b0 = bias[bn + col], b1 = bias[bn + col + 1];
                float vv0 = acc[mt][nt][0] + b0, gg0 = acc[mt][nt][1] + b1;
                float vv1 = acc[mt][nt][2] + b0, gg1 = acc[mt][nt][3] + b1;
                int cp = col >> 1;
                sg[r0 * 68 + cp]       = vv0 / (1.0f + __expf(-gg0));
                sg[(r0 + 8) * 68 + cp] = vv1 / (1.0f + __expf(-gg1));
            }
        }
        __syncthreads();
        int cpb = bn >> 1;
        __half* X = (__half*)Cv;
        const __half* R = (const __half*)resv;
        #pragma unroll
        for (int i = 0; i < 8; i++) {
            int j = t + i * 256;
            int r = j >> 4, c4 = j & 15;
            long off = (long)(bm + r) * Cn + cpb + c4 * 4;
            uint2 xraw = *(uint2*)(X + off);
            uint2 spraw = *(const uint2*)(R + off);
            float2 x0 = __half22float2(*(__half2*)&xraw.x);
            float2 x1 = __half22float2(*(__half2*)&xraw.y);
            float2 s0 = __half22float2(*(__half2*)&spraw.x);
            float2 s1 = __half22float2(*(__half2*)&spraw.y);
            float4 gv = *(float4*)&sg[r * 68 + c4 * 4];
            uint2 outp;
            *(__half2*)&outp.x = __floats2half2_rn(x0.x + s0.x + gv.x, x0.y + s0.y + gv.y);
            *(__half2*)&outp.y = __floats2half2_rn(x1.x + s1.x + gv.z, x1.y + s1.y + gv.w);
            *(uint2*)(X + off) = outp;
        }
        return;
    }

    #pragma unroll
    for (int mt = 0; mt < 4; mt++) {
        int row = bm + wm + mt * 16 + g;
        #pragma unroll
        for (int nt = 0; nt < 4; nt++) {
            int col = bn + wn + nt * 8 + tig * 2;
            float b0 = bias[col], b1 = bias[col + 1];
            float v00 = acc[mt][nt][0] + b0;
            float v01 = acc[mt][nt][1] + b1;
            float v10 = acc[mt][nt][2] + b0;
            float v11 = acc[mt][nt][3] + b1;
            if (EPI == 1) {
                v00 = 0.5f * v00 * (1.0f + erff(v00 * 0.70710678118654752f));
                v01 = 0.5f * v01 * (1.0f + erff(v01 * 0.70710678118654752f));
                v10 = 0.5f * v10 * (1.0f + erff(v10 * 0.70710678118654752f));
                v11 = 0.5f * v11 * (1.0f + erff(v11 * 0.70710678118654752f));
                __half2* C = (__half2*)Cv;
                C[((long)row * N + col) >> 1]       = __floats2half2_rn(v00, v01);
                C[((long)(row + 8) * N + col) >> 1] = __floats2half2_rn(v10, v11);
            } else if (EPI == 4) {
                __half2* C = (__half2*)Cv;
                C[((long)row * N + col) >> 1]       = __floats2half2_rn(v00, v01);
                C[((long)(row + 8) * N + col) >> 1] = __floats2half2_rn(v10, v11);
            } else {  // EPI == 2: residual is half, output float
                const __half2* R = (const __half2*)resv;
                float2 f0 = __half22float2(R[((long)row * N + col) >> 1]);
                float2 f1 = __half22float2(R[((long)(row + 8) * N + col) >> 1]);
                v00 += f0.x; v01 += f0.y;
                v10 += f1.x; v11 += f1.y;
                float* C = (float*)Cv;
                float2 p0 = {v00, v01}, p1 = {v10, v11};
                *(float2*)(C + (long)row * N + col)       = p0;
                *(float2*)(C + (long)(row + 8) * N + col) = p1;
            }
        }
    }
}

// ---------------- host launcher ----------------
extern "C" void kernel_launch(void* const* d_in, const int* in_sizes, int n_in,
                              void* d_out, int out_size) {
    const float* x      = (const float*)d_in[0];
    const float* g1     = (const float*)d_in[1];
    const float* b1     = (const float*)d_in[2];
    const float* qk_w   = (const float*)d_in[3];
    const float* qk_b   = (const float*)d_in[4];
    const float* v_w    = (const float*)d_in[5];
    const float* v_b    = (const float*)d_in[6];
    const float* lepe_w = (const float*)d_in[7];
    const float* lepe_b = (const float*)d_in[8];
    const float* g2     = (const float*)d_in[9];
    const float* b2     = (const float*)d_in[10];
    const float* spn_g  = (const float*)d_in[11];
    const float* spn_b  = (const float*)d_in[12];
    const float* sp_cw  = (const float*)d_in[13];
    const float* sp_cb  = (const float*)d_in[14];
    const float* g3     = (const float*)d_in[15];
    const float* b3     = (const float*)d_in[16];
    const float* w1     = (const float*)d_in[17];
    const float* bb1    = (const float*)d_in[18];
    const float* w2     = (const float*)d_in[19];
    const float* bb2    = (const float*)d_in[20];
    float* out = (float*)d_out;

    float *km, *kv, *kvpart, *kmpart, *bias2, *bias3;
    __half *xbufh, *lnh, *qkvh, *q2h, *k2h, *spinh, *hb, *ffnh, *qkvTh, *w1Th, *w2Th, *wtT2h;
    cudaGetSymbolAddress((void**)&xbufh,  g_xbufh);
    cudaGetSymbolAddress((void**)&lnh,    g_lnh);
    cudaGetSymbolAddress((void**)&qkvh,   g_qkvh);
    cudaGetSymbolAddress((void**)&q2h,    g_q2h);
    cudaGetSymbolAddress((void**)&k2h,    g_k2h);
    cudaGetSymbolAddress((void**)&km,     g_kmean);
    cudaGetSymbolAddress((void**)&kv,     g_kv);
    cudaGetSymbolAddress((void**)&kvpart, g_kvpart);
    cudaGetSymbolAddress((void**)&kmpart, g_kmpart);
    cudaGetSymbolAddress((void**)&spinh,  g_spinh);
    cudaGetSymbolAddress((void**)&hb,     g_hb);
    cudaGetSymbolAddress((void**)&ffnh,   g_ffnh);
    cudaGetSymbolAddress((void**)&qkvTh,  g_qkvTh);
    cudaGetSymbolAddress((void**)&w1Th,   g_w1Th);
    cudaGetSymbolAddress((void**)&w2Th,   g_w2Th);
    cudaGetSymbolAddress((void**)&wtT2h,  g_wtT2h);
    cudaGetSymbolAddress((void**)&bias2,  g_bias2);
    cudaGetSymbolAddress((void**)&bias3,  g_bias3);

    cudaFuncSetAttribute((const void*)gemm_h<4,0>, cudaFuncAttributeMaxDynamicSharedMemorySize, GSM);
    cudaFuncSetAttribute((const void*)gemm_h<3,1>, cudaFuncAttributeMaxDynamicSharedMemorySize, GSM);
    cudaFuncSetAttribute((const void*)gemm_h<1,0>, cudaFuncAttributeMaxDynamicSharedMemorySize, GSM);
    cudaFuncSetAttribute((const void*)gemm_h<2,0>, cudaFuncAttributeMaxDynamicSharedMemorySize, GSM);

    prep_weights_kernel<<<(int)((PW_TOT + 255) / 256), 256>>>(
        qk_w, v_w, w1, w2, sp_cw, qk_b, v_b, sp_cb,
        qkvTh, w1Th, w2Th, wtT2h, bias2, bias3);

    // Block 1: xbufh = x + attn(LN1(x))
    ln_h_kernel<<<BLn, 128>>>(x, g1, b1, lnh);
    gemm_h<4,0><<<dim3(1536 / 128, BLn / 128), 256, GSM>>>(lnh, qkvTh, bias3, nullptr, qkvh, BLn, 1536, Cn);
    qk_post_kernel<<<dim3(BHn, Ln / 64), 256>>>(qkvh, lepe_w, lepe_b, q2h, k2h);
    kv_kernel<<<dim3(BHn, KVCHUNKS), 256>>>(k2h, qkvh, kvpart, kmpart);
    kv_reduce_kernel<<<(BHn * Dn * Dn + BHn * Dn + 255) / 256, 256>>>(kvpart, kmpart, kv, km);
    attn_out_kernel<<<dim3(BHn, Ln / 128), 256>>>(q2h, kv, km, x, xbufh);

    // Block 2: gated conv state path
    ln2ln3_kernel<<<BLn, 128>>>(xbufh, g2, b2, spn_g, spn_b, spinh, hb);
    gemm_h<3,1><<<dim3(1024 / 128, BLn / 128), 256, GSM>>>(hb, wtT2h, bias2, spinh, xbufh, BLn, 1024, 3 * Cn);

    // Block 3: FFN
    ln_hh_kernel<<<BLn, 128>>>(xbufh, g3, b3, lnh);
    gemm_h<1,0><<<dim3(FFn / 128, BLn / 128), 256, GSM>>>(lnh, w1Th, bb1, nullptr, ffnh, BLn, FFn, Cn);
    gemm_h<2,0><<<dim3(512 / 128, BLn / 128), 256, GSM>>>(ffnh, w2Th, bb2, xbufh, out, BLn, 512, FFn);
}

// round 12
// speedup vs baseline: 1.5468x; 1.0543x over previous
#include <cuda_runtime.h>
#include <cuda_fp16.h>
#include <math.h>
#include <stdint.h>

#define Bn 8
#define Ln 2048
#define Cn 512
#define Hn 8
#define Dn 64
#define FFn 2048
#define BLn (Bn*Ln)          /* 16384 */
#define BHn (Bn*Hn)          /* 64    */
#define BHLn (BHn*Ln)        /* 131072*/
#define KVCHUNKS 8

// ---------------- scratch (static device globals; no allocation) ----------------
static __device__ __align__(16) __half g_xbufh[BLn*Cn];
static __device__ __align__(16) __half g_lnh[BLn*Cn];
static __device__ __align__(16) __half g_qkvh[(long)BLn*1536];
static __device__ __align__(16) __half g_q2h[BHLn*Dn];
static __device__ __align__(16) __half g_k2h[BHLn*Dn];
static __device__ __align__(16) float  g_kmean[BHn*Dn];
static __device__ __align__(16) float  g_kv[BHn*Dn*Dn];
static __device__ __align__(16) float  g_kvpart[KVCHUNKS*BHn*Dn*Dn];
static __device__ __align__(16) float  g_kmpart[KVCHUNKS*BHn*Dn];
static __device__ __align__(16) __half g_spinh[BLn*Cn];
static __device__ __align__(16) __half g_hb[BLn*Cn];
static __device__ __align__(16) __half g_ffnh[(long)BLn*FFn];
// weights (half), prepared once per call
static __device__ __align__(16) __half g_qkvTh[1536*512];
static __device__ __align__(16) __half g_w1Th[2048*512];
static __device__ __align__(16) __half g_w2Th[512*2048];
static __device__ __align__(16) __half g_wtT2h[1024*1536];
static __device__ __align__(16) float  g_bias2[1024];
static __device__ __align__(16) float  g_bias3[1536];

// ---------------- PTX helpers ----------------
__device__ __forceinline__ uint32_t smem_u32(const void* p) {
    uint32_t a;
    asm("{ .reg .u64 t; cvta.to.shared.u64 t, %1; cvt.u32.u64 %0, t; }" : "=r"(a) : "l"(p));
    return a;
}
__device__ __forceinline__ void cpasync16(uint32_t saddr, const void* g) {
    asm volatile("cp.async.cg.shared.global [%0], [%1], 16;" :: "r"(saddr), "l"(g) : "memory");
}
__device__ __forceinline__ void cpasync16z(uint32_t saddr, const void* g, uint32_t sz) {
    asm volatile("cp.async.cg.shared.global [%0], [%1], 16, %2;"
                 :: "r"(saddr), "l"(g), "r"(sz) : "memory");
}
#define CP_COMMIT() asm volatile("cp.async.commit_group;" ::: "memory")
#define CP_WAIT1()  asm volatile("cp.async.wait_group 1;" ::: "memory")

__device__ __forceinline__ void ldsm4(uint32_t* r, uint32_t addr) {
    asm volatile("ldmatrix.sync.aligned.m8n8.x4.shared.b16 {%0,%1,%2,%3}, [%4];"
        : "=r"(r[0]), "=r"(r[1]), "=r"(r[2]), "=r"(r[3]) : "r"(addr));
}
__device__ __forceinline__ void mma_f16(float* c, const uint32_t* a, const uint32_t* b) {
    asm volatile(
        "mma.sync.aligned.m16n8k16.row.col.f32.f16.f16.f32 "
        "{%0,%1,%2,%3}, {%4,%5,%6,%7}, {%8,%9}, {%0,%1,%2,%3};"
        : "+f"(c[0]), "+f"(c[1]), "+f"(c[2]), "+f"(c[3])
        : "r"(a[0]), "r"(a[1]), "r"(a[2]), "r"(a[3]), "r"(b[0]), "r"(b[1]));
}

// ---------------- small helpers ----------------
__device__ __forceinline__ float elu1f(float x) { return x > 0.0f ? x + 1.0f : __expf(x); }

// ---------------- one-shot weight prep ----------------
#define PW_S0 524288L
#define PW_S1 (PW_S0 + 262144L)
#define PW_S2 (PW_S1 + 1048576L)
#define PW_S3 (PW_S2 + 1048576L)
#define PW_S4 (PW_S3 + 1572864L)
#define PW_TOT (PW_S4 + 1536L)
__global__ void prep_weights_kernel(const float* __restrict__ qk_w, const float* __restrict__ v_w,
                                    const float* __restrict__ w1, const float* __restrict__ w2,
                                    const float* __restrict__ sp_cw,
                                    const float* __restrict__ qk_b, const float* __restrict__ v_b,
                                    const float* __restrict__ sp_cb,
                                    __half* __restrict__ qkvT, __half* __restrict__ w1T,
                                    __half* __restrict__ w2T, __half* __restrict__ wtT2,
                                    float* __restrict__ bias2, float* __restrict__ bias3) {
    long idx = (long)blockIdx.x * blockDim.x + threadIdx.x;
    if (idx < PW_S0) {
        int k = (int)(idx & 511), n = (int)(idx >> 9);
        qkvT[idx] = __float2half_rn(qk_w[(long)k * 1024 + n]);
    } else if (idx < PW_S1) {
        long i = idx - PW_S0;
        int k = (int)(i & 511), n = (int)(i >> 9);
        qkvT[idx] = __float2half_rn(v_w[(long)k * 512 + n]);
    } else if (idx < PW_S2) {
        long i = idx - PW_S1;
        int k = (int)(i & 511), n = (int)(i >> 9);
        w1T[i] = __float2half_rn(w1[(long)k * 2048 + n]);
    } else if (idx < PW_S3) {
        long i = idx - PW_S2;
        int k = (int)(i & 2047), n = (int)(i >> 11);
        w2T[i] = __float2half_rn(w2[(long)k * 512 + n]);
    } else if (idx < PW_S4) {
        long i = idx - PW_S3;
        int kk = (int)(i % 1536), n2 = (int)(i / 1536);
        int co = (n2 & 1) * 512 + (n2 >> 1);
        int k  = kk >> 9, ci = kk & 511;
        wtT2[i] = __float2half_rn(sp_cw[co * 1536 + ci * 3 + k]);
        if (kk == 0) bias2[n2] = sp_cb[co];
    } else if (idx < PW_TOT) {
        int j = (int)(idx - PW_S4);
        bias3[j] = (j < 1024) ? qk_b[j] : v_b[j - 1024];
    }
}

// ---------------- LayerNorm, float input -> half out ----------------
__global__ void ln_h_kernel(const float* __restrict__ in, const float* __restrict__ gam,
                            const float* __restrict__ bet, __half* __restrict__ out) {
    int row = blockIdx.x;
    int t = threadIdx.x;
    const float4 v = ((const float4*)(in + (long)row * Cn))[t];
    float s  = v.x + v.y + v.z + v.w;
    float sq = v.x*v.x + v.y*v.y + v.z*v.z + v.w*v.w;
    #pragma unroll
    for (int o = 16; o; o >>= 1) {
        s  += __shfl_xor_sync(0xFFFFFFFFu, s,  o);
        sq += __shfl_xor_sync(0xFFFFFFFFu, sq, o);
    }
    __shared__ float ss[4], ssq[4];
    if ((t & 31) == 0) { ss[t >> 5] = s; ssq[t >> 5] = sq; }
    __syncthreads();
    s  = ss[0] + ss[1] + ss[2] + ss[3];
    sq = ssq[0] + ssq[1] + ssq[2] + ssq[3];
    float mu   = s * (1.0f / Cn);
    float var  = sq * (1.0f / Cn) - mu * mu;
    float rstd = rsqrtf(var + 1e-5f);
    float4 g4 = ((const float4*)gam)[t];
    float4 b4 = ((const float4*)bet)[t];
    __half2* o = (__half2*)(out + (long)row * Cn);
    o[t * 2]     = __floats2half2_rn((v.x - mu) * rstd * g4.x + b4.x,
                                     (v.y - mu) * rstd * g4.y + b4.y);
    o[t * 2 + 1] = __floats2half2_rn((v.z - mu) * rstd * g4.z + b4.z,
                                     (v.w - mu) * rstd * g4.w + b4.w);
}

// ---------------- LayerNorm, half input -> half out ----------------
__global__ void ln_hh_kernel(const __half* __restrict__ in, const float* __restrict__ gam,
                             const float* __restrict__ bet, __half* __restrict__ out) {
    int row = blockIdx.x;
    int t = threadIdx.x;
    uint2 raw = ((const uint2*)(in + (long)row * Cn))[t];
    float2 p0 = __half22float2(*(__half2*)&raw.x);
    float2 p1 = __half22float2(*(__half2*)&raw.y);
    float4 v = {p0.x, p0.y, p1.x, p1.y};
    float s  = v.x + v.y + v.z + v.w;
    float sq = v.x*v.x + v.y*v.y + v.z*v.z + v.w*v.w;
    #pragma unroll
    for (int o = 16; o; o >>= 1) {
        s  += __shfl_xor_sync(0xFFFFFFFFu, s,  o);
        sq += __shfl_xor_sync(0xFFFFFFFFu, sq, o);
    }
    __shared__ float ss[4], ssq[4];
    if ((t & 31) == 0) { ss[t >> 5] = s; ssq[t >> 5] = sq; }
    __syncthreads();
    s  = ss[0] + ss[1] + ss[2] + ss[3];
    sq = ssq[0] + ssq[1] + ssq[2] + ssq[3];
    float mu   = s * (1.0f / Cn);
    float var  = sq * (1.0f / Cn) - mu * mu;
    float rstd = rsqrtf(var + 1e-5f);
    float4 g4 = ((const float4*)gam)[t];
    float4 b4 = ((const float4*)bet)[t];
    __half2* o = (__half2*)(out + (long)row * Cn);
    o[t * 2]     = __floats2half2_rn((v.x - mu) * rstd * g4.x + b4.x,
                                     (v.y - mu) * rstd * g4.y + b4.y);
    o[t * 2 + 1] = __floats2half2_rn((v.z - mu) * rstd * g4.z + b4.z,
                                     (v.w - mu) * rstd * g4.w + b4.w);
}

// ---------------- fused LN2 + LN3 (half in) ----------------
__global__ void ln2ln3_kernel(const __half* __restrict__ in,
                              const float* __restrict__ g2, const float* __restrict__ b2,
                              const float* __restrict__ g3, const float* __restrict__ b3,
                              __half* __restrict__ spin, __half* __restrict__ hb) {
    int row = blockIdx.x;
    int t = threadIdx.x;
    __shared__ float ss[4], ssq[4];
    uint2 raw = ((const uint2*)(in + (long)row * Cn))[t];
    float2 p0 = __half22float2(*(__half2*)&raw.x);
    float2 p1 = __half22float2(*(__half2*)&raw.y);
    float4 v = {p0.x, p0.y, p1.x, p1.y};
    float s  = v.x + v.y + v.z + v.w;
    float sq = v.x*v.x + v.y*v.y + v.z*v.z + v.w*v.w;
    #pragma unroll
    for (int o = 16; o; o >>= 1) {
        s  += __shfl_xor_sync(0xFFFFFFFFu, s,  o);
        sq += __shfl_xor_sync(0xFFFFFFFFu, sq, o);
    }
    if ((t & 31) == 0) { ss[t >> 5] = s; ssq[t >> 5] = sq; }
    __syncthreads();
    s  = ss[0] + ss[1] + ss[2] + ss[3];
    sq = ssq[0] + ssq[1] + ssq[2] + ssq[3];
    float mu   = s * (1.0f / Cn);
    float var  = sq * (1.0f / Cn) - mu * mu;
    float rstd = rsqrtf(var + 1e-5f);
    float4 gg = ((const float4*)g2)[t];
    float4 bb = ((const float4*)b2)[t];
    float4 o1;
    o1.x = (v.x - mu) * rstd * gg.x + bb.x;
    o1.y = (v.y - mu) * rstd * gg.y + bb.y;
    o1.z = (v.z - mu) * rstd * gg.z + bb.z;
    o1.w = (v.w - mu) * rstd * gg.w + bb.w;
    __half2* sp = (__half2*)(spin + (long)row * Cn);
    sp[t * 2]     = __floats2half2_rn(o1.x, o1.y);
    sp[t * 2 + 1] = __floats2half2_rn(o1.z, o1.w);
    float s2  = o1.x + o1.y + o1.z + o1.w;
    float sq2 = o1.x*o1.x + o1.y*o1.y + o1.z*o1.z + o1.w*o1.w;
    #pragma unroll
    for (int o = 16; o; o >>= 1) {
        s2  += __shfl_xor_sync(0xFFFFFFFFu, s2,  o);
        sq2 += __shfl_xor_sync(0xFFFFFFFFu, sq2, o);
    }
    __syncthreads();
    if ((t & 31) == 0) { ss[t >> 5] = s2; ssq[t >> 5] = sq2; }
    __syncthreads();
    s2  = ss[0] + ss[1] + ss[2] + ss[3];
    sq2 = ssq[0] + ssq[1] + ssq[2] + ssq[3];
    float mu2   = s2 * (1.0f / Cn);
    float var2  = sq2 * (1.0f / Cn) - mu2 * mu2;
    float rstd2 = rsqrtf(var2 + 1e-5f);
    float4 g4 = ((const float4*)g3)[t];
    float4 b4 = ((const float4*)b3)[t];
    __half2* o = (__half2*)(hb + (long)row * Cn);
    o[t * 2]     = __floats2half2_rn((o1.x - mu2) * rstd2 * g4.x + b4.x,
                                     (o1.y - mu2) * rstd2 * g4.y + b4.y);
    o[t * 2 + 1] = __floats2half2_rn((o1.z - mu2) * rstd2 * g4.z + b4.z,
                                     (o1.w - mu2) * rstd2 * g4.w + b4.w);
}

// ---------------- qk post: elu applied at smem fill, then pure-FMA LePE ----------------
__global__ void qk_post_kernel(const __half* __restrict__ qkv,
                               const float* __restrict__ lw, const float* __restrict__ lb,
                               __half* __restrict__ q2, __half* __restrict__ k2) {
    int bh = blockIdx.x;
    int lt = blockIdx.y;
    int l0 = lt * 64;
    int b = bh >> 3, h = bh & 7;
    const __half* base = qkv + (long)b * Ln * 1536 + h * 64;
    __shared__ __half sId[2][64][64];
    __shared__ __half sTapT[2][64][66];
    __shared__ __half sLo[2][64], sHi[2][64];
    int t = threadIdx.x;
    #pragma unroll
    for (int sel = 0; sel < 2; sel++) {
        #pragma unroll
        for (int i = 0; i < 2; i++) {
            int idx = t + i * 256;
            int r  = idx >> 3;
            int c8 = (idx & 7) * 8;
            __half tmp[8];
            *(uint4*)tmp = *(const uint4*)&base[(long)(l0 + r) * 1536 + sel * 512 + c8];
            #pragma unroll
            for (int k = 0; k < 8; k++) tmp[k] = __float2half_rn(elu1f(__half2float(tmp[k])));
            *(uint4*)&sId[sel][r][c8] = *(uint4*)tmp;
            *(uint4*)tmp = *(const uint4*)&base[(long)(r * 32 + lt) * 1536 + sel * 512 + c8];
            #pragma unroll
            for (int k = 0; k < 8; k++)
                sTapT[sel][c8 + k][r] = __float2half_rn(elu1f(__half2float(tmp[k])));
        }
    }
    if (t < 128) {
        int sel = t >> 6, d = t & 63;
        float lo = 0.0f, hi = 0.0f;
        if (l0 > 0)       lo = elu1f(__half2float(base[(long)(d * 32 + lt - 1) * 1536 + sel * 512 + 63]));
        if (l0 + 64 < Ln) hi = elu1f(__half2float(base[(long)(d * 32 + lt + 1) * 1536 + sel * 512]));
        sLo[sel][d] = __float2half_rn(lo);
        sHi[sel][d] = __float2half_rn(hi);
    }
    __syncthreads();
    int d2 = (t & 31) * 2, rb = t >> 5;
    #pragma unroll
    for (int sel = 0; sel < 2; sel++) {
        __half* dst = sel ? k2 : q2;
        float w0[2], w1[2], w2[2], bi[2];
        #pragma unroll
        for (int dd = 0; dd < 2; dd++) {
            int d = d2 + dd;
            w0[dd] = lw[d*3]; w1[dd] = lw[d*3+1]; w2[dd] = lw[d*3+2]; bi[dd] = lb[d];
        }
        #pragma unroll
        for (int i = 0; i < 8; i++) {
            int r = rb + i * 8;
            float o[2];
            #pragma unroll
            for (int dd = 0; dd < 2; dd++) {
                int d = d2 + dd;
                float c1 = __half2float(sTapT[sel][r][d]);
                float c0 = (r > 0) ? __half2float(sTapT[sel][r-1][d]) : __half2float(sLo[sel][d]);
                float c2 = (r < 63) ? __half2float(sTapT[sel][r+1][d]) : __half2float(sHi[sel][d]);
                o[dd] = __half2float(sId[sel][r][d]) + bi[dd]
                      + w0[dd] * c0 + w1[dd] * c1 + w2[dd] * c2;
            }
            *(__half2*)&dst[(long)bh * (Ln * Dn) + (long)(l0 + r) * 64 + d2] =
                __floats2half2_rn(o[0], o[1]);
        }
    }
}

// ---------------- kv partials + kmean partials (fused) ----------------
__global__ void kv_kernel(const __half* __restrict__ k2, const __half* __restrict__ qkv,
                          float* __restrict__ part, float* __restrict__ kmpart) {
    int bh = blockIdx.x, chunk = blockIdx.y;
    int b = bh >> 3, h = bh & 7;
    __shared__ float ks[32][64];
    __shared__ float vs[32][64];
    int t = threadIdx.x;
    int e0 = (t & 15) * 4, d0 = (t >> 4) * 4;
    float acc[4][4] = {};
    float ksum[4] = {};
    bool kmwriter = (t & 15) == 0;
    int lc = Ln / KVCHUNKS;
    for (int l0 = chunk * lc; l0 < chunk * lc + lc; l0 += 32) {
        #pragma unroll
        for (int i = 0; i < 2; i++) {
            int idx = t + i * 256;
            int r = idx >> 4, c4 = (idx & 15) * 4;
            int l = l0 + r;
            uint2 kr = *(const uint2*)&k2[((long)bh * Ln + l) * 64 + c4];
            uint2 vr = *(const uint2*)&qkv[((long)(b * Ln + l)) * 1536 + 1024 + h * 64 + c4];
            float2 k0 = __half22float2(*(__half2*)&kr.x);
            float2 k1 = __half22float2(*(__half2*)&kr.y);
            float2 v0 = __half22float2(*(__half2*)&vr.x);
            float2 v1 = __half22float2(*(__half2*)&vr.y);
            ks[r][c4] = k0.x; ks[r][c4+1] = k0.y; ks[r][c4+2] = k1.x; ks[r][c4+3] = k1.y;
            vs[r][c4] = v0.x; vs[r][c4+1] = v0.y; vs[r][c4+2] = v1.x; vs[r][c4+3] = v1.y;
        }
        __syncthreads();
        #pragma unroll
        for (int l = 0; l < 32; l++) {
            float4 kr = *(const float4*)&ks[l][d0];
            float4 vr = *(const float4*)&vs[l][e0];
            float k_[4] = {kr.x, kr.y, kr.z, kr.w};
            float v_[4] = {vr.x, vr.y, vr.z, vr.w};
            if (kmwriter) {
                ksum[0] += k_[0]; ksum[1] += k_[1]; ksum[2] += k_[2]; ksum[3] += k_[3];
            }
            #pragma unroll
            for (int i = 0; i < 4; i++)
                #pragma unroll
                for (int j = 0; j < 4; j++)
                    acc[i][j] += k_[i] * v_[j];
        }
        __syncthreads();
    }
    float* dst = part + ((long)chunk * BHn + bh) * (Dn * Dn);
    #pragma unroll
    for (int i = 0; i < 4; i++)
        #pragma unroll
        for (int j = 0; j < 4; j++)
            dst[(d0 + i) * 64 + e0 + j] = acc[i][j];
    if (kmwriter) {
        float* kd = kmpart + ((long)chunk * BHn + bh) * Dn + d0;
        kd[0] = ksum[0]; kd[1] = ksum[1]; kd[2] = ksum[2]; kd[3] = ksum[3];
    }
}

// ---------------- reduce kv partials + kmean partials ----------------
__global__ void kv_reduce_kernel(const float* __restrict__ part, const float* __restrict__ kmpart,
                                 float* __restrict__ kv, float* __restrict__ km) {
    int i = blockIdx.x * blockDim.x + threadIdx.x;
    if (i < BHn * Dn * Dn) {
        float s = 0.0f;
        #pragma unroll
        for (int c = 0; c < KVCHUNKS; c++) s += part[(long)c * (BHn * Dn * Dn) + i];
        kv[i] = s * (1.0f / Ln);
    } else if (i < BHn * Dn * Dn + BHn * Dn) {
        int j = i - BHn * Dn * Dn;
        float s = 0.0f;
        #pragma unroll
        for (int c = 0; c < KVCHUNKS; c++) s += kmpart[(long)c * (BHn * Dn) + j];
        km[j] = s * (1.0f / Ln);
    }
}

// ---------------- attention output ----------------
__global__ void attn_out_kernel(const __half* __restrict__ q2, const float* __restrict__ kv,
                                const float* __restrict__ km, const float* __restrict__ x,
                                __half* __restrict__ xbuf) {
    int bh = blockIdx.x, b = bh >> 3, h = bh & 7;
    int lbase = blockIdx.y * 128;
    __shared__ float kvs[64][64];
    __shared__ float qs[16][64];
    __shared__ float skm[64];
    int t = threadIdx.x;
    #pragma unroll
    for (int i = 0; i < 4; i++) {
        int idx = t + i * 256;
        ((float4*)kvs)[idx] = ((const float4*)(kv + (long)bh * 4096))[idx];
    }
    if (t < 64) skm[t] = km[bh * 64 + t];
    int g = t >> 4;
    int e0 = (t & 15) * 4;
    for (int it = 0; it < 8; it++) {
        __syncthreads();
        int rbase = lbase + it * 16;
        #pragma unroll
        for (int i = 0; i < 4; i++) {
            int idx = t + i * 256;
            int r = idx >> 6, c = idx & 63;
            qs[r][c] = __half2float(q2[((long)bh * Ln + rbase + r) * 64 + c]);
        }
        __syncthreads();
        int l = rbase + g;
        float part = qs[g][e0] * skm[e0] + qs[g][e0+1] * skm[e0+1]
                   + qs[g][e0+2] * skm[e0+2] + qs[g][e0+3] * skm[e0+3];
        #pragma unroll
        for (int o = 8; o; o >>= 1) part += __shfl_xor_sync(0xFFFFFFFFu, part, o);
        float zz = 1.0f / (part + 1e-6f);
        float4 acc = {0.f, 0.f, 0.f, 0.f};
        #pragma unroll
        for (int d = 0; d < 64; d++) {
            float qd = qs[g][d];
            float4 kvv = *(const float4*)&kvs[d][e0];
            acc.x += qd * kvv.x; acc.y += qd * kvv.y;
            acc.z += qd * kvv.z; acc.w += qd * kvv.w;
        }
        long off = ((long)(b * Ln + l)) * Cn + h * 64 + e0;
        float4 cur = *(const float4*)&x[off];
        cur.x += acc.x * zz; cur.y += acc.y * zz;
        cur.z += acc.z * zz; cur.w += acc.w * zz;
        uint2 outp;
        *(__half2*)&outp.x = __floats2half2_rn(cur.x, cur.y);
        *(__half2*)&outp.y = __floats2half2_rn(cur.z, cur.w);
        *(uint2*)&xbuf[off] = outp;
    }
}

// ================= fp16 mma.sync GEMM, K-chunk 64, 3-stage =================
// CTA 128x128, 8 warps; stage = A 16KB + B 16KB; rows of 128B, phys chunk16 = c ^ (r&7).
// CONVA=1: A is hb [BL,512] viewed as im2col [BL,1536] (tap = kchunk/8).
// EPI: 1 = bias + GELU (half out); 2 = bias + half residual (float out);
//      3 = gated conv: xbufh(half RMW) += spin(half) + vv*sigmoid(gg); 4 = bias (half out).
#define GSTG 32768
#define GSM  (3 * GSTG)

template<int EPI, int CONVA>
__global__ void __launch_bounds__(256, 2)
gemm_h(const __half* __restrict__ A, const __half* __restrict__ Bt,
       const float* __restrict__ bias, const void* __restrict__ resv,
       void* __restrict__ Cv, int M, int N, int K) {
    extern __shared__ char smraw[];
    uint32_t sb = smem_u32(smraw);
    int t = threadIdx.x, wid = t >> 5, lane = t & 31;
    int g = lane >> 2, tig = lane & 3;
    int bm = blockIdx.y * 128, bn = blockIdx.x * 128;
    int wm = (wid >> 2) * 64, wn = (wid & 3) * 32;

    // ---- cp.async slots: 4 A-chunks + 4 B-chunks per thread per stage ----
    const __half* aG[4]; const __half* bG[4]; uint32_t offA[4], offB[4];
    int rs[4], cs[4];
    #pragma unroll
    for (int i = 0; i < 4; i++) {
        int idx = t + i * 256;            // 0..1023
        int r = idx >> 3;                 // row 0..127
        int c = idx & 7;                  // 16B chunk in 128B row
        rs[i] = r; cs[i] = c;
        uint32_t off = (uint32_t)r * 128 + (uint32_t)((c ^ (r & 7)) << 4);
        offA[i] = off;
        offB[i] = off + 16384;
        if (!CONVA) aG[i] = A + (long)(bm + r) * K + c * 8;
        bG[i] = Bt + (long)(bn + r) * K + c * 8;
    }

    // ---- ldmatrix address components ----
    uint32_t aRow[4], aSw[4];
    #pragma unroll
    for (int mt = 0; mt < 4; mt++) {
        uint32_t m = wm + mt * 16 + (lane & 15);
        aRow[mt] = m * 128;
        aSw[mt] = m & 7;
    }
    uint32_t cHiA = lane >> 4;
    uint32_t bRow[2], bSw[2];
    #pragma unroll
    for (int np = 0; np < 2; np++) {
        uint32_t n = wn + np * 16 + ((lane >> 4) << 3) + (lane & 7);
        bRow[np] = n * 128 + 16384;
        bSw[np] = n & 7;
    }
    uint32_t cHiB = (lane >> 3) & 1;

    int nk = K >> 6;                      // K-chunks of 64

    auto loadA_conv = [&](uint32_t stb, int kt) {
        int tap = kt >> 3;                // 8 chunks per tap (512/64)
        int kin = (kt & 7) * 64;
        #pragma unroll
        for (int i = 0; i < 4; i++) {
            long row = bm + rs[i];
            int l = (int)(row & (Ln - 1));
            bool valid = (unsigned)(l + tap - 1) < (unsigned)Ln;
            const __half* src = valid ? (A + (row + tap - 1) * Cn + kin + cs[i] * 8) : A;
            cpasync16z(stb + offA[i], src, valid ? 16u : 0u);
        }
    };

    // prologue: stages 0,1
    #pragma unroll
    for (int s = 0; s < 2; s++) {
        uint32_t stb = sb + s * GSTG;
        if (CONVA) loadA_conv(stb, s);
        else {
            #pragma unroll
            for (int i = 0; i < 4; i++) cpasync16(stb + offA[i], aG[i] + s * 64);
        }
        #pragma unroll
        for (int i = 0; i < 4; i++) cpasync16(stb + offB[i], bG[i] + s * 64);
        CP_COMMIT();
    }
    CP_WAIT1();
    __syncthreads();

    float acc[4][4][4] = {};

    for (int kt = 0; kt < nk; kt++) {
        if (kt + 2 < nk) {
            uint32_t stb = sb + ((kt + 2) % 3) * GSTG;
            if (CONVA) loadA_conv(stb, kt + 2);
            else {
                #pragma unroll
                for (int i = 0; i < 4; i++) cpasync16(stb + offA[i], aG[i] + (long)(kt + 2) * 64);
            }
            #pragma unroll
            for (int i = 0; i < 4; i++) cpasync16(stb + offB[i], bG[i] + (long)(kt + 2) * 64);
        }
        CP_COMMIT();

        uint32_t stb = sb + (kt % 3) * GSTG;
        #pragma unroll
        for (int kb = 0; kb < 4; kb++) {
            uint32_t a[4][4], b[4][2];
            #pragma unroll
            for (int mt = 0; mt < 4; mt++) {
                uint32_t addr = stb + aRow[mt] + ((((uint32_t)(2 * kb) | cHiA) ^ aSw[mt]) << 4);
                ldsm4(a[mt], addr);
            }
            #pragma unroll
            for (int np = 0; np < 2; np++) {
                uint32_t bb[4];
                uint32_t addr = stb + bRow[np] + ((((uint32_t)(2 * kb) | cHiB) ^ bSw[np]) << 4);
                ldsm4(bb, addr);
                b[2*np][0] = bb[0]; b[2*np][1] = bb[1];
                b[2*np+1][0] = bb[2]; b[2*np+1][1] = bb[3];
            }
            #pragma unroll
            for (int mt = 0; mt < 4; mt++)
                #pragma unroll
                for (int nt = 0; nt < 4; nt++)
                    mma_f16(acc[mt][nt], a[mt], b[nt]);
        }

        CP_WAIT1();
        __syncthreads();
    }

    // ---- epilogue ----
    if (EPI == 3) {
        float* sg = (float*)smraw;
        #pragma unroll
        for (int mt = 0; mt < 4; mt++) {
            int r0 = wm + mt * 16 + g;
            #pragma unroll
            for (int nt = 0; nt < 4; nt++) {
                int col = wn + nt * 8 + tig * 2;
                float b0 = bias[bn + col], b1 = bias[bn + col + 1];
                float vv0 = acc[mt][nt][0] + b0, gg0 = acc[mt][nt][1] + b1;
                float vv1 = acc[mt][nt][2] + b0, gg1 = acc[mt][nt][3] + b1;
                int cp = col >> 1;
                sg[r0 * 68 + cp]       = vv0 / (1.0f + __expf(-gg0));
                sg[(r0 + 8) * 68 + cp] = vv1 / (1.0f + __expf(-gg1));
            }
        }
        __syncthreads();
        int cpb = bn >> 1;
        __half* X = (__half*)Cv;
        const __half* R = (const __half*)resv;
        #pragma unroll
        for (int i = 0; i < 8; i++) {
            int j = t + i * 256;
            int r = j >> 4, c4 = j & 15;
            long off = (long)(bm + r) * Cn + cpb + c4 * 4;
            uint2 xraw = *(uint2*)(X + off);
            uint2 spraw = *(const uint2*)(R + off);
            float2 x0 = __half22float2(*(__half2*)&xraw.x);
            float2 x1 = __half22float2(*(__half2*)&xraw.y);
            float2 s0 = __half22float2(*(__half2*)&spraw.x);
            float2 s1 = __half22float2(*(__half2*)&spraw.y);
            float4 gv = *(float4*)&sg[r * 68 + c4 * 4];
            uint2 outp;
            *(__half2*)&outp.x = __floats2half2_rn(x0.x + s0.x + gv.x, x0.y + s0.y + gv.y);
            *(__half2*)&outp.y = __floats2half2_rn(x1.x + s1.x + gv.z, x1.y + s1.y + gv.w);
            *(uint2*)(X + off) = outp;
        }
        return;
    }

    #pragma unroll
    for (int mt = 0; mt < 4; mt++) {
        int row = bm + wm + mt * 16 + g;
        #pragma unroll
        for (int nt = 0; nt < 4; nt++) {
            int col = bn + wn + nt * 8 + tig * 2;
            float b0 = bias[col], b1 = bias[col + 1];
            float v00 = acc[mt][nt][0] + b0;
            float v01 = acc[mt][nt][1] + b1;
            float v10 = acc[mt][nt][2] + b0;
            float v11 = acc[mt][nt][3] + b1;
            if (EPI == 1) {
                v00 = 0.5f * v00 * (1.0f + erff(v00 * 0.70710678118654752f));
                v01 = 0.5f * v01 * (1.0f + erff(v01 * 0.70710678118654752f));
                v10 = 0.5f * v10 * (1.0f + erff(v10 * 0.70710678118654752f));
                v11 = 0.5f * v11 * (1.0f + erff(v11 * 0.70710678118654752f));
                __half2* C = (__half2*)Cv;
                C[((long)row * N + col) >> 1]       = __floats2half2_rn(v00, v01);
                C[((long)(row + 8) * N + col) >> 1] = __floats2half2_rn(v10, v11);
            } else if (EPI == 4) {
                __half2* C = (__half2*)Cv;
                C[((long)row * N + col) >> 1]       = __floats2half2_rn(v00, v01);
                C[((long)(row + 8) * N + col) >> 1] = __floats2half2_rn(v10, v11);
            } else {  // EPI == 2
                const __half2* R = (const __half2*)resv;
                float2 f0 = __half22float2(R[((long)row * N + col) >> 1]);
                float2 f1 = __half22float2(R[((long)(row + 8) * N + col) >> 1]);
                v00 += f0.x; v01 += f0.y;
                v10 += f1.x; v11 += f1.y;
                float* C = (float*)Cv;
                float2 p0 = {v00, v01}, p1 = {v10, v11};
                *(float2*)(C + (long)row * N + col)       = p0;
                *(float2*)(C + (long)(row + 8) * N + col) = p1;
            }
        }
    }
}

// ---------------- host launcher ----------------
extern "C" void kernel_launch(void* const* d_in, const int* in_sizes, int n_in,
                              void* d_out, int out_size) {
    const float* x      = (const float*)d_in[0];
    const float* g1     = (const float*)d_in[1];
    const float* b1     = (const float*)d_in[2];
    const float* qk_w   = (const float*)d_in[3];
    const float* qk_b   = (const float*)d_in[4];
    const float* v_w    = (const float*)d_in[5];
    const float* v_b    = (const float*)d_in[6];
    const float* lepe_w = (const float*)d_in[7];
    const float* lepe_b = (const float*)d_in[8];
    const float* g2     = (const float*)d_in[9];
    const float* b2     = (const float*)d_in[10];
    const float* spn_g  = (const float*)d_in[11];
    const float* spn_b  = (const float*)d_in[12];
    const float* sp_cw  = (const float*)d_in[13];
    const float* sp_cb  = (const float*)d_in[14];
    const float* g3     = (const float*)d_in[15];
    const float* b3     = (const float*)d_in[16];
    const float* w1     = (const float*)d_in[17];
    const float* bb1    = (const float*)d_in[18];
    const float* w2     = (const float*)d_in[19];
    const float* bb2    = (const float*)d_in[20];
    float* out = (float*)d_out;

    float *km, *kv, *kvpart, *kmpart, *bias2, *bias3;
    __half *xbufh, *lnh, *qkvh, *q2h, *k2h, *spinh, *hb, *ffnh, *qkvTh, *w1Th, *w2Th, *wtT2h;
    cudaGetSymbolAddress((void**)&xbufh,  g_xbufh);
    cudaGetSymbolAddress((void**)&lnh,    g_lnh);
    cudaGetSymbolAddress((void**)&qkvh,   g_qkvh);
    cudaGetSymbolAddress((void**)&q2h,    g_q2h);
    cudaGetSymbolAddress((void**)&k2h,    g_k2h);
    cudaGetSymbolAddress((void**)&km,     g_kmean);
    cudaGetSymbolAddress((void**)&kv,     g_kv);
    cudaGetSymbolAddress((void**)&kvpart, g_kvpart);
    cudaGetSymbolAddress((void**)&kmpart, g_kmpart);
    cudaGetSymbolAddress((void**)&spinh,  g_spinh);
    cudaGetSymbolAddress((void**)&hb,     g_hb);
    cudaGetSymbolAddress((void**)&ffnh,   g_ffnh);
    cudaGetSymbolAddress((void**)&qkvTh,  g_qkvTh);
    cudaGetSymbolAddress((void**)&w1Th,   g_w1Th);
    cudaGetSymbolAddress((void**)&w2Th,   g_w2Th);
    cudaGetSymbolAddress((void**)&wtT2h,  g_wtT2h);
    cudaGetSymbolAddress((void**)&bias2,  g_bias2);
    cudaGetSymbolAddress((void**)&bias3,  g_bias3);

    cudaFuncSetAttribute((const void*)gemm_h<4,0>, cudaFuncAttributeMaxDynamicSharedMemorySize, GSM);
    cudaFuncSetAttribute((const void*)gemm_h<3,1>, cudaFuncAttributeMaxDynamicSharedMemorySize, GSM);
    cudaFuncSetAttribute((const void*)gemm_h<1,0>, cudaFuncAttributeMaxDynamicSharedMemorySize, GSM);
    cudaFuncSetAttribute((const void*)gemm_h<2,0>, cudaFuncAttributeMaxDynamicSharedMemorySize, GSM);

    prep_weights_kernel<<<(int)((PW_TOT + 255) / 256), 256>>>(
        qk_w, v_w, w1, w2, sp_cw, qk_b, v_b, sp_cb,
        qkvTh, w1Th, w2Th, wtT2h, bias2, bias3);

    // Block 1: xbufh = x + attn(LN1(x))
    ln_h_kernel<<<BLn, 128>>>(x, g1, b1, lnh);
    gemm_h<4,0><<<dim3(1536 / 128, BLn / 128), 256, GSM>>>(lnh, qkvTh, bias3, nullptr, qkvh, BLn, 1536, Cn);
    qk_post_kernel<<<dim3(BHn, Ln / 64), 256>>>(qkvh, lepe_w, lepe_b, q2h, k2h);
    kv_kernel<<<dim3(BHn, KVCHUNKS), 256>>>(k2h, qkvh, kvpart, kmpart);
    kv_reduce_kernel<<<(BHn * Dn * Dn + BHn * Dn + 255) / 256, 256>>>(kvpart, kmpart, kv, km);
    attn_out_kernel<<<dim3(BHn, Ln / 128), 256>>>(q2h, kv, km, x, xbufh);

    // Block 2: gated conv state path
    ln2ln3_kernel<<<BLn, 128>>>(xbufh, g2, b2, spn_g, spn_b, spinh, hb);
    gemm_h<3,1><<<dim3(1024 / 128, BLn / 128), 256, GSM>>>(hb, wtT2h, bias2, spinh, xbufh, BLn, 1024, 3 * Cn);

    // Block 3: FFN
    ln_hh_kernel<<<BLn, 128>>>(xbufh, g3, b3, lnh);
    gemm_h<1,0><<<dim3(FFn / 128, BLn / 128), 256, GSM>>>(lnh, w1Th, bb1, nullptr, ffnh, BLn, FFn, Cn);
    gemm_h<2,0><<<dim3(512 / 128, BLn / 128), 256, GSM>>>(ffnh, w2Th, bb2, xbufh, out, BLn, 512, FFn);
}

// round 13
// speedup vs baseline: 1.6917x; 1.0937x over previous
#include <cuda_runtime.h>
#include <cuda_fp16.h>
#include <math.h>
#include <stdint.h>

#define Bn 8
#define Ln 2048
#define Cn 512
#define Hn 8
#define Dn 64
#define FFn 2048
#define BLn (Bn*Ln)          /* 16384 */
#define BHn (Bn*Hn)          /* 64    */
#define BHLn (BHn*Ln)        /* 131072*/
#define KVCHUNKS 8

// ---------------- scratch (static device globals; no allocation) ----------------
static __device__ __align__(16) __half g_xbufh[BLn*Cn];
static __device__ __align__(16) __half g_lnh[BLn*Cn];
static __device__ __align__(16) __half g_qkvh[(long)BLn*1536];
static __device__ __align__(16) __half g_q2h[BHLn*Dn];
static __device__ __align__(16) __half g_k2h[BHLn*Dn];
static __device__ __align__(16) float  g_kvpart[KVCHUNKS*BHn*Dn*Dn];
static __device__ __align__(16) float  g_kmpart[KVCHUNKS*BHn*Dn];
static __device__ __align__(16) __half g_kvT2h[BHn*72*64];   // B^T tiles + km row + zero pad
static __device__ __align__(16) __half g_spinh[BLn*Cn];
static __device__ __align__(16) __half g_hb[BLn*Cn];
static __device__ __align__(16) __half g_ffnh[(long)BLn*FFn];
// weights (half), prepared once per call
static __device__ __align__(16) __half g_qkvTh[1536*512];
static __device__ __align__(16) __half g_w1Th[2048*512];
static __device__ __align__(16) __half g_w2Th[512*2048];
static __device__ __align__(16) __half g_wtT2h[1024*1536];
static __device__ __align__(16) float  g_bias2[1024];
static __device__ __align__(16) float  g_bias3[1536];

// ---------------- PTX helpers ----------------
__device__ __forceinline__ uint32_t smem_u32(const void* p) {
    uint32_t a;
    asm("{ .reg .u64 t; cvta.to.shared.u64 t, %1; cvt.u32.u64 %0, t; }" : "=r"(a) : "l"(p));
    return a;
}
__device__ __forceinline__ void cpasync16(uint32_t saddr, const void* g) {
    asm volatile("cp.async.cg.shared.global [%0], [%1], 16;" :: "r"(saddr), "l"(g) : "memory");
}
__device__ __forceinline__ void cpasync16z(uint32_t saddr, const void* g, uint32_t sz) {
    asm volatile("cp.async.cg.shared.global [%0], [%1], 16, %2;"
                 :: "r"(saddr), "l"(g), "r"(sz) : "memory");
}
#define CP_COMMIT() asm volatile("cp.async.commit_group;" ::: "memory")
#define CP_WAIT1()  asm volatile("cp.async.wait_group 1;" ::: "memory")

__device__ __forceinline__ void ldsm4(uint32_t* r, uint32_t addr) {
    asm volatile("ldmatrix.sync.aligned.m8n8.x4.shared.b16 {%0,%1,%2,%3}, [%4];"
        : "=r"(r[0]), "=r"(r[1]), "=r"(r[2]), "=r"(r[3]) : "r"(addr));
}
__device__ __forceinline__ void ldsm2(uint32_t* r, uint32_t addr) {
    asm volatile("ldmatrix.sync.aligned.m8n8.x2.shared.b16 {%0,%1}, [%2];"
        : "=r"(r[0]), "=r"(r[1]) : "r"(addr));
}
__device__ __forceinline__ void mma_f16(float* c, const uint32_t* a, const uint32_t* b) {
    asm volatile(
        "mma.sync.aligned.m16n8k16.row.col.f32.f16.f16.f32 "
        "{%0,%1,%2,%3}, {%4,%5,%6,%7}, {%8,%9}, {%0,%1,%2,%3};"
        : "+f"(c[0]), "+f"(c[1]), "+f"(c[2]), "+f"(c[3])
        : "r"(a[0]), "r"(a[1]), "r"(a[2]), "r"(a[3]), "r"(b[0]), "r"(b[1]));
}

// ---------------- small helpers ----------------
__device__ __forceinline__ float elu1f(float x) { return x > 0.0f ? x + 1.0f : __expf(x); }

// ---------------- one-shot weight prep ----------------
#define PW_S0 524288L
#define PW_S1 (PW_S0 + 262144L)
#define PW_S2 (PW_S1 + 1048576L)
#define PW_S3 (PW_S2 + 1048576L)
#define PW_S4 (PW_S3 + 1572864L)
#define PW_TOT (PW_S4 + 1536L)
__global__ void prep_weights_kernel(const float* __restrict__ qk_w, const float* __restrict__ v_w,
                                    const float* __restrict__ w1, const float* __restrict__ w2,
                                    const float* __restrict__ sp_cw,
                                    const float* __restrict__ qk_b, const float* __restrict__ v_b,
                                    const float* __restrict__ sp_cb,
                                    __half* __restrict__ qkvT, __half* __restrict__ w1T,
                                    __half* __restrict__ w2T, __half* __restrict__ wtT2,
                                    float* __restrict__ bias2, float* __restrict__ bias3) {
    long idx = (long)blockIdx.x * blockDim.x + threadIdx.x;
    if (idx < PW_S0) {
        int k = (int)(idx & 511), n = (int)(idx >> 9);
        qkvT[idx] = __float2half_rn(qk_w[(long)k * 1024 + n]);
    } else if (idx < PW_S1) {
        long i = idx - PW_S0;
        int k = (int)(i & 511), n = (int)(i >> 9);
        qkvT[idx] = __float2half_rn(v_w[(long)k * 512 + n]);
    } else if (idx < PW_S2) {
        long i = idx - PW_S1;
        int k = (int)(i & 511), n = (int)(i >> 9);
        w1T[i] = __float2half_rn(w1[(long)k * 2048 + n]);
    } else if (idx < PW_S3) {
        long i = idx - PW_S2;
        int k = (int)(i & 2047), n = (int)(i >> 11);
        w2T[i] = __float2half_rn(w2[(long)k * 512 + n]);
    } else if (idx < PW_S4) {
        long i = idx - PW_S3;
        int kk = (int)(i % 1536), n2 = (int)(i / 1536);
        int co = (n2 & 1) * 512 + (n2 >> 1);
        int k  = kk >> 9, ci = kk & 511;
        wtT2[i] = __float2half_rn(sp_cw[co * 1536 + ci * 3 + k]);
        if (kk == 0) bias2[n2] = sp_cb[co];
    } else if (idx < PW_TOT) {
        int j = (int)(idx - PW_S4);
        bias3[j] = (j < 1024) ? qk_b[j] : v_b[j - 1024];
    }
}

// ---------------- LayerNorm, float input -> half out ----------------
__global__ void ln_h_kernel(const float* __restrict__ in, const float* __restrict__ gam,
                            const float* __restrict__ bet, __half* __restrict__ out) {
    int row = blockIdx.x;
    int t = threadIdx.x;
    const float4 v = ((const float4*)(in + (long)row * Cn))[t];
    float s  = v.x + v.y + v.z + v.w;
    float sq = v.x*v.x + v.y*v.y + v.z*v.z + v.w*v.w;
    #pragma unroll
    for (int o = 16; o; o >>= 1) {
        s  += __shfl_xor_sync(0xFFFFFFFFu, s,  o);
        sq += __shfl_xor_sync(0xFFFFFFFFu, sq, o);
    }
    __shared__ float ss[4], ssq[4];
    if ((t & 31) == 0) { ss[t >> 5] = s; ssq[t >> 5] = sq; }
    __syncthreads();
    s  = ss[0] + ss[1] + ss[2] + ss[3];
    sq = ssq[0] + ssq[1] + ssq[2] + ssq[3];
    float mu   = s * (1.0f / Cn);
    float var  = sq * (1.0f / Cn) - mu * mu;
    float rstd = rsqrtf(var + 1e-5f);
    float4 g4 = ((const float4*)gam)[t];
    float4 b4 = ((const float4*)bet)[t];
    __half2* o = (__half2*)(out + (long)row * Cn);
    o[t * 2]     = __floats2half2_rn((v.x - mu) * rstd * g4.x + b4.x,
                                     (v.y - mu) * rstd * g4.y + b4.y);
    o[t * 2 + 1] = __floats2half2_rn((v.z - mu) * rstd * g4.z + b4.z,
                                     (v.w - mu) * rstd * g4.w + b4.w);
}

// ---------------- LayerNorm, half input -> half out ----------------
__global__ void ln_hh_kernel(const __half* __restrict__ in, const float* __restrict__ gam,
                             const float* __restrict__ bet, __half* __restrict__ out) {
    int row = blockIdx.x;
    int t = threadIdx.x;
    uint2 raw = ((const uint2*)(in + (long)row * Cn))[t];
    float2 p0 = __half22float2(*(__half2*)&raw.x);
    float2 p1 = __half22float2(*(__half2*)&raw.y);
    float4 v = {p0.x, p0.y, p1.x, p1.y};
    float s  = v.x + v.y + v.z + v.w;
    float sq = v.x*v.x + v.y*v.y + v.z*v.z + v.w*v.w;
    #pragma unroll
    for (int o = 16; o; o >>= 1) {
        s  += __shfl_xor_sync(0xFFFFFFFFu, s,  o);
        sq += __shfl_xor_sync(0xFFFFFFFFu, sq, o);
    }
    __shared__ float ss[4], ssq[4];
    if ((t & 31) == 0) { ss[t >> 5] = s; ssq[t >> 5] = sq; }
    __syncthreads();
    s  = ss[0] + ss[1] + ss[2] + ss[3];
    sq = ssq[0] + ssq[1] + ssq[2] + ssq[3];
    float mu   = s * (1.0f / Cn);
    float var  = sq * (1.0f / Cn) - mu * mu;
    float rstd = rsqrtf(var + 1e-5f);
    float4 g4 = ((const float4*)gam)[t];
    float4 b4 = ((const float4*)bet)[t];
    __half2* o = (__half2*)(out + (long)row * Cn);
    o[t * 2]     = __floats2half2_rn((v.x - mu) * rstd * g4.x + b4.x,
                                     (v.y - mu) * rstd * g4.y + b4.y);
    o[t * 2 + 1] = __floats2half2_rn((v.z - mu) * rstd * g4.z + b4.z,
                                     (v.w - mu) * rstd * g4.w + b4.w);
}

// ---------------- fused LN2 + LN3 (half in) ----------------
__global__ void ln2ln3_kernel(const __half* __restrict__ in,
                              const float* __restrict__ g2, const float* __restrict__ b2,
                              const float* __restrict__ g3, const float* __restrict__ b3,
                              __half* __restrict__ spin, __half* __restrict__ hb) {
    int row = blockIdx.x;
    int t = threadIdx.x;
    __shared__ float ss[4], ssq[4];
    uint2 raw = ((const uint2*)(in + (long)row * Cn))[t];
    float2 p0 = __half22float2(*(__half2*)&raw.x);
    float2 p1 = __half22float2(*(__half2*)&raw.y);
    float4 v = {p0.x, p0.y, p1.x, p1.y};
    float s  = v.x + v.y + v.z + v.w;
    float sq = v.x*v.x + v.y*v.y + v.z*v.z + v.w*v.w;
    #pragma unroll
    for (int o = 16; o; o >>= 1) {
        s  += __shfl_xor_sync(0xFFFFFFFFu, s,  o);
        sq += __shfl_xor_sync(0xFFFFFFFFu, sq, o);
    }
    if ((t & 31) == 0) { ss[t >> 5] = s; ssq[t >> 5] = sq; }
    __syncthreads();
    s  = ss[0] + ss[1] + ss[2] + ss[3];
    sq = ssq[0] + ssq[1] + ssq[2] + ssq[3];
    float mu   = s * (1.0f / Cn);
    float var  = sq * (1.0f / Cn) - mu * mu;
    float rstd = rsqrtf(var + 1e-5f);
    float4 gg = ((const float4*)g2)[t];
    float4 bb = ((const float4*)b2)[t];
    float4 o1;
    o1.x = (v.x - mu) * rstd * gg.x + bb.x;
    o1.y = (v.y - mu) * rstd * gg.y + bb.y;
    o1.z = (v.z - mu) * rstd * gg.z + bb.z;
    o1.w = (v.w - mu) * rstd * gg.w + bb.w;
    __half2* sp = (__half2*)(spin + (long)row * Cn);
    sp[t * 2]     = __floats2half2_rn(o1.x, o1.y);
    sp[t * 2 + 1] = __floats2half2_rn(o1.z, o1.w);
    float s2  = o1.x + o1.y + o1.z + o1.w;
    float sq2 = o1.x*o1.x + o1.y*o1.y + o1.z*o1.z + o1.w*o1.w;
    #pragma unroll
    for (int o = 16; o; o >>= 1) {
        s2  += __shfl_xor_sync(0xFFFFFFFFu, s2,  o);
        sq2 += __shfl_xor_sync(0xFFFFFFFFu, sq2, o);
    }
    __syncthreads();
    if ((t & 31) == 0) { ss[t >> 5] = s2; ssq[t >> 5] = sq2; }
    __syncthreads();
    s2  = ss[0] + ss[1] + ss[2] + ss[3];
    sq2 = ssq[0] + ssq[1] + ssq[2] + ssq[3];
    float mu2   = s2 * (1.0f / Cn);
    float var2  = sq2 * (1.0f / Cn) - mu2 * mu2;
    float rstd2 = rsqrtf(var2 + 1e-5f);
    float4 g4 = ((const float4*)g3)[t];
    float4 b4 = ((const float4*)b3)[t];
    __half2* o = (__half2*)(hb + (long)row * Cn);
    o[t * 2]     = __floats2half2_rn((o1.x - mu2) * rstd2 * g4.x + b4.x,
                                     (o1.y - mu2) * rstd2 * g4.y + b4.y);
    o[t * 2 + 1] = __floats2half2_rn((o1.z - mu2) * rstd2 * g4.z + b4.z,
                                     (o1.w - mu2) * rstd2 * g4.w + b4.w);
}

// ---------------- qk post: elu at smem fill, half2 FMA LePE ----------------
__global__ void qk_post_kernel(const __half* __restrict__ qkv,
                               const float* __restrict__ lw, const float* __restrict__ lb,
                               __half* __restrict__ q2, __half* __restrict__ k2) {
    int bh = blockIdx.x;
    int lt = blockIdx.y;
    int l0 = lt * 64;
    int b = bh >> 3, h = bh & 7;
    const __half* base = qkv + (long)b * Ln * 1536 + h * 64;
    __shared__ __align__(16) __half sId[2][64][64];
    __shared__ __align__(16) __half sTapT[2][64][68];   // pad 68: half2 stays 4B-aligned
    __shared__ __align__(4)  __half sLo[2][64], sHi[2][64];
    int t = threadIdx.x;
    #pragma unroll
    for (int sel = 0; sel < 2; sel++) {
        #pragma unroll
        for (int i = 0; i < 2; i++) {
            int idx = t + i * 256;
            int r  = idx >> 3;
            int c8 = (idx & 7) * 8;
            __half tmp[8];
            *(uint4*)tmp = *(const uint4*)&base[(long)(l0 + r) * 1536 + sel * 512 + c8];
            #pragma unroll
            for (int k = 0; k < 8; k++) tmp[k] = __float2half_rn(elu1f(__half2float(tmp[k])));
            *(uint4*)&sId[sel][r][c8] = *(uint4*)tmp;
            *(uint4*)tmp = *(const uint4*)&base[(long)(r * 32 + lt) * 1536 + sel * 512 + c8];
            #pragma unroll
            for (int k = 0; k < 8; k++)
                sTapT[sel][c8 + k][r] = __float2half_rn(elu1f(__half2float(tmp[k])));
        }
    }
    if (t < 128) {
        int sel = t >> 6, d = t & 63;
        float lo = 0.0f, hi = 0.0f;
        if (l0 > 0)       lo = elu1f(__half2float(base[(long)(d * 32 + lt - 1) * 1536 + sel * 512 + 63]));
        if (l0 + 64 < Ln) hi = elu1f(__half2float(base[(long)(d * 32 + lt + 1) * 1536 + sel * 512]));
        sLo[sel][d] = __float2half_rn(lo);
        sHi[sel][d] = __float2half_rn(hi);
    }
    __syncthreads();
    int d2 = (t & 31) * 2, rb = t >> 5;
    __half2 w0h = __floats2half2_rn(lw[d2*3],   lw[d2*3+3]);
    __half2 w1h = __floats2half2_rn(lw[d2*3+1], lw[d2*3+4]);
    __half2 w2h = __floats2half2_rn(lw[d2*3+2], lw[d2*3+5]);
    __half2 bi2 = __floats2half2_rn(lb[d2], lb[d2+1]);
    #pragma unroll
    for (int sel = 0; sel < 2; sel++) {
        __half* dst = sel ? k2 : q2;
        #pragma unroll
        for (int i = 0; i < 8; i++) {
            int r = rb + i * 8;
            __half2 c1 = *(__half2*)&sTapT[sel][r][d2];
            __half2 c0 = (r > 0)  ? *(__half2*)&sTapT[sel][r-1][d2] : *(__half2*)&sLo[sel][d2];
            __half2 c2 = (r < 63) ? *(__half2*)&sTapT[sel][r+1][d2] : *(__half2*)&sHi[sel][d2];
            __half2 o = __hadd2(*(__half2*)&sId[sel][r][d2], bi2);
            o = __hfma2(w0h, c0, o);
            o = __hfma2(w1h, c1, o);
            o = __hfma2(w2h, c2, o);
            *(__half2*)&dst[(long)bh * (Ln * Dn) + (long)(l0 + r) * 64 + d2] = o;
        }
    }
}

// ---------------- kv partials + kmean partials (fused) ----------------
__global__ void kv_kernel(const __half* __restrict__ k2, const __half* __restrict__ qkv,
                          float* __restrict__ part, float* __restrict__ kmpart) {
    int bh = blockIdx.x, chunk = blockIdx.y;
    int b = bh >> 3, h = bh & 7;
    __shared__ float ks[32][64];
    __shared__ float vs[32][64];
    int t = threadIdx.x;
    int e0 = (t & 15) * 4, d0 = (t >> 4) * 4;
    float acc[4][4] = {};
    float ksum[4] = {};
    bool kmwriter = (t & 15) == 0;
    int lc = Ln / KVCHUNKS;
    for (int l0 = chunk * lc; l0 < chunk * lc + lc; l0 += 32) {
        #pragma unroll
        for (int i = 0; i < 2; i++) {
            int idx = t + i * 256;
            int r = idx >> 4, c4 = (idx & 15) * 4;
            int l = l0 + r;
            uint2 kr = *(const uint2*)&k2[((long)bh * Ln + l) * 64 + c4];
            uint2 vr = *(const uint2*)&qkv[((long)(b * Ln + l)) * 1536 + 1024 + h * 64 + c4];
            float2 k0 = __half22float2(*(__half2*)&kr.x);
            float2 k1 = __half22float2(*(__half2*)&kr.y);
            float2 v0 = __half22float2(*(__half2*)&vr.x);
            float2 v1 = __half22float2(*(__half2*)&vr.y);
            ks[r][c4] = k0.x; ks[r][c4+1] = k0.y; ks[r][c4+2] = k1.x; ks[r][c4+3] = k1.y;
            vs[r][c4] = v0.x; vs[r][c4+1] = v0.y; vs[r][c4+2] = v1.x; vs[r][c4+3] = v1.y;
        }
        __syncthreads();
        #pragma unroll
        for (int l = 0; l < 32; l++) {
            float4 kr = *(const float4*)&ks[l][d0];
            float4 vr = *(const float4*)&vs[l][e0];
            float k_[4] = {kr.x, kr.y, kr.z, kr.w};
            float v_[4] = {vr.x, vr.y, vr.z, vr.w};
            if (kmwriter) {
                ksum[0] += k_[0]; ksum[1] += k_[1]; ksum[2] += k_[2]; ksum[3] += k_[3];
            }
            #pragma unroll
            for (int i = 0; i < 4; i++)
                #pragma unroll
                for (int j = 0; j < 4; j++)
                    acc[i][j] += k_[i] * v_[j];
        }
        __syncthreads();
    }
    float* dst = part + ((long)chunk * BHn + bh) * (Dn * Dn);
    #pragma unroll
    for (int i = 0; i < 4; i++)
        #pragma unroll
        for (int j = 0; j < 4; j++)
            dst[(d0 + i) * 64 + e0 + j] = acc[i][j];
    if (kmwriter) {
        float* kd = kmpart + ((long)chunk * BHn + bh) * Dn + d0;
        kd[0] = ksum[0]; kd[1] = ksum[1]; kd[2] = ksum[2]; kd[3] = ksum[3];
    }
}

// ---------------- reduce partials -> kvT2 (half, [bh][72][64]) ----------------
// rows 0..63: kvT (row e, col d); row 64: kmean; rows 65..71: zero.
__global__ void kv_reduce_kernel(const float* __restrict__ part, const float* __restrict__ kmpart,
                                 __half* __restrict__ kvT2) {
    int i = blockIdx.x * blockDim.x + threadIdx.x;
    if (i < BHn * 4096) {
        int bh = i >> 12;
        int de = i & 4095;
        int d = de >> 6, e = de & 63;
        float s = 0.0f;
        #pragma unroll
        for (int c = 0; c < KVCHUNKS; c++) s += part[(long)c * (BHn * 4096) + i];
        kvT2[(long)bh * 4608 + e * 64 + d] = __float2half_rn(s * (1.0f / Ln));
    } else if (i < BHn * 4096 + BHn * 64) {
        int j = i - BHn * 4096;
        int bh = j >> 6, d = j & 63;
        float s = 0.0f;
        #pragma unroll
        for (int c = 0; c < KVCHUNKS; c++) s += kmpart[(long)c * (BHn * 64) + j];
        kvT2[(long)bh * 4608 + 4096 + d] = __float2half_rn(s * (1.0f / Ln));
    } else if (i < BHn * 4096 + BHn * 64 + BHn * 448) {
        int j = i - BHn * 4096 - BHn * 64;
        int bh = j / 448, rr = j % 448;
        kvT2[(long)bh * 4608 + 4160 + rr] = __ushort_as_half((unsigned short)0);
    }
}

// ---------------- attention output via mma: xbufh = x + (q2@kvT^T) * z ----------------
// Per block: 128 rows x 64 cols, K=64. B has 9 n-tiles: 8 real + km tile (z denominator).
__global__ void attn_out_kernel(const __half* __restrict__ q2, const __half* __restrict__ kvT2,
                                const float* __restrict__ x, __half* __restrict__ xbuf) {
    int bh = blockIdx.x, b = bh >> 3, h = bh & 7;
    int lbase = blockIdx.y * 128;
    __shared__ __align__(16) __half qs[128 * 64];
    __shared__ __align__(16) __half bs[72 * 64];
    int t = threadIdx.x, wid = t >> 5, lane = t & 31;
    int g = lane >> 2, tig = lane & 3;
    #pragma unroll
    for (int i = 0; i < 4; i++) {
        int idx = t + i * 256;                 // 0..1023
        int r = idx >> 3, c = idx & 7;
        *(uint4*)((char*)qs + r * 128 + ((c ^ (r & 7)) << 4)) =
            *(const uint4*)&q2[((long)bh * Ln + lbase + r) * 64 + c * 8];
    }
    #pragma unroll
    for (int i = 0; i < 3; i++) {
        int idx = t + i * 256;
        if (idx < 576) {
            int r = idx >> 3, c = idx & 7;
            *(uint4*)((char*)bs + r * 128 + ((c ^ (r & 7)) << 4)) =
                *(const uint4*)&kvT2[(long)bh * 4608 + r * 64 + c * 8];
        }
    }
    __syncthreads();
    uint32_t sq = smem_u32(qs), sbm = smem_u32(bs);
    uint32_t m = (uint32_t)(wid * 16 + (lane & 15));
    uint32_t aRow = m * 128, aSw = m & 7, cHiA = (uint32_t)(lane >> 4);
    float acc[9][4] = {};
    #pragma unroll
    for (int kb = 0; kb < 4; kb++) {
        uint32_t a[4];
        ldsm4(a, sq + aRow + ((((uint32_t)(2 * kb) | cHiA) ^ aSw) << 4));
        #pragma unroll
        for (int np = 0; np < 4; np++) {
            uint32_t r = (uint32_t)(np * 16 + ((lane >> 4) << 3) + (lane & 7));
            uint32_t ch = (uint32_t)(2 * kb) | (uint32_t)((lane >> 3) & 1);
            uint32_t bb[4];
            ldsm4(bb, sbm + r * 128 + ((ch ^ (r & 7)) << 4));
            uint32_t b0[2] = {bb[0], bb[1]}, b1[2] = {bb[2], bb[3]};
            mma_f16(acc[2 * np],     a, b0);
            mma_f16(acc[2 * np + 1], a, b1);
        }
        {
            uint32_t r = (uint32_t)(64 + (lane & 7));
            uint32_t ch = (uint32_t)(2 * kb) | (uint32_t)((lane >> 3) & 1);
            uint32_t bb[2];
            ldsm2(bb, sbm + r * 128 + ((ch ^ (r & 7)) << 4));
            mma_f16(acc[8], a, bb);
        }
    }
    // z from km tile (col 0 lives in tig==0 lanes)
    float zg  = __shfl_sync(0xFFFFFFFFu, acc[8][0], lane & ~3) + 1e-6f;
    float zg8 = __shfl_sync(0xFFFFFFFFu, acc[8][2], lane & ~3) + 1e-6f;
    zg = 1.0f / zg;
    zg8 = 1.0f / zg8;
    int row0 = lbase + wid * 16 + g;
    #pragma unroll
    for (int nt = 0; nt < 8; nt++) {
        int col = h * 64 + nt * 8 + tig * 2;
        long off0 = (long)(b * Ln + row0) * Cn + col;
        long off1 = off0 + 8L * Cn;
        float2 x0 = *(const float2*)&x[off0];
        float2 x1 = *(const float2*)&x[off1];
        *(__half2*)&xbuf[off0] = __floats2half2_rn(x0.x + acc[nt][0] * zg,  x0.y + acc[nt][1] * zg);
        *(__half2*)&xbuf[off1] = __floats2half2_rn(x1.x + acc[nt][2] * zg8, x1.y + acc[nt][3] * zg8);
    }
}

// ================= fp16 mma.sync GEMM, K-chunk 64, 3-stage =================
#define GSTG 32768
#define GSM  (3 * GSTG)

template<int EPI, int CONVA>
__global__ void __launch_bounds__(256, 2)
gemm_h(const __half* __restrict__ A, const __half* __restrict__ Bt,
       const float* __restrict__ bias, const void* __restrict__ resv,
       void* __restrict__ Cv, int M, int N, int K) {
    extern __shared__ char smraw[];
    uint32_t sb = smem_u32(smraw);
    int t = threadIdx.x, wid = t >> 5, lane = t & 31;
    int g = lane >> 2, tig = lane & 3;
    int bm = blockIdx.y * 128, bn = blockIdx.x * 128;
    int wm = (wid >> 2) * 64, wn = (wid & 3) * 32;

    const __half* aG[4]; const __half* bG[4]; uint32_t offA[4], offB[4];
    int rs[4], cs[4];
    #pragma unroll
    for (int i = 0; i < 4; i++) {
        int idx = t + i * 256;
        int r = idx >> 3;
        int c = idx & 7;
        rs[i] = r; cs[i] = c;
        uint32_t off = (uint32_t)r * 128 + (uint32_t)((c ^ (r & 7)) << 4);
        offA[i] = off;
        offB[i] = off + 16384;
        if (!CONVA) aG[i] = A + (long)(bm + r) * K + c * 8;
        bG[i] = Bt + (long)(bn + r) * K + c * 8;
    }

    uint32_t aRow[4], aSw[4];
    #pragma unroll
    for (int mt = 0; mt < 4; mt++) {
        uint32_t m = wm + mt * 16 + (lane & 15);
        aRow[mt] = m * 128;
        aSw[mt] = m & 7;
    }
    uint32_t cHiA = lane >> 4;
    uint32_t bRow[2], bSw[2];
    #pragma unroll
    for (int np = 0; np < 2; np++) {
        uint32_t n = wn + np * 16 + ((lane >> 4) << 3) + (lane & 7);
        bRow[np] = n * 128 + 16384;
        bSw[np] = n & 7;
    }
    uint32_t cHiB = (lane >> 3) & 1;

    int nk = K >> 6;

    auto loadA_conv = [&](uint32_t stb, int kt) {
        int tap = kt >> 3;
        int kin = (kt & 7) * 64;
        #pragma unroll
        for (int i = 0; i < 4; i++) {
            long row = bm + rs[i];
            int l = (int)(row & (Ln - 1));
            bool valid = (unsigned)(l + tap - 1) < (unsigned)Ln;
            const __half* src = valid ? (A + (row + tap - 1) * Cn + kin + cs[i] * 8) : A;
            cpasync16z(stb + offA[i], src, valid ? 16u : 0u);
        }
    };

    #pragma unroll
    for (int s = 0; s < 2; s++) {
        uint32_t stb = sb + s * GSTG;
        if (CONVA) loadA_conv(stb, s);
        else {
            #pragma unroll
            for (int i = 0; i < 4; i++) cpasync16(stb + offA[i], aG[i] + s * 64);
        }
        #pragma unroll
        for (int i = 0; i < 4; i++) cpasync16(stb + offB[i], bG[i] + s * 64);
        CP_COMMIT();
    }
    CP_WAIT1();
    __syncthreads();

    float acc[4][4][4] = {};

    for (int kt = 0; kt < nk; kt++) {
        if (kt + 2 < nk) {
            uint32_t stb = sb + ((kt + 2) % 3) * GSTG;
            if (CONVA) loadA_conv(stb, kt + 2);
            else {
                #pragma unroll
                for (int i = 0; i < 4; i++) cpasync16(stb + offA[i], aG[i] + (long)(kt + 2) * 64);
            }
            #pragma unroll
            for (int i = 0; i < 4; i++) cpasync16(stb + offB[i], bG[i] + (long)(kt + 2) * 64);
        }
        CP_COMMIT();

        uint32_t stb = sb + (kt % 3) * GSTG;
        #pragma unroll
        for (int kb = 0; kb < 4; kb++) {
            uint32_t a[4][4], b[4][2];
            #pragma unroll
            for (int mt = 0; mt < 4; mt++) {
                uint32_t addr = stb + aRow[mt] + ((((uint32_t)(2 * kb) | cHiA) ^ aSw[mt]) << 4);
                ldsm4(a[mt], addr);
            }
            #pragma unroll
            for (int np = 0; np < 2; np++) {
                uint32_t bb[4];
                uint32_t addr = stb + bRow[np] + ((((uint32_t)(2 * kb) | cHiB) ^ bSw[np]) << 4);
                ldsm4(bb, addr);
                b[2*np][0] = bb[0]; b[2*np][1] = bb[1];
                b[2*np+1][0] = bb[2]; b[2*np+1][1] = bb[3];
            }
            #pragma unroll
            for (int mt = 0; mt < 4; mt++)
                #pragma unroll
                for (int nt = 0; nt < 4; nt++)
                    mma_f16(acc[mt][nt], a[mt], b[nt]);
        }

        CP_WAIT1();
        __syncthreads();
    }

    // ---- epilogue ----
    if (EPI == 3) {
        float* sg = (float*)smraw;
        #pragma unroll
        for (int mt = 0; mt < 4; mt++) {
            int r0 = wm + mt * 16 + g;
            #pragma unroll
            for (int nt = 0; nt < 4; nt++) {
                int col = wn + nt * 8 + tig * 2;
                float b0 = bias[bn + col], b1 = bias[bn + col + 1];
                float vv0 = acc[mt][nt][0] + b0, gg0 = acc[mt][nt][1] + b1;
                float vv1 = acc[mt][nt][2] + b0, gg1 = acc[mt][nt][3] + b1;
                int cp = col >> 1;
                sg[r0 * 68 + cp]       = vv0 / (1.0f + __expf(-gg0));
                sg[(r0 + 8) * 68 + cp] = vv1 / (1.0f + __expf(-gg1));
            }
        }
        __syncthreads();
        int cpb = bn >> 1;
        __half* X = (__half*)Cv;
        const __half* R = (const __half*)resv;
        #pragma unroll
        for (int i = 0; i < 8; i++) {
            int j = t + i * 256;
            int r = j >> 4, c4 = j & 15;
            long off = (long)(bm + r) * Cn + cpb + c4 * 4;
            uint2 xraw = *(uint2*)(X + off);
            uint2 spraw = *(const uint2*)(R + off);
            float2 x0 = __half22float2(*(__half2*)&xraw.x);
            float2 x1 = __half22float2(*(__half2*)&xraw.y);
            float2 s0 = __half22float2(*(__half2*)&spraw.x);
            float2 s1 = __half22float2(*(__half2*)&spraw.y);
            float4 gv = *(float4*)&sg[r * 68 + c4 * 4];
            uint2 outp;
            *(__half2*)&outp.x = __floats2half2_rn(x0.x + s0.x + gv.x, x0.y + s0.y + gv.y);
            *(__half2*)&outp.y = __floats2half2_rn(x1.x + s1.x + gv.z, x1.y + s1.y + gv.w);
            *(uint2*)(X + off) = outp;
        }
        return;
    }

    #pragma unroll
    for (int mt = 0; mt < 4; mt++) {
        int row = bm + wm + mt * 16 + g;
        #pragma unroll
        for (int nt = 0; nt < 4; nt++) {
            int col = bn + wn + nt * 8 + tig * 2;
            float b0 = bias[col], b1 = bias[col + 1];
            float v00 = acc[mt][nt][0] + b0;
            float v01 = acc[mt][nt][1] + b1;
            float v10 = acc[mt][nt][2] + b0;
            float v11 = acc[mt][nt][3] + b1;
            if (EPI == 1) {
                v00 = 0.5f * v00 * (1.0f + erff(v00 * 0.70710678118654752f));
                v01 = 0.5f * v01 * (1.0f + erff(v01 * 0.70710678118654752f));
                v10 = 0.5f * v10 * (1.0f + erff(v10 * 0.70710678118654752f));
                v11 = 0.5f * v11 * (1.0f + erff(v11 * 0.70710678118654752f));
                __half2* C = (__half2*)Cv;
                C[((long)row * N + col) >> 1]       = __floats2half2_rn(v00, v01);
                C[((long)(row + 8) * N + col) >> 1] = __floats2half2_rn(v10, v11);
            } else if (EPI == 4) {
                __half2* C = (__half2*)Cv;
                C[((long)row * N + col) >> 1]       = __floats2half2_rn(v00, v01);
                C[((long)(row + 8) * N + col) >> 1] = __floats2half2_rn(v10, v11);
            } else {  // EPI == 2
                const __half2* R = (const __half2*)resv;
                float2 f0 = __half22float2(R[((long)row * N + col) >> 1]);
                float2 f1 = __half22float2(R[((long)(row + 8) * N + col) >> 1]);
                v00 += f0.x; v01 += f0.y;
                v10 += f1.x; v11 += f1.y;
                float* C = (float*)Cv;
                float2 p0 = {v00, v01}, p1 = {v10, v11};
                *(float2*)(C + (long)row * N + col)       = p0;
                *(float2*)(C + (long)(row + 8) * N + col) = p1;
            }
        }
    }
}

// ---------------- host launcher ----------------
extern "C" void kernel_launch(void* const* d_in, const int* in_sizes, int n_in,
                              void* d_out, int out_size) {
    const float* x      = (const float*)d_in[0];
    const float* g1     = (const float*)d_in[1];
    const float* b1     = (const float*)d_in[2];
    const float* qk_w   = (const float*)d_in[3];
    const float* qk_b   = (const float*)d_in[4];
    const float* v_w    = (const float*)d_in[5];
    const float* v_b    = (const float*)d_in[6];
    const float* lepe_w = (const float*)d_in[7];
    const float* lepe_b = (const float*)d_in[8];
    const float* g2     = (const float*)d_in[9];
    const float* b2     = (const float*)d_in[10];
    const float* spn_g  = (const float*)d_in[11];
    const float* spn_b  = (const float*)d_in[12];
    const float* sp_cw  = (const float*)d_in[13];
    const float* sp_cb  = (const float*)d_in[14];
    const float* g3     = (const float*)d_in[15];
    const float* b3     = (const float*)d_in[16];
    const float* w1     = (const float*)d_in[17];
    const float* bb1    = (const float*)d_in[18];
    const float* w2     = (const float*)d_in[19];
    const float* bb2    = (const float*)d_in[20];
    float* out = (float*)d_out;

    float *kvpart, *kmpart, *bias2, *bias3;
    __half *xbufh, *lnh, *qkvh, *q2h, *k2h, *kvT2h, *spinh, *hb, *ffnh, *qkvTh, *w1Th, *w2Th, *wtT2h;
    cudaGetSymbolAddress((void**)&xbufh,  g_xbufh);
    cudaGetSymbolAddress((void**)&lnh,    g_lnh);
    cudaGetSymbolAddress((void**)&qkvh,   g_qkvh);
    cudaGetSymbolAddress((void**)&q2h,    g_q2h);
    cudaGetSymbolAddress((void**)&k2h,    g_k2h);
    cudaGetSymbolAddress((void**)&kvpart, g_kvpart);
    cudaGetSymbolAddress((void**)&kmpart, g_kmpart);
    cudaGetSymbolAddress((void**)&kvT2h,  g_kvT2h);
    cudaGetSymbolAddress((void**)&spinh,  g_spinh);
    cudaGetSymbolAddress((void**)&hb,     g_hb);
    cudaGetSymbolAddress((void**)&ffnh,   g_ffnh);
    cudaGetSymbolAddress((void**)&qkvTh,  g_qkvTh);
    cudaGetSymbolAddress((void**)&w1Th,   g_w1Th);
    cudaGetSymbolAddress((void**)&w2Th,   g_w2Th);
    cudaGetSymbolAddress((void**)&wtT2h,  g_wtT2h);
    cudaGetSymbolAddress((void**)&bias2,  g_bias2);
    cudaGetSymbolAddress((void**)&bias3,  g_bias3);

    cudaFuncSetAttribute((const void*)gemm_h<4,0>, cudaFuncAttributeMaxDynamicSharedMemorySize, GSM);
    cudaFuncSetAttribute((const void*)gemm_h<3,1>, cudaFuncAttributeMaxDynamicSharedMemorySize, GSM);
    cudaFuncSetAttribute((const void*)gemm_h<1,0>, cudaFuncAttributeMaxDynamicSharedMemorySize, GSM);
    cudaFuncSetAttribute((const void*)gemm_h<2,0>, cudaFuncAttributeMaxDynamicSharedMemorySize, GSM);

    prep_weights_kernel<<<(int)((PW_TOT + 255) / 256), 256>>>(
        qk_w, v_w, w1, w2, sp_cw, qk_b, v_b, sp_cb,
        qkvTh, w1Th, w2Th, wtT2h, bias2, bias3);

    // Block 1: xbufh = x + attn(LN1(x))
    ln_h_kernel<<<BLn, 128>>>(x, g1, b1, lnh);
    gemm_h<4,0><<<dim3(1536 / 128, BLn / 128), 256, GSM>>>(lnh, qkvTh, bias3, nullptr, qkvh, BLn, 1536, Cn);
    qk_post_kernel<<<dim3(BHn, Ln / 64), 256>>>(qkvh, lepe_w, lepe_b, q2h, k2h);
    kv_kernel<<<dim3(BHn, KVCHUNKS), 256>>>(k2h, qkvh, kvpart, kmpart);
    kv_reduce_kernel<<<(BHn * 4096 + BHn * 64 + BHn * 448 + 255) / 256, 256>>>(kvpart, kmpart, kvT2h);
    attn_out_kernel<<<dim3(BHn, Ln / 128), 256>>>(q2h, kvT2h, x, xbufh);

    // Block 2: gated conv state path
    ln2ln3_kernel<<<BLn, 128>>>(xbufh, g2, b2, spn_g, spn_b, spinh, hb);
    gemm_h<3,1><<<dim3(1024 / 128, BLn / 128), 256, GSM>>>(hb, wtT2h, bias2, spinh, xbufh, BLn, 1024, 3 * Cn);

    // Block 3: FFN
    ln_hh_kernel<<<BLn, 128>>>(xbufh, g3, b3, lnh);
    gemm_h<1,0><<<dim3(FFn / 128, BLn / 128), 256, GSM>>>(lnh, w1Th, bb1, nullptr, ffnh, BLn, FFn, Cn);
    gemm_h<2,0><<<dim3(512 / 128, BLn / 128), 256, GSM>>>(ffnh, w2Th, bb2, xbufh, out, BLn, 512, FFn);
}